// round 1
// baseline (speedup 1.0000x reference)
#include <cuda_runtime.h>

#define S_LEN 2048
#define D_MODEL 1024
#define N_HEADS 16
#define HEAD_DIM 64
#define TBL 4095        // 2*S - 1
#define TBL_PAD 4096

// ---------------- scratch (static __device__ arrays: sanctioned, no allocs) ----
__device__ float g_Q [S_LEN * D_MODEL];
__device__ float g_K [S_LEN * D_MODEL];   // pre-scaled by 1/sqrt(HD)
__device__ float g_V [S_LEN * D_MODEL];
__device__ float g_AO[S_LEN * D_MODEL];
__device__ float g_QR[(size_t)N_HEADS * S_LEN * TBL_PAD];  // 512 MiB

// =============================================================================
// Kernel 1/4: classic 128x128x8 SGEMM with bias + output scale.
// C[2048,1024] = A[2048,1024] @ B[1024,1024] + bias, *scale.
// blockIdx.z selects one of three argument sets (batched QKV projection).
// =============================================================================
struct GemmArgs {
    const float* A;
    const float* B;
    const float* bias;
    float*       C;
    float        scale;
};

__global__ __launch_bounds__(256) void sgemm_bias_kernel(GemmArgs g0, GemmArgs g1, GemmArgs g2)
{
    GemmArgs g = (blockIdx.z == 0) ? g0 : ((blockIdx.z == 1) ? g1 : g2);

    __shared__ float As[8][132];   // transposed A tile, pad 132 -> conflict-free STS
    __shared__ float Bs[8][128];

    const int tid = threadIdx.x;
    const int tx = tid & 15, ty = tid >> 4;
    const int row0 = blockIdx.y * 128, col0 = blockIdx.x * 128;

    const int la_r = tid >> 1;          // 0..127
    const int la_c = (tid & 1) * 4;     // 0 or 4
    const int lb_r = tid >> 5;          // 0..7
    const int lb_c = (tid & 31) * 4;    // 0..124

    const float* Ap = g.A + (size_t)(row0 + la_r) * D_MODEL + la_c;
    const float* Bp = g.B + (size_t)lb_r * D_MODEL + col0 + lb_c;

    float acc[8][8];
    #pragma unroll
    for (int i = 0; i < 8; i++)
        #pragma unroll
        for (int j = 0; j < 8; j++) acc[i][j] = 0.f;

    for (int k0 = 0; k0 < D_MODEL; k0 += 8) {
        float4 a = *(const float4*)(Ap + k0);
        float4 b = *(const float4*)(Bp + (size_t)k0 * D_MODEL);
        As[la_c + 0][la_r] = a.x;
        As[la_c + 1][la_r] = a.y;
        As[la_c + 2][la_r] = a.z;
        As[la_c + 3][la_r] = a.w;
        *(float4*)&Bs[lb_r][lb_c] = b;
        __syncthreads();

        #pragma unroll
        for (int k = 0; k < 8; k++) {
            float ar[8], br[8];
            *(float4*)&ar[0] = *(const float4*)&As[k][ty * 8];
            *(float4*)&ar[4] = *(const float4*)&As[k][ty * 8 + 4];
            *(float4*)&br[0] = *(const float4*)&Bs[k][tx * 8];
            *(float4*)&br[4] = *(const float4*)&Bs[k][tx * 8 + 4];
            #pragma unroll
            for (int i = 0; i < 8; i++)
                #pragma unroll
                for (int j = 0; j < 8; j++)
                    acc[i][j] += ar[i] * br[j];
        }
        __syncthreads();
    }

    #pragma unroll
    for (int i = 0; i < 8; i++) {
        const int r = row0 + ty * 8 + i;
        #pragma unroll
        for (int jj = 0; jj < 8; jj += 4) {
            const int c = col0 + tx * 8 + jj;
            float4 o;
            o.x = (acc[i][jj + 0] + g.bias[c + 0]) * g.scale;
            o.y = (acc[i][jj + 1] + g.bias[c + 1]) * g.scale;
            o.z = (acc[i][jj + 2] + g.bias[c + 2]) * g.scale;
            o.w = (acc[i][jj + 3] + g.bias[c + 3]) * g.scale;
            *(float4*)&g.C[(size_t)r * D_MODEL + c] = o;
        }
    }
}

// =============================================================================
// Kernel 2/4: qrel GEMM.  QR[h][i][t] = sum_d Q[i, h*64+d] * T[t][d]
// CTA tile: 128 i-rows x 64 t-cols, full K=64 in smem. micro-tile 8x4.
// =============================================================================
#define QREL_SMEM_FLOATS (64 * 132 + 64 * 68)

__global__ __launch_bounds__(256) void qrel_kernel(const float* __restrict__ Q,
                                                   const float* __restrict__ T,
                                                   float* __restrict__ R)
{
    extern __shared__ float sm[];
    float* Qs = sm;               // [64][132], d-major: Qs[d*132 + r]
    float* Ts = sm + 64 * 132;    // [64][68],  d-major: Ts[d*68  + t]

    const int t0 = blockIdx.x * 64;
    const int i0 = blockIdx.y * 128;
    const int h  = blockIdx.z;
    const int tid = threadIdx.x;
    const int tx = tid & 15, ty = tid >> 4;

    #pragma unroll
    for (int rep = 0; rep < 8; rep++) {
        int lin = rep * 1024 + tid * 4;
        int r = lin >> 6, d = lin & 63;
        float4 v = *(const float4*)&Q[(size_t)(i0 + r) * D_MODEL + h * HEAD_DIM + d];
        Qs[(d + 0) * 132 + r] = v.x;
        Qs[(d + 1) * 132 + r] = v.y;
        Qs[(d + 2) * 132 + r] = v.z;
        Qs[(d + 3) * 132 + r] = v.w;
    }
    #pragma unroll
    for (int rep = 0; rep < 4; rep++) {
        int lin = rep * 1024 + tid * 4;
        int t = lin >> 6, d = lin & 63;
        float4 v = make_float4(0.f, 0.f, 0.f, 0.f);
        if (t0 + t < TBL) v = *(const float4*)&T[(size_t)(t0 + t) * HEAD_DIM + d];
        Ts[(d + 0) * 68 + t] = v.x;
        Ts[(d + 1) * 68 + t] = v.y;
        Ts[(d + 2) * 68 + t] = v.z;
        Ts[(d + 3) * 68 + t] = v.w;
    }
    __syncthreads();

    float acc[8][4];
    #pragma unroll
    for (int i = 0; i < 8; i++)
        #pragma unroll
        for (int j = 0; j < 4; j++) acc[i][j] = 0.f;

    #pragma unroll 8
    for (int d = 0; d < 64; d++) {
        float a[8], b[4];
        *(float4*)&a[0] = *(const float4*)&Qs[d * 132 + ty * 8];
        *(float4*)&a[4] = *(const float4*)&Qs[d * 132 + ty * 8 + 4];
        *(float4*)&b[0] = *(const float4*)&Ts[d * 68 + tx * 4];
        #pragma unroll
        for (int i = 0; i < 8; i++)
            #pragma unroll
            for (int j = 0; j < 4; j++)
                acc[i][j] += a[i] * b[j];
    }

    #pragma unroll
    for (int i = 0; i < 8; i++) {
        const int r = i0 + ty * 8 + i;
        *(float4*)&R[(size_t)(h * S_LEN + r) * TBL_PAD + t0 + tx * 4] =
            make_float4(acc[i][0], acc[i][1], acc[i][2], acc[i][3]);
    }
}

// =============================================================================
// Kernel 3/4: flash attention, 128 query rows per CTA per head.
// Score accumulators are INITIALIZED from the gathered rel term (global LDGs
// overlap the K/V smem fill + score FMA loop). K is pre-scaled by 1/8.
// =============================================================================
#define ATTN_SMEM_FLOATS (64 * 132 + 64 * 68 + 64 * 68 + 64 * 132 + 128 + 128)

__global__ __launch_bounds__(256, 2) void attn_kernel(const float* __restrict__ Q,
                                                      const float* __restrict__ K,
                                                      const float* __restrict__ V,
                                                      const float* __restrict__ QR,
                                                      float* __restrict__ AO)
{
    extern __shared__ float sm[];
    float* Qs       = sm;                   // [64][132] d-major: Qs[d*132+r]
    float* Ks       = Qs + 64 * 132;        // [64][68]  d-major: Ks[d*68+c]
    float* Vs       = Ks + 64 * 68;         // [64][68]  c-major: Vs[c*68+d]
    float* ScT      = Vs + 64 * 68;         // [64][132] c-major: ScT[c*132+r]
    float* rowscale = ScT + 64 * 132;       // [128]
    float* rowl     = rowscale + 128;       // [128]

    const int i0 = blockIdx.x * 128;
    const int h  = blockIdx.y;
    const int tid = threadIdx.x;
    const int tx = tid & 15, ty = tid >> 4;

    #pragma unroll
    for (int rep = 0; rep < 8; rep++) {
        int lin = rep * 1024 + tid * 4;
        int r = lin >> 6, d = lin & 63;
        float4 v = *(const float4*)&Q[(size_t)(i0 + r) * D_MODEL + h * HEAD_DIM + d];
        Qs[(d + 0) * 132 + r] = v.x;
        Qs[(d + 1) * 132 + r] = v.y;
        Qs[(d + 2) * 132 + r] = v.z;
        Qs[(d + 3) * 132 + r] = v.w;
    }

    float m_prev = -1e30f, lsum = 0.f;      // valid for tid < 128 (row owner)
    float acc_o[8][4];
    #pragma unroll
    for (int i = 0; i < 8; i++)
        #pragma unroll
        for (int j = 0; j < 4; j++) acc_o[i][j] = 0.f;

    for (int jt = 0; jt < 32; jt++) {
        const int j0 = jt * 64;
        __syncthreads();   // previous tile fully consumed (also orders Qs fill)

        // fill K (d-major) and V (c-major) tiles
        #pragma unroll
        for (int rep = 0; rep < 4; rep++) {
            int lin = rep * 1024 + tid * 4;
            int c = lin >> 6, d = lin & 63;
            float4 kv = *(const float4*)&K[(size_t)(j0 + c) * D_MODEL + h * HEAD_DIM + d];
            Ks[(d + 0) * 68 + c] = kv.x;
            Ks[(d + 1) * 68 + c] = kv.y;
            Ks[(d + 2) * 68 + c] = kv.z;
            Ks[(d + 3) * 68 + c] = kv.w;
            float4 vv = *(const float4*)&V[(size_t)(j0 + c) * D_MODEL + h * HEAD_DIM + d];
            *(float4*)&Vs[c * 68 + d] = vv;
        }

        // init score accumulators with rel term: QR[h, r, r - j + 2047]
        float acc_s[8][4];
        #pragma unroll
        for (int i = 0; i < 8; i++) {
            const int r = i0 + ty * 8 + i;
            const float* qr = QR + (size_t)(h * S_LEN + r) * TBL_PAD + (r - j0 + S_LEN - 1);
            #pragma unroll
            for (int j = 0; j < 4; j++)
                acc_s[i][j] = qr[-(tx * 4 + j)];
        }
        __syncthreads();

        // scores += Q . K' (K' already carries the 1/8 scale)
        #pragma unroll 8
        for (int d = 0; d < 64; d++) {
            float a[8], b[4];
            *(float4*)&a[0] = *(const float4*)&Qs[d * 132 + ty * 8];
            *(float4*)&a[4] = *(const float4*)&Qs[d * 132 + ty * 8 + 4];
            *(float4*)&b[0] = *(const float4*)&Ks[d * 68 + tx * 4];
            #pragma unroll
            for (int i = 0; i < 8; i++)
                #pragma unroll
                for (int j = 0; j < 4; j++)
                    acc_s[i][j] += a[i] * b[j];
        }

        // scatter scores transposed [c][r] (float4 along r)
        #pragma unroll
        for (int j = 0; j < 4; j++) {
            *(float4*)&ScT[(tx * 4 + j) * 132 + ty * 8] =
                make_float4(acc_s[0][j], acc_s[1][j], acc_s[2][j], acc_s[3][j]);
            *(float4*)&ScT[(tx * 4 + j) * 132 + ty * 8 + 4] =
                make_float4(acc_s[4][j], acc_s[5][j], acc_s[6][j], acc_s[7][j]);
        }
        __syncthreads();

        // online softmax, one thread per query row
        if (tid < 128) {
            const int r = tid;
            float mx = -1e30f;
            #pragma unroll 8
            for (int c = 0; c < 64; c++) mx = fmaxf(mx, ScT[c * 132 + r]);
            float m_new = fmaxf(m_prev, mx);
            float corr = __expf(m_prev - m_new);
            float ls = 0.f;
            #pragma unroll 8
            for (int c = 0; c < 64; c++) {
                float p = __expf(ScT[c * 132 + r] - m_new);
                ScT[c * 132 + r] = p;
                ls += p;
            }
            lsum = lsum * corr + ls;
            m_prev = m_new;
            rowscale[r] = corr;
        }
        __syncthreads();

        // rescale output accumulators, then O += P @ V
        #pragma unroll
        for (int i = 0; i < 8; i++) {
            float s = rowscale[ty * 8 + i];
            #pragma unroll
            for (int j = 0; j < 4; j++) acc_o[i][j] *= s;
        }
        #pragma unroll 8
        for (int c = 0; c < 64; c++) {
            float p[8], v[4];
            *(float4*)&p[0] = *(const float4*)&ScT[c * 132 + ty * 8];
            *(float4*)&p[4] = *(const float4*)&ScT[c * 132 + ty * 8 + 4];
            *(float4*)&v[0] = *(const float4*)&Vs[c * 68 + tx * 4];
            #pragma unroll
            for (int i = 0; i < 8; i++)
                #pragma unroll
                for (int j = 0; j < 4; j++)
                    acc_o[i][j] += p[i] * v[j];
        }
    }

    if (tid < 128) rowl[tid] = lsum;
    __syncthreads();

    #pragma unroll
    for (int i = 0; i < 8; i++) {
        const int r = ty * 8 + i;
        const float inv = 1.f / rowl[r];
        *(float4*)&AO[(size_t)(i0 + r) * D_MODEL + h * HEAD_DIM + tx * 4] =
            make_float4(acc_o[i][0] * inv, acc_o[i][1] * inv,
                        acc_o[i][2] * inv, acc_o[i][3] * inv);
    }
}

// =============================================================================
// Launcher
// =============================================================================
extern "C" void kernel_launch(void* const* d_in, const int* in_sizes, int n_in,
                              void* d_out, int out_size)
{
    const float* x   = (const float*)d_in[0];
    const float* Wq  = (const float*)d_in[1];
    const float* bq  = (const float*)d_in[2];
    const float* Wk  = (const float*)d_in[3];
    const float* bk  = (const float*)d_in[4];
    const float* Wv  = (const float*)d_in[5];
    const float* bv  = (const float*)d_in[6];
    const float* Wo  = (const float*)d_in[7];
    const float* bo  = (const float*)d_in[8];
    const float* rel = (const float*)d_in[9];
    float* out = (float*)d_out;

    float *pQ, *pK, *pV, *pAO, *pQR;
    cudaGetSymbolAddress((void**)&pQ,  g_Q);
    cudaGetSymbolAddress((void**)&pK,  g_K);
    cudaGetSymbolAddress((void**)&pV,  g_V);
    cudaGetSymbolAddress((void**)&pAO, g_AO);
    cudaGetSymbolAddress((void**)&pQR, g_QR);

    const int qrel_smem = QREL_SMEM_FLOATS * (int)sizeof(float);   // 51,200 B
    const int attn_smem = ATTN_SMEM_FLOATS * (int)sizeof(float);   // 103,424 B
    cudaFuncSetAttribute(qrel_kernel, cudaFuncAttributeMaxDynamicSharedMemorySize, qrel_smem);
    cudaFuncSetAttribute(attn_kernel, cudaFuncAttributeMaxDynamicSharedMemorySize, attn_smem);

    // 1) fused Q/K/V projections (K folded with 1/sqrt(64))
    GemmArgs gq{ x, Wq, bq, pQ, 1.0f };
    GemmArgs gk{ x, Wk, bk, pK, 0.125f };
    GemmArgs gv{ x, Wv, bv, pV, 1.0f };
    sgemm_bias_kernel<<<dim3(8, 16, 3), 256>>>(gq, gk, gv);

    // 2) qrel = Q @ rel_table^T per head
    qrel_kernel<<<dim3(64, 16, 16), 256, qrel_smem>>>(pQ, rel, pQR);

    // 3) flash attention with gathered rel scores
    attn_kernel<<<dim3(16, 16), 256, attn_smem>>>(pQ, pK, pV, pQR, pAO);

    // 4) output projection
    GemmArgs go{ pAO, Wo, bo, out, 1.0f };
    sgemm_bias_kernel<<<dim3(8, 16, 1), 256>>>(go, go, go);
}

// round 2
// speedup vs baseline: 1.1166x; 1.1166x over previous
#include <cuda_runtime.h>

#define S_LEN 2048
#define D_MODEL 1024
#define N_HEADS 16
#define HEAD_DIM 64
#define TBL 4095        // 2*S - 1
#define KPACK 2048      // packed rel length per row

// ---------------- scratch (static __device__ arrays) -------------------------
__device__ float g_Q [S_LEN * D_MODEL];
__device__ float g_K [S_LEN * D_MODEL];   // pre-scaled by 1/sqrt(HD)
__device__ float g_V [S_LEN * D_MODEL];
__device__ float g_AO[S_LEN * D_MODEL];
__device__ float g_QR[(size_t)N_HEADS * S_LEN * KPACK];  // 256 MiB, packed: QR[h][i][k]=Q[i].T[i+k]

struct GemmArgs {
    const float* A;
    const float* B;
    const float* bias;
    float*       C;
    float        scale;
};

// =============================================================================
// Kernel 1: 128x128x8 SGEMM, double-buffered smem, bias + scale epilogue.
// =============================================================================
__global__ __launch_bounds__(256) void sgemm_bias_kernel(GemmArgs g0, GemmArgs g1, GemmArgs g2)
{
    GemmArgs g = (blockIdx.z == 0) ? g0 : ((blockIdx.z == 1) ? g1 : g2);

    __shared__ float As[2][8][132];
    __shared__ float Bs[2][8][128];

    const int tid = threadIdx.x;
    const int tx = tid & 15, ty = tid >> 4;
    const int row0 = blockIdx.y * 128, col0 = blockIdx.x * 128;

    const int la_r = tid >> 1;
    const int la_c = (tid & 1) * 4;
    const int lb_r = tid >> 5;
    const int lb_c = (tid & 31) * 4;

    const float* Ap = g.A + (size_t)(row0 + la_r) * D_MODEL + la_c;
    const float* Bp = g.B + (size_t)lb_r * D_MODEL + col0 + lb_c;

    float acc[8][8];
    #pragma unroll
    for (int i = 0; i < 8; i++)
        #pragma unroll
        for (int j = 0; j < 8; j++) acc[i][j] = 0.f;

    float4 a = *(const float4*)(Ap);
    float4 b = *(const float4*)(Bp);
    As[0][la_c + 0][la_r] = a.x;
    As[0][la_c + 1][la_r] = a.y;
    As[0][la_c + 2][la_r] = a.z;
    As[0][la_c + 3][la_r] = a.w;
    *(float4*)&Bs[0][lb_r][lb_c] = b;
    __syncthreads();

    int buf = 0;
    for (int k0 = 0; k0 < D_MODEL; k0 += 8) {
        const bool more = (k0 + 8) < D_MODEL;
        if (more) {
            a = *(const float4*)(Ap + k0 + 8);
            b = *(const float4*)(Bp + (size_t)(k0 + 8) * D_MODEL);
        }
        #pragma unroll
        for (int k = 0; k < 8; k++) {
            float ar[8], br[8];
            *(float4*)&ar[0] = *(const float4*)&As[buf][k][ty * 8];
            *(float4*)&ar[4] = *(const float4*)&As[buf][k][ty * 8 + 4];
            *(float4*)&br[0] = *(const float4*)&Bs[buf][k][tx * 8];
            *(float4*)&br[4] = *(const float4*)&Bs[buf][k][tx * 8 + 4];
            #pragma unroll
            for (int i = 0; i < 8; i++)
                #pragma unroll
                for (int j = 0; j < 8; j++)
                    acc[i][j] += ar[i] * br[j];
        }
        if (more) {
            As[buf ^ 1][la_c + 0][la_r] = a.x;
            As[buf ^ 1][la_c + 1][la_r] = a.y;
            As[buf ^ 1][la_c + 2][la_r] = a.z;
            As[buf ^ 1][la_c + 3][la_r] = a.w;
            *(float4*)&Bs[buf ^ 1][lb_r][lb_c] = b;
            __syncthreads();
            buf ^= 1;
        }
    }

    #pragma unroll
    for (int i = 0; i < 8; i++) {
        const int r = row0 + ty * 8 + i;
        #pragma unroll
        for (int jj = 0; jj < 8; jj += 4) {
            const int c = col0 + tx * 8 + jj;
            float4 o;
            o.x = (acc[i][jj + 0] + g.bias[c + 0]) * g.scale;
            o.y = (acc[i][jj + 1] + g.bias[c + 1]) * g.scale;
            o.z = (acc[i][jj + 2] + g.bias[c + 2]) * g.scale;
            o.w = (acc[i][jj + 3] + g.bias[c + 3]) * g.scale;
            *(float4*)&g.C[(size_t)r * D_MODEL + c] = o;
        }
    }
}

// =============================================================================
// Kernel 1b: 128x64x8 SGEMM (more CTAs -> better SM coverage for small GEMMs),
// double-buffered, bias + scale.  Used for the output projection.
// =============================================================================
__global__ __launch_bounds__(256) void sgemm_bias_64_kernel(const float* __restrict__ A,
                                                            const float* __restrict__ B,
                                                            const float* __restrict__ bias,
                                                            float* __restrict__ C)
{
    __shared__ float As[2][8][132];
    __shared__ float Bs[2][8][64];

    const int tid = threadIdx.x;
    const int tx = tid & 15, ty = tid >> 4;
    const int row0 = blockIdx.y * 128, col0 = blockIdx.x * 64;

    const int la_r = tid >> 1;
    const int la_c = (tid & 1) * 4;
    const int lb_r = tid >> 5;          // 0..7
    const int lb_c = (tid & 31) * 2;    // 0..62

    const float* Ap = A + (size_t)(row0 + la_r) * D_MODEL + la_c;
    const float* Bp = B + (size_t)lb_r * D_MODEL + col0 + lb_c;

    float acc[8][4];
    #pragma unroll
    for (int i = 0; i < 8; i++)
        #pragma unroll
        for (int j = 0; j < 4; j++) acc[i][j] = 0.f;

    float4 a = *(const float4*)(Ap);
    float2 b = *(const float2*)(Bp);
    As[0][la_c + 0][la_r] = a.x;
    As[0][la_c + 1][la_r] = a.y;
    As[0][la_c + 2][la_r] = a.z;
    As[0][la_c + 3][la_r] = a.w;
    *(float2*)&Bs[0][lb_r][lb_c] = b;
    __syncthreads();

    int buf = 0;
    for (int k0 = 0; k0 < D_MODEL; k0 += 8) {
        const bool more = (k0 + 8) < D_MODEL;
        if (more) {
            a = *(const float4*)(Ap + k0 + 8);
            b = *(const float2*)(Bp + (size_t)(k0 + 8) * D_MODEL);
        }
        #pragma unroll
        for (int k = 0; k < 8; k++) {
            float ar[8], br[4];
            *(float4*)&ar[0] = *(const float4*)&As[buf][k][ty * 8];
            *(float4*)&ar[4] = *(const float4*)&As[buf][k][ty * 8 + 4];
            *(float4*)&br[0] = *(const float4*)&Bs[buf][k][tx * 4];
            #pragma unroll
            for (int i = 0; i < 8; i++)
                #pragma unroll
                for (int j = 0; j < 4; j++)
                    acc[i][j] += ar[i] * br[j];
        }
        if (more) {
            As[buf ^ 1][la_c + 0][la_r] = a.x;
            As[buf ^ 1][la_c + 1][la_r] = a.y;
            As[buf ^ 1][la_c + 2][la_r] = a.z;
            As[buf ^ 1][la_c + 3][la_r] = a.w;
            *(float2*)&Bs[buf ^ 1][lb_r][lb_c] = b;
            __syncthreads();
            buf ^= 1;
        }
    }

    #pragma unroll
    for (int i = 0; i < 8; i++) {
        const int r = row0 + ty * 8 + i;
        const int c = col0 + tx * 4;
        float4 o;
        o.x = acc[i][0] + bias[c + 0];
        o.y = acc[i][1] + bias[c + 1];
        o.z = acc[i][2] + bias[c + 2];
        o.w = acc[i][3] + bias[c + 3];
        *(float4*)&C[(size_t)r * D_MODEL + c] = o;
    }
}

// =============================================================================
// Kernel 2: packed qrel.  QR[h][i][k] = Q[i]dot T[i+k], k in [0,2048).
// Only t-blocks overlapping [i0, i0+2175) are launched (grid.x = 35).
// Output is diagonal-packed; stores predicated on k range (coalesced rows).
// =============================================================================
#define QREL_SMEM_FLOATS (64 * 132 + 64 * 68)

__global__ __launch_bounds__(256) void qrel_kernel(const float* __restrict__ Q,
                                                   const float* __restrict__ T,
                                                   float* __restrict__ R)
{
    extern __shared__ float sm[];
    float* Qs = sm;               // [64][132], d-major
    float* Ts = sm + 64 * 132;    // [64][68],  d-major

    const int i0 = blockIdx.y * 128;
    const int t0 = i0 + blockIdx.x * 64;   // t range [i0, i0+2240) covers k<2048
    const int h  = blockIdx.z;
    const int tid = threadIdx.x;
    const int tx = tid & 15, ty = tid >> 4;

    #pragma unroll
    for (int rep = 0; rep < 8; rep++) {
        int lin = rep * 1024 + tid * 4;
        int r = lin >> 6, d = lin & 63;
        float4 v = *(const float4*)&Q[(size_t)(i0 + r) * D_MODEL + h * HEAD_DIM + d];
        Qs[(d + 0) * 132 + r] = v.x;
        Qs[(d + 1) * 132 + r] = v.y;
        Qs[(d + 2) * 132 + r] = v.z;
        Qs[(d + 3) * 132 + r] = v.w;
    }
    #pragma unroll
    for (int rep = 0; rep < 4; rep++) {
        int lin = rep * 1024 + tid * 4;
        int t = lin >> 6, d = lin & 63;
        float4 v = make_float4(0.f, 0.f, 0.f, 0.f);
        if (t0 + t < TBL) v = *(const float4*)&T[(size_t)(t0 + t) * HEAD_DIM + d];
        Ts[(d + 0) * 68 + t] = v.x;
        Ts[(d + 1) * 68 + t] = v.y;
        Ts[(d + 2) * 68 + t] = v.z;
        Ts[(d + 3) * 68 + t] = v.w;
    }
    __syncthreads();

    float acc[8][4];
    #pragma unroll
    for (int i = 0; i < 8; i++)
        #pragma unroll
        for (int j = 0; j < 4; j++) acc[i][j] = 0.f;

    #pragma unroll 8
    for (int d = 0; d < 64; d++) {
        float a[8], b[4];
        *(float4*)&a[0] = *(const float4*)&Qs[d * 132 + ty * 8];
        *(float4*)&a[4] = *(const float4*)&Qs[d * 132 + ty * 8 + 4];
        *(float4*)&b[0] = *(const float4*)&Ts[d * 68 + tx * 4];
        #pragma unroll
        for (int i = 0; i < 8; i++)
            #pragma unroll
            for (int j = 0; j < 4; j++)
                acc[i][j] += a[i] * b[j];
    }

    #pragma unroll
    for (int i = 0; i < 8; i++) {
        const int r = i0 + ty * 8 + i;
        float* Rrow = R + (((size_t)(h * S_LEN + r)) << 11);
        #pragma unroll
        for (int j = 0; j < 4; j++) {
            const int k = t0 + tx * 4 + j - r;   // t - i
            if ((unsigned)k < (unsigned)KPACK) Rrow[k] = acc[i][j];
        }
    }
}

// =============================================================================
// Kernel 3: flash attention (unchanged math), gather from packed QR:
// rel[i,j] = QR[h][i][2047 - j].
// =============================================================================
#define ATTN_SMEM_FLOATS (64 * 132 + 64 * 68 + 64 * 68 + 64 * 132 + 128 + 128)

__global__ __launch_bounds__(256, 2) void attn_kernel(const float* __restrict__ Q,
                                                      const float* __restrict__ K,
                                                      const float* __restrict__ V,
                                                      const float* __restrict__ QR,
                                                      float* __restrict__ AO)
{
    extern __shared__ float sm[];
    float* Qs       = sm;                   // [64][132] d-major
    float* Ks       = Qs + 64 * 132;        // [64][68]  d-major
    float* Vs       = Ks + 64 * 68;         // [64][68]  c-major
    float* ScT      = Vs + 64 * 68;         // [64][132] c-major
    float* rowscale = ScT + 64 * 132;
    float* rowl     = rowscale + 128;

    const int i0 = blockIdx.x * 128;
    const int h  = blockIdx.y;
    const int tid = threadIdx.x;
    const int tx = tid & 15, ty = tid >> 4;

    #pragma unroll
    for (int rep = 0; rep < 8; rep++) {
        int lin = rep * 1024 + tid * 4;
        int r = lin >> 6, d = lin & 63;
        float4 v = *(const float4*)&Q[(size_t)(i0 + r) * D_MODEL + h * HEAD_DIM + d];
        Qs[(d + 0) * 132 + r] = v.x;
        Qs[(d + 1) * 132 + r] = v.y;
        Qs[(d + 2) * 132 + r] = v.z;
        Qs[(d + 3) * 132 + r] = v.w;
    }

    float m_prev = -1e30f, lsum = 0.f;
    float acc_o[8][4];
    #pragma unroll
    for (int i = 0; i < 8; i++)
        #pragma unroll
        for (int j = 0; j < 4; j++) acc_o[i][j] = 0.f;

    for (int jt = 0; jt < 32; jt++) {
        const int j0 = jt * 64;
        __syncthreads();

        #pragma unroll
        for (int rep = 0; rep < 4; rep++) {
            int lin = rep * 1024 + tid * 4;
            int c = lin >> 6, d = lin & 63;
            float4 kv = *(const float4*)&K[(size_t)(j0 + c) * D_MODEL + h * HEAD_DIM + d];
            Ks[(d + 0) * 68 + c] = kv.x;
            Ks[(d + 1) * 68 + c] = kv.y;
            Ks[(d + 2) * 68 + c] = kv.z;
            Ks[(d + 3) * 68 + c] = kv.w;
            float4 vv = *(const float4*)&V[(size_t)(j0 + c) * D_MODEL + h * HEAD_DIM + d];
            *(float4*)&Vs[c * 68 + d] = vv;
        }

        // init scores with packed rel term: QR[h][r][2047 - j]
        float acc_s[8][4];
        #pragma unroll
        for (int i = 0; i < 8; i++) {
            const int r = i0 + ty * 8 + i;
            const float* qr = QR + (((size_t)(h * S_LEN + r)) << 11) + (KPACK - 1 - j0);
            #pragma unroll
            for (int j = 0; j < 4; j++)
                acc_s[i][j] = qr[-(tx * 4 + j)];
        }
        __syncthreads();

        #pragma unroll 8
        for (int d = 0; d < 64; d++) {
            float a[8], b[4];
            *(float4*)&a[0] = *(const float4*)&Qs[d * 132 + ty * 8];
            *(float4*)&a[4] = *(const float4*)&Qs[d * 132 + ty * 8 + 4];
            *(float4*)&b[0] = *(const float4*)&Ks[d * 68 + tx * 4];
            #pragma unroll
            for (int i = 0; i < 8; i++)
                #pragma unroll
                for (int j = 0; j < 4; j++)
                    acc_s[i][j] += a[i] * b[j];
        }

        #pragma unroll
        for (int j = 0; j < 4; j++) {
            *(float4*)&ScT[(tx * 4 + j) * 132 + ty * 8] =
                make_float4(acc_s[0][j], acc_s[1][j], acc_s[2][j], acc_s[3][j]);
            *(float4*)&ScT[(tx * 4 + j) * 132 + ty * 8 + 4] =
                make_float4(acc_s[4][j], acc_s[5][j], acc_s[6][j], acc_s[7][j]);
        }
        __syncthreads();

        if (tid < 128) {
            const int r = tid;
            float mx = -1e30f;
            #pragma unroll 8
            for (int c = 0; c < 64; c++) mx = fmaxf(mx, ScT[c * 132 + r]);
            float m_new = fmaxf(m_prev, mx);
            float corr = __expf(m_prev - m_new);
            float ls = 0.f;
            #pragma unroll 8
            for (int c = 0; c < 64; c++) {
                float p = __expf(ScT[c * 132 + r] - m_new);
                ScT[c * 132 + r] = p;
                ls += p;
            }
            lsum = lsum * corr + ls;
            m_prev = m_new;
            rowscale[r] = corr;
        }
        __syncthreads();

        #pragma unroll
        for (int i = 0; i < 8; i++) {
            float s = rowscale[ty * 8 + i];
            #pragma unroll
            for (int j = 0; j < 4; j++) acc_o[i][j] *= s;
        }
        #pragma unroll 8
        for (int c = 0; c < 64; c++) {
            float p[8], v[4];
            *(float4*)&p[0] = *(const float4*)&ScT[c * 132 + ty * 8];
            *(float4*)&p[4] = *(const float4*)&ScT[c * 132 + ty * 8 + 4];
            *(float4*)&v[0] = *(const float4*)&Vs[c * 68 + tx * 4];
            #pragma unroll
            for (int i = 0; i < 8; i++)
                #pragma unroll
                for (int j = 0; j < 4; j++)
                    acc_o[i][j] += p[i] * v[j];
        }
    }

    if (tid < 128) rowl[tid] = lsum;
    __syncthreads();

    #pragma unroll
    for (int i = 0; i < 8; i++) {
        const int r = ty * 8 + i;
        const float inv = 1.f / rowl[r];
        *(float4*)&AO[(size_t)(i0 + r) * D_MODEL + h * HEAD_DIM + tx * 4] =
            make_float4(acc_o[i][0] * inv, acc_o[i][1] * inv,
                        acc_o[i][2] * inv, acc_o[i][3] * inv);
    }
}

// =============================================================================
// Launcher
// =============================================================================
extern "C" void kernel_launch(void* const* d_in, const int* in_sizes, int n_in,
                              void* d_out, int out_size)
{
    const float* x   = (const float*)d_in[0];
    const float* Wq  = (const float*)d_in[1];
    const float* bq  = (const float*)d_in[2];
    const float* Wk  = (const float*)d_in[3];
    const float* bk  = (const float*)d_in[4];
    const float* Wv  = (const float*)d_in[5];
    const float* bv  = (const float*)d_in[6];
    const float* Wo  = (const float*)d_in[7];
    const float* bo  = (const float*)d_in[8];
    const float* rel = (const float*)d_in[9];
    float* out = (float*)d_out;

    float *pQ, *pK, *pV, *pAO, *pQR;
    cudaGetSymbolAddress((void**)&pQ,  g_Q);
    cudaGetSymbolAddress((void**)&pK,  g_K);
    cudaGetSymbolAddress((void**)&pV,  g_V);
    cudaGetSymbolAddress((void**)&pAO, g_AO);
    cudaGetSymbolAddress((void**)&pQR, g_QR);

    const int qrel_smem = QREL_SMEM_FLOATS * (int)sizeof(float);
    const int attn_smem = ATTN_SMEM_FLOATS * (int)sizeof(float);
    cudaFuncSetAttribute(qrel_kernel, cudaFuncAttributeMaxDynamicSharedMemorySize, qrel_smem);
    cudaFuncSetAttribute(attn_kernel, cudaFuncAttributeMaxDynamicSharedMemorySize, attn_smem);

    // 1) fused Q/K/V projections (K folded with 1/sqrt(64))
    GemmArgs gq{ x, Wq, bq, pQ, 1.0f };
    GemmArgs gk{ x, Wk, bk, pK, 0.125f };
    GemmArgs gv{ x, Wv, bv, pV, 1.0f };
    sgemm_bias_kernel<<<dim3(8, 16, 3), 256>>>(gq, gk, gv);

    // 2) packed qrel (only the diagonal band that attention reads)
    qrel_kernel<<<dim3(35, 16, 16), 256, qrel_smem>>>(pQ, rel, pQR);

    // 3) flash attention with packed rel gather
    attn_kernel<<<dim3(16, 16), 256, attn_smem>>>(pQ, pK, pV, pQR, pAO);

    // 4) output projection (128x64 tiles -> 256 CTAs, covers all SMs)
    sgemm_bias_64_kernel<<<dim3(16, 16), 256>>>(pAO, Wo, bo, out);
}

// round 3
// speedup vs baseline: 1.1170x; 1.0003x over previous
#include <cuda_runtime.h>

#define S_LEN 2048
#define D_MODEL 1024
#define N_HEADS 16
#define HEAD_DIM 64
#define TBL 4095        // 2*S - 1
#define KPACK 2048      // packed rel length per row

// ---------------- scratch (static __device__ arrays) -------------------------
__device__ float g_Q [S_LEN * D_MODEL];
__device__ float g_K [S_LEN * D_MODEL];   // pre-scaled by 1/sqrt(HD)
__device__ float g_V [S_LEN * D_MODEL];
__device__ float g_AO[S_LEN * D_MODEL];
__device__ float g_QR[(size_t)N_HEADS * S_LEN * KPACK];  // 256 MiB, packed: QR[h][i][k]=Q[i].T[i+k]

struct GemmArgs {
    const float* A;
    const float* B;
    const float* bias;
    float*       C;
    float        scale;
};

// =============================================================================
// Kernel 1: 128x128x8 SGEMM, double-buffered smem, bias + scale epilogue.
// =============================================================================
__global__ __launch_bounds__(256) void sgemm_bias_kernel(GemmArgs g0, GemmArgs g1, GemmArgs g2)
{
    GemmArgs g = (blockIdx.z == 0) ? g0 : ((blockIdx.z == 1) ? g1 : g2);

    __shared__ float As[2][8][132];
    __shared__ float Bs[2][8][128];

    const int tid = threadIdx.x;
    const int tx = tid & 15, ty = tid >> 4;
    const int row0 = blockIdx.y * 128, col0 = blockIdx.x * 128;

    const int la_r = tid >> 1;
    const int la_c = (tid & 1) * 4;
    const int lb_r = tid >> 5;
    const int lb_c = (tid & 31) * 4;

    const float* Ap = g.A + (size_t)(row0 + la_r) * D_MODEL + la_c;
    const float* Bp = g.B + (size_t)lb_r * D_MODEL + col0 + lb_c;

    float acc[8][8];
    #pragma unroll
    for (int i = 0; i < 8; i++)
        #pragma unroll
        for (int j = 0; j < 8; j++) acc[i][j] = 0.f;

    float4 a = *(const float4*)(Ap);
    float4 b = *(const float4*)(Bp);
    As[0][la_c + 0][la_r] = a.x;
    As[0][la_c + 1][la_r] = a.y;
    As[0][la_c + 2][la_r] = a.z;
    As[0][la_c + 3][la_r] = a.w;
    *(float4*)&Bs[0][lb_r][lb_c] = b;
    __syncthreads();

    int buf = 0;
    for (int k0 = 0; k0 < D_MODEL; k0 += 8) {
        const bool more = (k0 + 8) < D_MODEL;
        if (more) {
            a = *(const float4*)(Ap + k0 + 8);
            b = *(const float4*)(Bp + (size_t)(k0 + 8) * D_MODEL);
        }
        #pragma unroll
        for (int k = 0; k < 8; k++) {
            float ar[8], br[8];
            *(float4*)&ar[0] = *(const float4*)&As[buf][k][ty * 8];
            *(float4*)&ar[4] = *(const float4*)&As[buf][k][ty * 8 + 4];
            *(float4*)&br[0] = *(const float4*)&Bs[buf][k][tx * 8];
            *(float4*)&br[4] = *(const float4*)&Bs[buf][k][tx * 8 + 4];
            #pragma unroll
            for (int i = 0; i < 8; i++)
                #pragma unroll
                for (int j = 0; j < 8; j++)
                    acc[i][j] += ar[i] * br[j];
        }
        if (more) {
            As[buf ^ 1][la_c + 0][la_r] = a.x;
            As[buf ^ 1][la_c + 1][la_r] = a.y;
            As[buf ^ 1][la_c + 2][la_r] = a.z;
            As[buf ^ 1][la_c + 3][la_r] = a.w;
            *(float4*)&Bs[buf ^ 1][lb_r][lb_c] = b;
            __syncthreads();
            buf ^= 1;
        }
    }

    #pragma unroll
    for (int i = 0; i < 8; i++) {
        const int r = row0 + ty * 8 + i;
        #pragma unroll
        for (int jj = 0; jj < 8; jj += 4) {
            const int c = col0 + tx * 8 + jj;
            float4 o;
            o.x = (acc[i][jj + 0] + g.bias[c + 0]) * g.scale;
            o.y = (acc[i][jj + 1] + g.bias[c + 1]) * g.scale;
            o.z = (acc[i][jj + 2] + g.bias[c + 2]) * g.scale;
            o.w = (acc[i][jj + 3] + g.bias[c + 3]) * g.scale;
            *(float4*)&g.C[(size_t)r * D_MODEL + c] = o;
        }
    }
}

// =============================================================================
// Kernel 1b: 128x64x8 SGEMM (more CTAs -> better SM coverage for small GEMMs),
// double-buffered, bias + scale.  Used for the output projection.
// =============================================================================
__global__ __launch_bounds__(256) void sgemm_bias_64_kernel(const float* __restrict__ A,
                                                            const float* __restrict__ B,
                                                            const float* __restrict__ bias,
                                                            float* __restrict__ C)
{
    __shared__ float As[2][8][132];
    __shared__ float Bs[2][8][64];

    const int tid = threadIdx.x;
    const int tx = tid & 15, ty = tid >> 4;
    const int row0 = blockIdx.y * 128, col0 = blockIdx.x * 64;

    const int la_r = tid >> 1;
    const int la_c = (tid & 1) * 4;
    const int lb_r = tid >> 5;          // 0..7
    const int lb_c = (tid & 31) * 2;    // 0..62

    const float* Ap = A + (size_t)(row0 + la_r) * D_MODEL + la_c;
    const float* Bp = B + (size_t)lb_r * D_MODEL + col0 + lb_c;

    float acc[8][4];
    #pragma unroll
    for (int i = 0; i < 8; i++)
        #pragma unroll
        for (int j = 0; j < 4; j++) acc[i][j] = 0.f;

    float4 a = *(const float4*)(Ap);
    float2 b = *(const float2*)(Bp);
    As[0][la_c + 0][la_r] = a.x;
    As[0][la_c + 1][la_r] = a.y;
    As[0][la_c + 2][la_r] = a.z;
    As[0][la_c + 3][la_r] = a.w;
    *(float2*)&Bs[0][lb_r][lb_c] = b;
    __syncthreads();

    int buf = 0;
    for (int k0 = 0; k0 < D_MODEL; k0 += 8) {
        const bool more = (k0 + 8) < D_MODEL;
        if (more) {
            a = *(const float4*)(Ap + k0 + 8);
            b = *(const float2*)(Bp + (size_t)(k0 + 8) * D_MODEL);
        }
        #pragma unroll
        for (int k = 0; k < 8; k++) {
            float ar[8], br[4];
            *(float4*)&ar[0] = *(const float4*)&As[buf][k][ty * 8];
            *(float4*)&ar[4] = *(const float4*)&As[buf][k][ty * 8 + 4];
            *(float4*)&br[0] = *(const float4*)&Bs[buf][k][tx * 4];
            #pragma unroll
            for (int i = 0; i < 8; i++)
                #pragma unroll
                for (int j = 0; j < 4; j++)
                    acc[i][j] += ar[i] * br[j];
        }
        if (more) {
            As[buf ^ 1][la_c + 0][la_r] = a.x;
            As[buf ^ 1][la_c + 1][la_r] = a.y;
            As[buf ^ 1][la_c + 2][la_r] = a.z;
            As[buf ^ 1][la_c + 3][la_r] = a.w;
            *(float2*)&Bs[buf ^ 1][lb_r][lb_c] = b;
            __syncthreads();
            buf ^= 1;
        }
    }

    #pragma unroll
    for (int i = 0; i < 8; i++) {
        const int r = row0 + ty * 8 + i;
        const int c = col0 + tx * 4;
        float4 o;
        o.x = acc[i][0] + bias[c + 0];
        o.y = acc[i][1] + bias[c + 1];
        o.z = acc[i][2] + bias[c + 2];
        o.w = acc[i][3] + bias[c + 3];
        *(float4*)&C[(size_t)r * D_MODEL + c] = o;
    }
}

// =============================================================================
// Kernel 2: packed qrel.  QR[h][i][k] = Q[i]dot T[i+k], k in [0,2048).
// Only t-blocks overlapping [i0, i0+2175) are launched (grid.x = 35).
// Output is diagonal-packed; stores predicated on k range (coalesced rows).
// =============================================================================
#define QREL_SMEM_FLOATS (64 * 132 + 64 * 68)

__global__ __launch_bounds__(256) void qrel_kernel(const float* __restrict__ Q,
                                                   const float* __restrict__ T,
                                                   float* __restrict__ R)
{
    extern __shared__ float sm[];
    float* Qs = sm;               // [64][132], d-major
    float* Ts = sm + 64 * 132;    // [64][68],  d-major

    const int i0 = blockIdx.y * 128;
    const int t0 = i0 + blockIdx.x * 64;   // t range [i0, i0+2240) covers k<2048
    const int h  = blockIdx.z;
    const int tid = threadIdx.x;
    const int tx = tid & 15, ty = tid >> 4;

    #pragma unroll
    for (int rep = 0; rep < 8; rep++) {
        int lin = rep * 1024 + tid * 4;
        int r = lin >> 6, d = lin & 63;
        float4 v = *(const float4*)&Q[(size_t)(i0 + r) * D_MODEL + h * HEAD_DIM + d];
        Qs[(d + 0) * 132 + r] = v.x;
        Qs[(d + 1) * 132 + r] = v.y;
        Qs[(d + 2) * 132 + r] = v.z;
        Qs[(d + 3) * 132 + r] = v.w;
    }
    #pragma unroll
    for (int rep = 0; rep < 4; rep++) {
        int lin = rep * 1024 + tid * 4;
        int t = lin >> 6, d = lin & 63;
        float4 v = make_float4(0.f, 0.f, 0.f, 0.f);
        if (t0 + t < TBL) v = *(const float4*)&T[(size_t)(t0 + t) * HEAD_DIM + d];
        Ts[(d + 0) * 68 + t] = v.x;
        Ts[(d + 1) * 68 + t] = v.y;
        Ts[(d + 2) * 68 + t] = v.z;
        Ts[(d + 3) * 68 + t] = v.w;
    }
    __syncthreads();

    float acc[8][4];
    #pragma unroll
    for (int i = 0; i < 8; i++)
        #pragma unroll
        for (int j = 0; j < 4; j++) acc[i][j] = 0.f;

    #pragma unroll 8
    for (int d = 0; d < 64; d++) {
        float a[8], b[4];
        *(float4*)&a[0] = *(const float4*)&Qs[d * 132 + ty * 8];
        *(float4*)&a[4] = *(const float4*)&Qs[d * 132 + ty * 8 + 4];
        *(float4*)&b[0] = *(const float4*)&Ts[d * 68 + tx * 4];
        #pragma unroll
        for (int i = 0; i < 8; i++)
            #pragma unroll
            for (int j = 0; j < 4; j++)
                acc[i][j] += a[i] * b[j];
    }

    #pragma unroll
    for (int i = 0; i < 8; i++) {
        const int r = i0 + ty * 8 + i;
        float* Rrow = R + (((size_t)(h * S_LEN + r)) << 11);
        #pragma unroll
        for (int j = 0; j < 4; j++) {
            const int k = t0 + tx * 4 + j - r;   // t - i
            if ((unsigned)k < (unsigned)KPACK) Rrow[k] = acc[i][j];
        }
    }
}

// =============================================================================
// Kernel 3: flash attention (unchanged math), gather from packed QR:
// rel[i,j] = QR[h][i][2047 - j].
// =============================================================================
#define ATTN_SMEM_FLOATS (64 * 132 + 64 * 68 + 64 * 68 + 64 * 132 + 128 + 128)

__global__ __launch_bounds__(256, 2) void attn_kernel(const float* __restrict__ Q,
                                                      const float* __restrict__ K,
                                                      const float* __restrict__ V,
                                                      const float* __restrict__ QR,
                                                      float* __restrict__ AO)
{
    extern __shared__ float sm[];
    float* Qs       = sm;                   // [64][132] d-major
    float* Ks       = Qs + 64 * 132;        // [64][68]  d-major
    float* Vs       = Ks + 64 * 68;         // [64][68]  c-major
    float* ScT      = Vs + 64 * 68;         // [64][132] c-major
    float* rowscale = ScT + 64 * 132;
    float* rowl     = rowscale + 128;

    const int i0 = blockIdx.x * 128;
    const int h  = blockIdx.y;
    const int tid = threadIdx.x;
    const int tx = tid & 15, ty = tid >> 4;

    #pragma unroll
    for (int rep = 0; rep < 8; rep++) {
        int lin = rep * 1024 + tid * 4;
        int r = lin >> 6, d = lin & 63;
        float4 v = *(const float4*)&Q[(size_t)(i0 + r) * D_MODEL + h * HEAD_DIM + d];
        Qs[(d + 0) * 132 + r] = v.x;
        Qs[(d + 1) * 132 + r] = v.y;
        Qs[(d + 2) * 132 + r] = v.z;
        Qs[(d + 3) * 132 + r] = v.w;
    }

    float m_prev = -1e30f, lsum = 0.f;
    float acc_o[8][4];
    #pragma unroll
    for (int i = 0; i < 8; i++)
        #pragma unroll
        for (int j = 0; j < 4; j++) acc_o[i][j] = 0.f;

    for (int jt = 0; jt < 32; jt++) {
        const int j0 = jt * 64;
        __syncthreads();

        #pragma unroll
        for (int rep = 0; rep < 4; rep++) {
            int lin = rep * 1024 + tid * 4;
            int c = lin >> 6, d = lin & 63;
            float4 kv = *(const float4*)&K[(size_t)(j0 + c) * D_MODEL + h * HEAD_DIM + d];
            Ks[(d + 0) * 68 + c] = kv.x;
            Ks[(d + 1) * 68 + c] = kv.y;
            Ks[(d + 2) * 68 + c] = kv.z;
            Ks[(d + 3) * 68 + c] = kv.w;
            float4 vv = *(const float4*)&V[(size_t)(j0 + c) * D_MODEL + h * HEAD_DIM + d];
            *(float4*)&Vs[c * 68 + d] = vv;
        }

        // init scores with packed rel term: QR[h][r][2047 - j]
        float acc_s[8][4];
        #pragma unroll
        for (int i = 0; i < 8; i++) {
            const int r = i0 + ty * 8 + i;
            const float* qr = QR + (((size_t)(h * S_LEN + r)) << 11) + (KPACK - 1 - j0);
            #pragma unroll
            for (int j = 0; j < 4; j++)
                acc_s[i][j] = qr[-(tx * 4 + j)];
        }
        __syncthreads();

        #pragma unroll 8
        for (int d = 0; d < 64; d++) {
            float a[8], b[4];
            *(float4*)&a[0] = *(const float4*)&Qs[d * 132 + ty * 8];
            *(float4*)&a[4] = *(const float4*)&Qs[d * 132 + ty * 8 + 4];
            *(float4*)&b[0] = *(const float4*)&Ks[d * 68 + tx * 4];
            #pragma unroll
            for (int i = 0; i < 8; i++)
                #pragma unroll
                for (int j = 0; j < 4; j++)
                    acc_s[i][j] += a[i] * b[j];
        }

        #pragma unroll
        for (int j = 0; j < 4; j++) {
            *(float4*)&ScT[(tx * 4 + j) * 132 + ty * 8] =
                make_float4(acc_s[0][j], acc_s[1][j], acc_s[2][j], acc_s[3][j]);
            *(float4*)&ScT[(tx * 4 + j) * 132 + ty * 8 + 4] =
                make_float4(acc_s[4][j], acc_s[5][j], acc_s[6][j], acc_s[7][j]);
        }
        __syncthreads();

        if (tid < 128) {
            const int r = tid;
            float mx = -1e30f;
            #pragma unroll 8
            for (int c = 0; c < 64; c++) mx = fmaxf(mx, ScT[c * 132 + r]);
            float m_new = fmaxf(m_prev, mx);
            float corr = __expf(m_prev - m_new);
            float ls = 0.f;
            #pragma unroll 8
            for (int c = 0; c < 64; c++) {
                float p = __expf(ScT[c * 132 + r] - m_new);
                ScT[c * 132 + r] = p;
                ls += p;
            }
            lsum = lsum * corr + ls;
            m_prev = m_new;
            rowscale[r] = corr;
        }
        __syncthreads();

        #pragma unroll
        for (int i = 0; i < 8; i++) {
            float s = rowscale[ty * 8 + i];
            #pragma unroll
            for (int j = 0; j < 4; j++) acc_o[i][j] *= s;
        }
        #pragma unroll 8
        for (int c = 0; c < 64; c++) {
            float p[8], v[4];
            *(float4*)&p[0] = *(const float4*)&ScT[c * 132 + ty * 8];
            *(float4*)&p[4] = *(const float4*)&ScT[c * 132 + ty * 8 + 4];
            *(float4*)&v[0] = *(const float4*)&Vs[c * 68 + tx * 4];
            #pragma unroll
            for (int i = 0; i < 8; i++)
                #pragma unroll
                for (int j = 0; j < 4; j++)
                    acc_o[i][j] += p[i] * v[j];
        }
    }

    if (tid < 128) rowl[tid] = lsum;
    __syncthreads();

    #pragma unroll
    for (int i = 0; i < 8; i++) {
        const int r = ty * 8 + i;
        const float inv = 1.f / rowl[r];
        *(float4*)&AO[(size_t)(i0 + r) * D_MODEL + h * HEAD_DIM + tx * 4] =
            make_float4(acc_o[i][0] * inv, acc_o[i][1] * inv,
                        acc_o[i][2] * inv, acc_o[i][3] * inv);
    }
}

// =============================================================================
// Launcher
// =============================================================================
extern "C" void kernel_launch(void* const* d_in, const int* in_sizes, int n_in,
                              void* d_out, int out_size)
{
    const float* x   = (const float*)d_in[0];
    const float* Wq  = (const float*)d_in[1];
    const float* bq  = (const float*)d_in[2];
    const float* Wk  = (const float*)d_in[3];
    const float* bk  = (const float*)d_in[4];
    const float* Wv  = (const float*)d_in[5];
    const float* bv  = (const float*)d_in[6];
    const float* Wo  = (const float*)d_in[7];
    const float* bo  = (const float*)d_in[8];
    const float* rel = (const float*)d_in[9];
    float* out = (float*)d_out;

    float *pQ, *pK, *pV, *pAO, *pQR;
    cudaGetSymbolAddress((void**)&pQ,  g_Q);
    cudaGetSymbolAddress((void**)&pK,  g_K);
    cudaGetSymbolAddress((void**)&pV,  g_V);
    cudaGetSymbolAddress((void**)&pAO, g_AO);
    cudaGetSymbolAddress((void**)&pQR, g_QR);

    const int qrel_smem = QREL_SMEM_FLOATS * (int)sizeof(float);
    const int attn_smem = ATTN_SMEM_FLOATS * (int)sizeof(float);
    cudaFuncSetAttribute(qrel_kernel, cudaFuncAttributeMaxDynamicSharedMemorySize, qrel_smem);
    cudaFuncSetAttribute(attn_kernel, cudaFuncAttributeMaxDynamicSharedMemorySize, attn_smem);

    // 1) fused Q/K/V projections (K folded with 1/sqrt(64))
    GemmArgs gq{ x, Wq, bq, pQ, 1.0f };
    GemmArgs gk{ x, Wk, bk, pK, 0.125f };
    GemmArgs gv{ x, Wv, bv, pV, 1.0f };
    sgemm_bias_kernel<<<dim3(8, 16, 3), 256>>>(gq, gk, gv);

    // 2) packed qrel (only the diagonal band that attention reads)
    qrel_kernel<<<dim3(35, 16, 16), 256, qrel_smem>>>(pQ, rel, pQR);

    // 3) flash attention with packed rel gather
    attn_kernel<<<dim3(16, 16), 256, attn_smem>>>(pQ, pK, pV, pQR, pAO);

    // 4) output projection (128x64 tiles -> 256 CTAs, covers all SMs)
    sgemm_bias_64_kernel<<<dim3(16, 16), 256>>>(pAO, Wo, bo, out);
}

// round 6
// speedup vs baseline: 1.7161x; 1.5364x over previous
#include <cuda_runtime.h>
#include <cuda_bf16.h>
#include <cstdint>

#define S_LEN 2048
#define D_MODEL 1024
#define N_HEADS 16
#define HEAD_DIM 64
#define TBL 4095        // 2*S - 1
#define KPACK 2048      // packed rel length per row
#define TPAD 4096       // padded rel_table rows (rows >= TBL zeroed)

// ---------------- scratch (__device__ arrays, no allocs) ---------------------
__device__ float g_Q [S_LEN * D_MODEL];
__device__ float g_K [S_LEN * D_MODEL];   // pre-scaled by 1/sqrt(HD)
__device__ float g_V [S_LEN * D_MODEL];
__device__ float g_QR[(size_t)N_HEADS * S_LEN * KPACK];  // 256 MiB packed rel

__device__ __nv_bfloat16 g_xh [S_LEN * D_MODEL], g_xl [S_LEN * D_MODEL];
__device__ __nv_bfloat16 g_Qh [S_LEN * D_MODEL], g_Ql [S_LEN * D_MODEL];
__device__ __nv_bfloat16 g_AOh[S_LEN * D_MODEL], g_AOl[S_LEN * D_MODEL];
__device__ __nv_bfloat16 g_Wth[4u * D_MODEL * D_MODEL], g_Wtl[4u * D_MODEL * D_MODEL]; // W^T planes
__device__ __nv_bfloat16 g_Th [TPAD * HEAD_DIM], g_Tl [TPAD * HEAD_DIM];

// ============================ helpers ========================================
__device__ __forceinline__ uint32_t smem_u32(const void* p) {
    uint32_t a;
    asm("{ .reg .u64 t; cvta.to.shared.u64 t, %1; cvt.u32.u64 %0, t; }" : "=r"(a) : "l"(p));
    return a;
}
__device__ __forceinline__ void ldm_x4(uint32_t* r, uint32_t addr) {
    asm volatile("ldmatrix.sync.aligned.m8n8.x4.shared.b16 {%0,%1,%2,%3}, [%4];"
        : "=r"(r[0]), "=r"(r[1]), "=r"(r[2]), "=r"(r[3]) : "r"(addr));
}
__device__ __forceinline__ void mma_bf16(float* c, const uint32_t* a, const uint32_t* b) {
    asm volatile("mma.sync.aligned.m16n8k16.row.col.f32.bf16.bf16.f32 "
        "{%0,%1,%2,%3}, {%4,%5,%6,%7}, {%8,%9}, {%0,%1,%2,%3};"
        : "+f"(c[0]), "+f"(c[1]), "+f"(c[2]), "+f"(c[3])
        : "r"(a[0]), "r"(a[1]), "r"(a[2]), "r"(a[3]), "r"(b[0]), "r"(b[1]));
}
#define CP_ASYNC16(dst, src) \
    asm volatile("cp.async.cg.shared.global [%0], [%1], 16;" :: "r"(dst), "l"(src))
#define CP_COMMIT() asm volatile("cp.async.commit_group;")
#define CP_WAIT(N)  asm volatile("cp.async.wait_group %0;" :: "n"(N) : "memory")

__device__ __forceinline__ void split2(float v, __nv_bfloat16& h, __nv_bfloat16& l) {
    h = __float2bfloat16(v);
    l = __float2bfloat16(v - __bfloat162float(h));
}

// ============================ split kernels ==================================
__global__ void split_plane_kernel(const float* __restrict__ src,
                                   __nv_bfloat16* __restrict__ ph,
                                   __nv_bfloat16* __restrict__ pl, int n4)
{
    int i = blockIdx.x * blockDim.x + threadIdx.x;
    if (i >= n4) return;
    float4 v = *(const float4*)(src + (size_t)i * 4);
    __nv_bfloat16 h, l;
    split2(v.x, h, l); ph[i*4+0] = h; pl[i*4+0] = l;
    split2(v.y, h, l); ph[i*4+1] = h; pl[i*4+1] = l;
    split2(v.z, h, l); ph[i*4+2] = h; pl[i*4+2] = l;
    split2(v.w, h, l); ph[i*4+3] = h; pl[i*4+3] = l;
}

__global__ void split_T_kernel(const float* __restrict__ rel,
                               __nv_bfloat16* __restrict__ th,
                               __nv_bfloat16* __restrict__ tl)
{
    int i = blockIdx.x * blockDim.x + threadIdx.x;   // over TPAD*HEAD_DIM
    if (i >= TPAD * HEAD_DIM) return;
    int t = i >> 6;
    float v = (t < TBL) ? rel[i] : 0.f;
    __nv_bfloat16 h, l; split2(v, h, l);
    th[i] = h; tl[i] = l;
}

struct WSrc { const float* w[4]; };
__global__ __launch_bounds__(256) void wsplit_kernel(WSrc ws,
                                                     __nv_bfloat16* __restrict__ dh,
                                                     __nv_bfloat16* __restrict__ dl)
{
    __shared__ float t[32][33];
    const float* W = ws.w[blockIdx.z];
    __nv_bfloat16* oh = dh + (size_t)blockIdx.z * D_MODEL * D_MODEL;
    __nv_bfloat16* ol = dl + (size_t)blockIdx.z * D_MODEL * D_MODEL;
    const int n0 = blockIdx.x * 32, k0 = blockIdx.y * 32;
    const int tx = threadIdx.x & 31, ty = threadIdx.x >> 5;
    #pragma unroll
    for (int rr = 0; rr < 32; rr += 8)
        t[ty + rr][tx] = W[(size_t)(k0 + ty + rr) * D_MODEL + n0 + tx];
    __syncthreads();
    #pragma unroll
    for (int rr = 0; rr < 32; rr += 8) {
        float v = t[tx][ty + rr];                    // = W[k0+tx][n0+ty+rr]
        __nv_bfloat16 h, l; split2(v, h, l);
        oh[(size_t)(n0 + ty + rr) * D_MODEL + k0 + tx] = h;
        ol[(size_t)(n0 + ty + rr) * D_MODEL + k0 + tx] = l;
    }
}

// ============================ mma.sync projection GEMM =======================
// C[m,n] = sum_k A[m,k] * Wt[n,k]; bf16 hi/lo planes, fp32 accum, bias+scale.
// CTA 128x128, 8 warps (2m x 4n) of 64x32 warp tiles. k chunks of 32,
// double-buffered cp.async. smem rows pitched 40 bf16 (80B) -> conflict-free
// 16B-granule ldmatrix (stride 5 granules covers all 8 residues).
#define GPITCH 40
#define PLANE_B (128 * GPITCH * 2)     // 10240 bytes per plane
#define STAGE_B (4 * PLANE_B)          // 40960 bytes per stage

struct TCArgs {
    const __nv_bfloat16 *Ah, *Al, *Bh, *Bl;
    const float* bias; float* C;
    __nv_bfloat16 *Ch, *Cl;   // optional bf16-split copy of C
    float scale;
};

__global__ __launch_bounds__(256) void tc_gemm_kernel(TCArgs a0, TCArgs a1, TCArgs a2)
{
    TCArgs a = (blockIdx.z == 0) ? a0 : ((blockIdx.z == 1) ? a1 : a2);
    extern __shared__ char dsm[];
    __shared__ float biasS[128];

    const int tid = threadIdx.x, lane = tid & 31, w = tid >> 5;
    const int wm = w >> 2, wn = w & 3;
    const int m0 = blockIdx.y * 128, n0 = blockIdx.x * 128;
    const uint32_t sbase = smem_u32(dsm);

    if (tid < 128) biasS[tid] = a.bias[n0 + tid];

    const __nv_bfloat16* gsrc[4] = { a.Ah, a.Al, a.Bh, a.Bl };
    const int rb[4] = { m0, m0, n0, n0 };

    // prologue: chunk 0 -> stage 0
    #pragma unroll
    for (int p = 0; p < 4; p++) {
        const __nv_bfloat16* g = gsrc[p];
        #pragma unroll
        for (int v = 0; v < 2; v++) {
            const int idx = tid + v * 256;
            const int row = idx >> 2, c16 = idx & 3;
            CP_ASYNC16(sbase + p * PLANE_B + row * 80 + c16 * 16,
                       g + (size_t)(rb[p] + row) * D_MODEL + c16 * 8);
        }
    }
    CP_COMMIT();

    float acc[4][4][4];
    #pragma unroll
    for (int i = 0; i < 4; i++)
        #pragma unroll
        for (int j = 0; j < 4; j++)
            #pragma unroll
            for (int q = 0; q < 4; q++) acc[i][j][q] = 0.f;

    for (int c = 0; c < 32; c++) {
        if (c + 1 < 32) {
            const int k0 = (c + 1) * 32;
            const uint32_t st = sbase + ((c + 1) & 1) * STAGE_B;
            #pragma unroll
            for (int p = 0; p < 4; p++) {
                const __nv_bfloat16* g = gsrc[p];
                #pragma unroll
                for (int v = 0; v < 2; v++) {
                    const int idx = tid + v * 256;
                    const int row = idx >> 2, c16 = idx & 3;
                    CP_ASYNC16(st + p * PLANE_B + row * 80 + c16 * 16,
                               g + (size_t)(rb[p] + row) * D_MODEL + k0 + c16 * 8);
                }
            }
            CP_COMMIT(); CP_WAIT(1);
        } else {
            CP_WAIT(0);
        }
        __syncthreads();

        const uint32_t sb = sbase + (c & 1) * STAGE_B;
        #pragma unroll
        for (int ks = 0; ks < 2; ks++) {
            const uint32_t colb = (uint32_t)(ks * 16 + ((lane >> 4) * 8)) * 2;
            uint32_t ah[4][4], al[4][4], bh[2][4], bl[2][4];
            #pragma unroll
            for (int mt = 0; mt < 4; mt++) {
                const uint32_t r = wm * 64 + mt * 16 + (lane & 15);
                ldm_x4(ah[mt], sb + 0 * PLANE_B + r * 80 + colb);
                ldm_x4(al[mt], sb + 1 * PLANE_B + r * 80 + colb);
            }
            #pragma unroll
            for (int nt2 = 0; nt2 < 2; nt2++) {
                const uint32_t r = wn * 32 + nt2 * 16 + (lane & 15);
                ldm_x4(bh[nt2], sb + 2 * PLANE_B + r * 80 + colb);
                ldm_x4(bl[nt2], sb + 3 * PLANE_B + r * 80 + colb);
            }
            #pragma unroll
            for (int mt = 0; mt < 4; mt++)
                #pragma unroll
                for (int nt = 0; nt < 4; nt++) {
                    uint32_t bhf[2] = { bh[nt >> 1][nt & 1], bh[nt >> 1][(nt & 1) + 2] };
                    uint32_t blf[2] = { bl[nt >> 1][nt & 1], bl[nt >> 1][(nt & 1) + 2] };
                    mma_bf16(acc[mt][nt], ah[mt], bhf);
                    mma_bf16(acc[mt][nt], ah[mt], blf);
                    mma_bf16(acc[mt][nt], al[mt], bhf);
                }
        }
        __syncthreads();
    }

    // epilogue
    #pragma unroll
    for (int mt = 0; mt < 4; mt++) {
        const int r0 = m0 + wm * 64 + mt * 16 + (lane >> 2);
        #pragma unroll
        for (int nt = 0; nt < 4; nt++) {
            const int cl = wn * 32 + nt * 8 + 2 * (lane & 3);
            const int cg = n0 + cl;
            float2 v0, v1;
            v0.x = (acc[mt][nt][0] + biasS[cl + 0]) * a.scale;
            v0.y = (acc[mt][nt][1] + biasS[cl + 1]) * a.scale;
            v1.x = (acc[mt][nt][2] + biasS[cl + 0]) * a.scale;
            v1.y = (acc[mt][nt][3] + biasS[cl + 1]) * a.scale;
            *(float2*)&a.C[(size_t)r0 * D_MODEL + cg]       = v0;
            *(float2*)&a.C[(size_t)(r0 + 8) * D_MODEL + cg] = v1;
            if (a.Ch) {
                __nv_bfloat16 h0,l0,h1,l1;
                split2(v0.x,h0,l0); split2(v0.y,h1,l1);
                *(__nv_bfloat162*)&a.Ch[(size_t)r0 * D_MODEL + cg] = __nv_bfloat162{h0,h1};
                *(__nv_bfloat162*)&a.Cl[(size_t)r0 * D_MODEL + cg] = __nv_bfloat162{l0,l1};
                split2(v1.x,h0,l0); split2(v1.y,h1,l1);
                *(__nv_bfloat162*)&a.Ch[(size_t)(r0 + 8) * D_MODEL + cg] = __nv_bfloat162{h0,h1};
                *(__nv_bfloat162*)&a.Cl[(size_t)(r0 + 8) * D_MODEL + cg] = __nv_bfloat162{l0,l1};
            }
        }
    }
}

// ============================ mma.sync qrel ==================================
// QR[h][i][k] = Q[i,h,:].T[i+k,:], k in [0,2048). CTA = (t-tile, i-block, head):
// 128(i) x 128(t) tile, K=64 one shot. Pitch 72 bf16 (144B; stride 9 granules
// mod 8 covers all residues). Predicated packed store straight from fragments.
#define QPITCH 72
#define QPLANE_B (128 * QPITCH * 2)    // 18432 bytes

__global__ __launch_bounds__(256) void tc_qrel_kernel(const __nv_bfloat16* __restrict__ Qh,
                                                      const __nv_bfloat16* __restrict__ Ql,
                                                      const __nv_bfloat16* __restrict__ Th,
                                                      const __nv_bfloat16* __restrict__ Tl,
                                                      float* __restrict__ R)
{
    extern __shared__ char dsm[];
    const int tid = threadIdx.x, lane = tid & 31, w = tid >> 5;
    const int wm = w >> 2, wn = w & 3;
    const int tt = blockIdx.x, i0 = blockIdx.y * 128, h = blockIdx.z;
    const int t0 = i0 + tt * 128;
    const uint32_t sbase = smem_u32(dsm);

    #pragma unroll
    for (int p = 0; p < 4; p++) {
        #pragma unroll
        for (int v = 0; v < 4; v++) {
            const int idx = tid + v * 256;
            const int row = idx >> 3, c16 = idx & 7;
            const __nv_bfloat16* src;
            if (p == 0)      src = Qh + (size_t)(i0 + row) * D_MODEL + h * HEAD_DIM + c16 * 8;
            else if (p == 1) src = Ql + (size_t)(i0 + row) * D_MODEL + h * HEAD_DIM + c16 * 8;
            else if (p == 2) src = Th + (size_t)(t0 + row) * HEAD_DIM + c16 * 8;
            else             src = Tl + (size_t)(t0 + row) * HEAD_DIM + c16 * 8;
            CP_ASYNC16(sbase + p * QPLANE_B + row * 144 + c16 * 16, src);
        }
    }
    CP_COMMIT(); CP_WAIT(0);
    __syncthreads();

    float acc[4][4][4];
    #pragma unroll
    for (int i = 0; i < 4; i++)
        #pragma unroll
        for (int j = 0; j < 4; j++)
            #pragma unroll
            for (int q = 0; q < 4; q++) acc[i][j][q] = 0.f;

    #pragma unroll
    for (int ks = 0; ks < 4; ks++) {
        const uint32_t colb = (uint32_t)(ks * 16 + ((lane >> 4) * 8)) * 2;
        uint32_t ah[4][4], al[4][4], bh[2][4], bl[2][4];
        #pragma unroll
        for (int mt = 0; mt < 4; mt++) {
            const uint32_t r = wm * 64 + mt * 16 + (lane & 15);
            ldm_x4(ah[mt], sbase + 0 * QPLANE_B + r * 144 + colb);
            ldm_x4(al[mt], sbase + 1 * QPLANE_B + r * 144 + colb);
        }
        #pragma unroll
        for (int nt2 = 0; nt2 < 2; nt2++) {
            const uint32_t r = wn * 32 + nt2 * 16 + (lane & 15);
            ldm_x4(bh[nt2], sbase + 2 * QPLANE_B + r * 144 + colb);
            ldm_x4(bl[nt2], sbase + 3 * QPLANE_B + r * 144 + colb);
        }
        #pragma unroll
        for (int mt = 0; mt < 4; mt++)
            #pragma unroll
            for (int nt = 0; nt < 4; nt++) {
                uint32_t bhf[2] = { bh[nt >> 1][nt & 1], bh[nt >> 1][(nt & 1) + 2] };
                uint32_t blf[2] = { bl[nt >> 1][nt & 1], bl[nt >> 1][(nt & 1) + 2] };
                mma_bf16(acc[mt][nt], ah[mt], bhf);
                mma_bf16(acc[mt][nt], ah[mt], blf);
                mma_bf16(acc[mt][nt], al[mt], bhf);
            }
    }

    // predicated packed store: k = tt*128 + cloc - iloc
    #pragma unroll
    for (int mt = 0; mt < 4; mt++) {
        const int rloc = wm * 64 + mt * 16 + (lane >> 2);
        float* Rrow0 = R + (((size_t)(h * S_LEN + i0 + rloc))     << 11);
        float* Rrow1 = R + (((size_t)(h * S_LEN + i0 + rloc + 8)) << 11);
        #pragma unroll
        for (int nt = 0; nt < 4; nt++) {
            const int cloc = wn * 32 + nt * 8 + 2 * (lane & 3);
            const int k0 = tt * 128 + cloc - rloc;
            if ((unsigned)(k0)     < (unsigned)KPACK) Rrow0[k0]     = acc[mt][nt][0];
            if ((unsigned)(k0 + 1) < (unsigned)KPACK) Rrow0[k0 + 1] = acc[mt][nt][1];
            if ((unsigned)(k0 - 8) < (unsigned)KPACK) Rrow1[k0 - 8] = acc[mt][nt][2];
            if ((unsigned)(k0 - 7) < (unsigned)KPACK) Rrow1[k0 - 7] = acc[mt][nt][3];
        }
    }
}

// ============================ flash attention (fp32) =========================
#define ATTN_SMEM_FLOATS (64 * 132 + 64 * 68 + 64 * 68 + 64 * 132 + 128 + 128)

__global__ __launch_bounds__(256, 2) void attn_kernel(const float* __restrict__ Q,
                                                      const float* __restrict__ K,
                                                      const float* __restrict__ V,
                                                      const float* __restrict__ QR,
                                                      __nv_bfloat16* __restrict__ AOh,
                                                      __nv_bfloat16* __restrict__ AOl)
{
    extern __shared__ float sm[];
    float* Qs       = sm;
    float* Ks       = Qs + 64 * 132;
    float* Vs       = Ks + 64 * 68;
    float* ScT      = Vs + 64 * 68;
    float* rowscale = ScT + 64 * 132;
    float* rowl     = rowscale + 128;

    const int i0 = blockIdx.x * 128;
    const int h  = blockIdx.y;
    const int tid = threadIdx.x;
    const int tx = tid & 15, ty = tid >> 4;

    #pragma unroll
    for (int rep = 0; rep < 8; rep++) {
        int lin = rep * 1024 + tid * 4;
        int r = lin >> 6, d = lin & 63;
        float4 v = *(const float4*)&Q[(size_t)(i0 + r) * D_MODEL + h * HEAD_DIM + d];
        Qs[(d + 0) * 132 + r] = v.x;
        Qs[(d + 1) * 132 + r] = v.y;
        Qs[(d + 2) * 132 + r] = v.z;
        Qs[(d + 3) * 132 + r] = v.w;
    }

    float m_prev = -1e30f, lsum = 0.f;
    float acc_o[8][4];
    #pragma unroll
    for (int i = 0; i < 8; i++)
        #pragma unroll
        for (int j = 0; j < 4; j++) acc_o[i][j] = 0.f;

    for (int jt = 0; jt < 32; jt++) {
        const int j0 = jt * 64;
        __syncthreads();

        #pragma unroll
        for (int rep = 0; rep < 4; rep++) {
            int lin = rep * 1024 + tid * 4;
            int c = lin >> 6, d = lin & 63;
            float4 kv = *(const float4*)&K[(size_t)(j0 + c) * D_MODEL + h * HEAD_DIM + d];
            Ks[(d + 0) * 68 + c] = kv.x;
            Ks[(d + 1) * 68 + c] = kv.y;
            Ks[(d + 2) * 68 + c] = kv.z;
            Ks[(d + 3) * 68 + c] = kv.w;
            float4 vv = *(const float4*)&V[(size_t)(j0 + c) * D_MODEL + h * HEAD_DIM + d];
            *(float4*)&Vs[c * 68 + d] = vv;
        }

        float acc_s[8][4];
        #pragma unroll
        for (int i = 0; i < 8; i++) {
            const int r = i0 + ty * 8 + i;
            const float* qr = QR + (((size_t)(h * S_LEN + r)) << 11) + (KPACK - 1 - j0);
            #pragma unroll
            for (int j = 0; j < 4; j++)
                acc_s[i][j] = qr[-(tx * 4 + j)];
        }
        __syncthreads();

        #pragma unroll 8
        for (int d = 0; d < 64; d++) {
            float a[8], b[4];
            *(float4*)&a[0] = *(const float4*)&Qs[d * 132 + ty * 8];
            *(float4*)&a[4] = *(const float4*)&Qs[d * 132 + ty * 8 + 4];
            *(float4*)&b[0] = *(const float4*)&Ks[d * 68 + tx * 4];
            #pragma unroll
            for (int i = 0; i < 8; i++)
                #pragma unroll
                for (int j = 0; j < 4; j++)
                    acc_s[i][j] += a[i] * b[j];
        }

        #pragma unroll
        for (int j = 0; j < 4; j++) {
            *(float4*)&ScT[(tx * 4 + j) * 132 + ty * 8] =
                make_float4(acc_s[0][j], acc_s[1][j], acc_s[2][j], acc_s[3][j]);
            *(float4*)&ScT[(tx * 4 + j) * 132 + ty * 8 + 4] =
                make_float4(acc_s[4][j], acc_s[5][j], acc_s[6][j], acc_s[7][j]);
        }
        __syncthreads();

        if (tid < 128) {
            const int r = tid;
            float mx = -1e30f;
            #pragma unroll 8
            for (int c = 0; c < 64; c++) mx = fmaxf(mx, ScT[c * 132 + r]);
            float m_new = fmaxf(m_prev, mx);
            float corr = __expf(m_prev - m_new);
            float ls = 0.f;
            #pragma unroll 8
            for (int c = 0; c < 64; c++) {
                float p = __expf(ScT[c * 132 + r] - m_new);
                ScT[c * 132 + r] = p;
                ls += p;
            }
            lsum = lsum * corr + ls;
            m_prev = m_new;
            rowscale[r] = corr;
        }
        __syncthreads();

        #pragma unroll
        for (int i = 0; i < 8; i++) {
            float s = rowscale[ty * 8 + i];
            #pragma unroll
            for (int j = 0; j < 4; j++) acc_o[i][j] *= s;
        }
        #pragma unroll 8
        for (int c = 0; c < 64; c++) {
            float p[8], v[4];
            *(float4*)&p[0] = *(const float4*)&ScT[c * 132 + ty * 8];
            *(float4*)&p[4] = *(const float4*)&ScT[c * 132 + ty * 8 + 4];
            *(float4*)&v[0] = *(const float4*)&Vs[c * 68 + tx * 4];
            #pragma unroll
            for (int i = 0; i < 8; i++)
                #pragma unroll
                for (int j = 0; j < 4; j++)
                    acc_o[i][j] += p[i] * v[j];
        }
    }

    if (tid < 128) rowl[tid] = lsum;
    __syncthreads();

    #pragma unroll
    for (int i = 0; i < 8; i++) {
        const int r = ty * 8 + i;
        const float inv = 1.f / rowl[r];
        const size_t idx = (size_t)(i0 + r) * D_MODEL + h * HEAD_DIM + tx * 4;
        float4 o = make_float4(acc_o[i][0] * inv, acc_o[i][1] * inv,
                               acc_o[i][2] * inv, acc_o[i][3] * inv);
        __nv_bfloat16 h0,l0,h1,l1,h2,l2,h3,l3;
        split2(o.x,h0,l0); split2(o.y,h1,l1); split2(o.z,h2,l2); split2(o.w,h3,l3);
        __nv_bfloat162* Hp = (__nv_bfloat162*)&AOh[idx];
        __nv_bfloat162* Lp = (__nv_bfloat162*)&AOl[idx];
        Hp[0] = __nv_bfloat162{h0,h1}; Hp[1] = __nv_bfloat162{h2,h3};
        Lp[0] = __nv_bfloat162{l0,l1}; Lp[1] = __nv_bfloat162{l2,l3};
    }
}

// ============================ Launcher =======================================
extern "C" void kernel_launch(void* const* d_in, const int* in_sizes, int n_in,
                              void* d_out, int out_size)
{
    const float* x   = (const float*)d_in[0];
    const float* Wq  = (const float*)d_in[1];
    const float* bq  = (const float*)d_in[2];
    const float* Wk  = (const float*)d_in[3];
    const float* bk  = (const float*)d_in[4];
    const float* Wv  = (const float*)d_in[5];
    const float* bv  = (const float*)d_in[6];
    const float* Wo  = (const float*)d_in[7];
    const float* bo  = (const float*)d_in[8];
    const float* rel = (const float*)d_in[9];
    float* out = (float*)d_out;

    float *pQ, *pK, *pV, *pQR;
    __nv_bfloat16 *pxh, *pxl, *pQhS, *pQlS, *pAOh, *pAOl, *pWth, *pWtl, *pTh, *pTl;
    cudaGetSymbolAddress((void**)&pQ,   g_Q);
    cudaGetSymbolAddress((void**)&pK,   g_K);
    cudaGetSymbolAddress((void**)&pV,   g_V);
    cudaGetSymbolAddress((void**)&pQR,  g_QR);
    cudaGetSymbolAddress((void**)&pxh,  g_xh);
    cudaGetSymbolAddress((void**)&pxl,  g_xl);
    cudaGetSymbolAddress((void**)&pQhS, g_Qh);
    cudaGetSymbolAddress((void**)&pQlS, g_Ql);
    cudaGetSymbolAddress((void**)&pAOh, g_AOh);
    cudaGetSymbolAddress((void**)&pAOl, g_AOl);
    cudaGetSymbolAddress((void**)&pWth, g_Wth);
    cudaGetSymbolAddress((void**)&pWtl, g_Wtl);
    cudaGetSymbolAddress((void**)&pTh,  g_Th);
    cudaGetSymbolAddress((void**)&pTl,  g_Tl);

    const int gemm_smem = 2 * STAGE_B;                 // 81,920
    const int qrel_smem = 4 * QPLANE_B;                // 73,728
    const int attn_smem = ATTN_SMEM_FLOATS * (int)sizeof(float);
    cudaFuncSetAttribute(tc_gemm_kernel, cudaFuncAttributeMaxDynamicSharedMemorySize, gemm_smem);
    cudaFuncSetAttribute(tc_qrel_kernel, cudaFuncAttributeMaxDynamicSharedMemorySize, qrel_smem);
    cudaFuncSetAttribute(attn_kernel,    cudaFuncAttributeMaxDynamicSharedMemorySize, attn_smem);

    // 0) splits: x, W^T (x4), rel_table
    split_plane_kernel<<<(S_LEN * D_MODEL / 4 + 255) / 256, 256>>>(x, pxh, pxl, S_LEN * D_MODEL / 4);
    WSrc ws; ws.w[0] = Wq; ws.w[1] = Wk; ws.w[2] = Wv; ws.w[3] = Wo;
    wsplit_kernel<<<dim3(32, 32, 4), 256>>>(ws, pWth, pWtl);
    split_T_kernel<<<(TPAD * HEAD_DIM + 255) / 256, 256>>>(rel, pTh, pTl);

    const size_t MM = (size_t)D_MODEL * D_MODEL;

    // 1) QKV projections (mma.sync split-bf16); Q also emits bf16 planes
    TCArgs aq{ pxh, pxl, pWth + 0*MM, pWtl + 0*MM, bq, pQ, pQhS, pQlS, 1.0f };
    TCArgs ak{ pxh, pxl, pWth + 1*MM, pWtl + 1*MM, bk, pK, nullptr, nullptr, 0.125f };
    TCArgs av{ pxh, pxl, pWth + 2*MM, pWtl + 2*MM, bv, pV, nullptr, nullptr, 1.0f };
    tc_gemm_kernel<<<dim3(8, 16, 3), 256, gemm_smem>>>(aq, ak, av);

    // 2) packed banded qrel (mma.sync)
    tc_qrel_kernel<<<dim3(17, 16, 16), 256, qrel_smem>>>(pQhS, pQlS, pTh, pTl, pQR);

    // 3) flash attention (fp32), emits AO bf16 planes directly
    attn_kernel<<<dim3(16, 16), 256, attn_smem>>>(pQ, pK, pV, pQR, pAOh, pAOl);

    // 4) output projection (mma.sync)
    float* dummy = pQ;  // unused scratch for C (out is the real target)
    TCArgs ao{ pAOh, pAOl, pWth + 3*MM, pWtl + 3*MM, bo, out, nullptr, nullptr, 1.0f };
    (void)dummy;
    tc_gemm_kernel<<<dim3(8, 16, 1), 256, gemm_smem>>>(ao, ao, ao);
}

// round 8
// speedup vs baseline: 2.3877x; 1.3914x over previous
#include <cuda_runtime.h>
#include <cuda_bf16.h>
#include <cstdint>

#define S_LEN 2048
#define D_MODEL 1024
#define N_HEADS 16
#define HEAD_DIM 64
#define TBL 4095        // 2*S - 1
#define KPACK 2048      // packed rel length per row
#define TPAD 4096       // padded rel_table rows (rows >= TBL zeroed)

// ---------------- scratch (__device__ arrays, no allocs) ---------------------
__device__ float g_QR[(size_t)N_HEADS * S_LEN * KPACK];  // 256 MiB packed rel

__device__ __nv_bfloat16 g_xh [S_LEN * D_MODEL], g_xl [S_LEN * D_MODEL];
__device__ __nv_bfloat16 g_Qh [S_LEN * D_MODEL], g_Ql [S_LEN * D_MODEL];
__device__ __nv_bfloat16 g_Kh [S_LEN * D_MODEL], g_Kl [S_LEN * D_MODEL];
__device__ __nv_bfloat16 g_Vh [S_LEN * D_MODEL], g_Vl [S_LEN * D_MODEL];
__device__ __nv_bfloat16 g_AOh[S_LEN * D_MODEL], g_AOl[S_LEN * D_MODEL];
__device__ __nv_bfloat16 g_Wth[4u * D_MODEL * D_MODEL], g_Wtl[4u * D_MODEL * D_MODEL];
__device__ __nv_bfloat16 g_Th [TPAD * HEAD_DIM], g_Tl [TPAD * HEAD_DIM];

// ============================ helpers ========================================
__device__ __forceinline__ uint32_t smem_u32(const void* p) {
    uint32_t a;
    asm("{ .reg .u64 t; cvta.to.shared.u64 t, %1; cvt.u32.u64 %0, t; }" : "=r"(a) : "l"(p));
    return a;
}
__device__ __forceinline__ void ldm_x4(uint32_t* r, uint32_t addr) {
    asm volatile("ldmatrix.sync.aligned.m8n8.x4.shared.b16 {%0,%1,%2,%3}, [%4];"
        : "=r"(r[0]), "=r"(r[1]), "=r"(r[2]), "=r"(r[3]) : "r"(addr));
}
__device__ __forceinline__ void ldm_x4_t(uint32_t* r, uint32_t addr) {
    asm volatile("ldmatrix.sync.aligned.m8n8.x4.trans.shared.b16 {%0,%1,%2,%3}, [%4];"
        : "=r"(r[0]), "=r"(r[1]), "=r"(r[2]), "=r"(r[3]) : "r"(addr));
}
__device__ __forceinline__ void mma_bf16(float* c, const uint32_t* a, const uint32_t* b) {
    asm volatile("mma.sync.aligned.m16n8k16.row.col.f32.bf16.bf16.f32 "
        "{%0,%1,%2,%3}, {%4,%5,%6,%7}, {%8,%9}, {%0,%1,%2,%3};"
        : "+f"(c[0]), "+f"(c[1]), "+f"(c[2]), "+f"(c[3])
        : "r"(a[0]), "r"(a[1]), "r"(a[2]), "r"(a[3]), "r"(b[0]), "r"(b[1]));
}
#define CP_ASYNC16(dst, src) \
    asm volatile("cp.async.cg.shared.global [%0], [%1], 16;" :: "r"(dst), "l"(src))
#define CP_COMMIT() asm volatile("cp.async.commit_group;")
#define CP_WAIT(N)  asm volatile("cp.async.wait_group %0;" :: "n"(N) : "memory")

__device__ __forceinline__ void split2(float v, __nv_bfloat16& h, __nv_bfloat16& l) {
    h = __float2bfloat16(v);
    l = __float2bfloat16(v - __bfloat162float(h));
}
__device__ __forceinline__ uint32_t pack2(__nv_bfloat16 lo, __nv_bfloat16 hi) {
    __nv_bfloat162 t{lo, hi};
    return *(uint32_t*)&t;
}

// ============================ split kernels ==================================
__global__ void split_plane_kernel(const float* __restrict__ src,
                                   __nv_bfloat16* __restrict__ ph,
                                   __nv_bfloat16* __restrict__ pl, int n4)
{
    int i = blockIdx.x * blockDim.x + threadIdx.x;
    if (i >= n4) return;
    float4 v = *(const float4*)(src + (size_t)i * 4);
    __nv_bfloat16 h, l;
    split2(v.x, h, l); ph[i*4+0] = h; pl[i*4+0] = l;
    split2(v.y, h, l); ph[i*4+1] = h; pl[i*4+1] = l;
    split2(v.z, h, l); ph[i*4+2] = h; pl[i*4+2] = l;
    split2(v.w, h, l); ph[i*4+3] = h; pl[i*4+3] = l;
}

__global__ void split_T_kernel(const float* __restrict__ rel,
                               __nv_bfloat16* __restrict__ th,
                               __nv_bfloat16* __restrict__ tl)
{
    int i = blockIdx.x * blockDim.x + threadIdx.x;
    if (i >= TPAD * HEAD_DIM) return;
    int t = i >> 6;
    float v = (t < TBL) ? rel[i] : 0.f;
    __nv_bfloat16 h, l; split2(v, h, l);
    th[i] = h; tl[i] = l;
}

struct WSrc { const float* w[4]; };
__global__ __launch_bounds__(256) void wsplit_kernel(WSrc ws,
                                                     __nv_bfloat16* __restrict__ dh,
                                                     __nv_bfloat16* __restrict__ dl)
{
    __shared__ float t[32][33];
    const float* W = ws.w[blockIdx.z];
    __nv_bfloat16* oh = dh + (size_t)blockIdx.z * D_MODEL * D_MODEL;
    __nv_bfloat16* ol = dl + (size_t)blockIdx.z * D_MODEL * D_MODEL;
    const int n0 = blockIdx.x * 32, k0 = blockIdx.y * 32;
    const int tx = threadIdx.x & 31, ty = threadIdx.x >> 5;
    #pragma unroll
    for (int rr = 0; rr < 32; rr += 8)
        t[ty + rr][tx] = W[(size_t)(k0 + ty + rr) * D_MODEL + n0 + tx];
    __syncthreads();
    #pragma unroll
    for (int rr = 0; rr < 32; rr += 8) {
        float v = t[tx][ty + rr];
        __nv_bfloat16 h, l; split2(v, h, l);
        oh[(size_t)(n0 + ty + rr) * D_MODEL + k0 + tx] = h;
        ol[(size_t)(n0 + ty + rr) * D_MODEL + k0 + tx] = l;
    }
}

// ============================ mma.sync projection GEMM =======================
#define GPITCH 40
#define PLANE_B (128 * GPITCH * 2)     // 10240 bytes per plane
#define STAGE_B (4 * PLANE_B)          // 40960 bytes per stage

struct TCArgs {
    const __nv_bfloat16 *Ah, *Al, *Bh, *Bl;
    const float* bias; float* C;       // C may be null (bf16-only output)
    __nv_bfloat16 *Ch, *Cl;            // may be null (fp32-only output)
    float scale;
};

__global__ __launch_bounds__(256) void tc_gemm_kernel(TCArgs a0, TCArgs a1, TCArgs a2)
{
    TCArgs a = (blockIdx.z == 0) ? a0 : ((blockIdx.z == 1) ? a1 : a2);
    extern __shared__ char dsm[];
    __shared__ float biasS[128];

    const int tid = threadIdx.x, lane = tid & 31, w = tid >> 5;
    const int wm = w >> 2, wn = w & 3;
    const int m0 = blockIdx.y * 128, n0 = blockIdx.x * 128;
    const uint32_t sbase = smem_u32(dsm);

    if (tid < 128) biasS[tid] = a.bias[n0 + tid];

    const __nv_bfloat16* gsrc[4] = { a.Ah, a.Al, a.Bh, a.Bl };
    const int rb[4] = { m0, m0, n0, n0 };

    #pragma unroll
    for (int p = 0; p < 4; p++) {
        const __nv_bfloat16* g = gsrc[p];
        #pragma unroll
        for (int v = 0; v < 2; v++) {
            const int idx = tid + v * 256;
            const int row = idx >> 2, c16 = idx & 3;
            CP_ASYNC16(sbase + p * PLANE_B + row * 80 + c16 * 16,
                       g + (size_t)(rb[p] + row) * D_MODEL + c16 * 8);
        }
    }
    CP_COMMIT();

    float acc[4][4][4];
    #pragma unroll
    for (int i = 0; i < 4; i++)
        #pragma unroll
        for (int j = 0; j < 4; j++)
            #pragma unroll
            for (int q = 0; q < 4; q++) acc[i][j][q] = 0.f;

    for (int c = 0; c < 32; c++) {
        if (c + 1 < 32) {
            const int k0 = (c + 1) * 32;
            const uint32_t st = sbase + ((c + 1) & 1) * STAGE_B;
            #pragma unroll
            for (int p = 0; p < 4; p++) {
                const __nv_bfloat16* g = gsrc[p];
                #pragma unroll
                for (int v = 0; v < 2; v++) {
                    const int idx = tid + v * 256;
                    const int row = idx >> 2, c16 = idx & 3;
                    CP_ASYNC16(st + p * PLANE_B + row * 80 + c16 * 16,
                               g + (size_t)(rb[p] + row) * D_MODEL + k0 + c16 * 8);
                }
            }
            CP_COMMIT(); CP_WAIT(1);
        } else {
            CP_WAIT(0);
        }
        __syncthreads();

        const uint32_t sb = sbase + (c & 1) * STAGE_B;
        #pragma unroll
        for (int ks = 0; ks < 2; ks++) {
            const uint32_t colb = (uint32_t)(ks * 16 + ((lane >> 4) * 8)) * 2;
            uint32_t ah[4][4], al[4][4], bh[2][4], bl[2][4];
            #pragma unroll
            for (int mt = 0; mt < 4; mt++) {
                const uint32_t r = wm * 64 + mt * 16 + (lane & 15);
                ldm_x4(ah[mt], sb + 0 * PLANE_B + r * 80 + colb);
                ldm_x4(al[mt], sb + 1 * PLANE_B + r * 80 + colb);
            }
            #pragma unroll
            for (int nt2 = 0; nt2 < 2; nt2++) {
                const uint32_t r = wn * 32 + nt2 * 16 + (lane & 15);
                ldm_x4(bh[nt2], sb + 2 * PLANE_B + r * 80 + colb);
                ldm_x4(bl[nt2], sb + 3 * PLANE_B + r * 80 + colb);
            }
            #pragma unroll
            for (int mt = 0; mt < 4; mt++)
                #pragma unroll
                for (int nt = 0; nt < 4; nt++) {
                    uint32_t bhf[2] = { bh[nt >> 1][nt & 1], bh[nt >> 1][(nt & 1) + 2] };
                    uint32_t blf[2] = { bl[nt >> 1][nt & 1], bl[nt >> 1][(nt & 1) + 2] };
                    mma_bf16(acc[mt][nt], ah[mt], bhf);
                    mma_bf16(acc[mt][nt], ah[mt], blf);
                    mma_bf16(acc[mt][nt], al[mt], bhf);
                }
        }
        __syncthreads();
    }

    #pragma unroll
    for (int mt = 0; mt < 4; mt++) {
        const int r0 = m0 + wm * 64 + mt * 16 + (lane >> 2);
        #pragma unroll
        for (int nt = 0; nt < 4; nt++) {
            const int cl = wn * 32 + nt * 8 + 2 * (lane & 3);
            const int cg = n0 + cl;
            float2 v0, v1;
            v0.x = (acc[mt][nt][0] + biasS[cl + 0]) * a.scale;
            v0.y = (acc[mt][nt][1] + biasS[cl + 1]) * a.scale;
            v1.x = (acc[mt][nt][2] + biasS[cl + 0]) * a.scale;
            v1.y = (acc[mt][nt][3] + biasS[cl + 1]) * a.scale;
            if (a.C) {
                *(float2*)&a.C[(size_t)r0 * D_MODEL + cg]       = v0;
                *(float2*)&a.C[(size_t)(r0 + 8) * D_MODEL + cg] = v1;
            }
            if (a.Ch) {
                __nv_bfloat16 h0,l0,h1,l1;
                split2(v0.x,h0,l0); split2(v0.y,h1,l1);
                *(__nv_bfloat162*)&a.Ch[(size_t)r0 * D_MODEL + cg] = __nv_bfloat162{h0,h1};
                *(__nv_bfloat162*)&a.Cl[(size_t)r0 * D_MODEL + cg] = __nv_bfloat162{l0,l1};
                split2(v1.x,h0,l0); split2(v1.y,h1,l1);
                *(__nv_bfloat162*)&a.Ch[(size_t)(r0 + 8) * D_MODEL + cg] = __nv_bfloat162{h0,h1};
                *(__nv_bfloat162*)&a.Cl[(size_t)(r0 + 8) * D_MODEL + cg] = __nv_bfloat162{l0,l1};
            }
        }
    }
}

// ============================ mma.sync qrel ==================================
#define QPITCH 72
#define QPLANE_B (128 * QPITCH * 2)    // 18432 bytes

__global__ __launch_bounds__(256) void tc_qrel_kernel(const __nv_bfloat16* __restrict__ Qh,
                                                      const __nv_bfloat16* __restrict__ Ql,
                                                      const __nv_bfloat16* __restrict__ Th,
                                                      const __nv_bfloat16* __restrict__ Tl,
                                                      float* __restrict__ R)
{
    extern __shared__ char dsm[];
    const int tid = threadIdx.x, lane = tid & 31, w = tid >> 5;
    const int wm = w >> 2, wn = w & 3;
    const int tt = blockIdx.x, i0 = blockIdx.y * 128, h = blockIdx.z;
    const int t0 = i0 + tt * 128;
    const uint32_t sbase = smem_u32(dsm);

    #pragma unroll
    for (int p = 0; p < 4; p++) {
        #pragma unroll
        for (int v = 0; v < 4; v++) {
            const int idx = tid + v * 256;
            const int row = idx >> 3, c16 = idx & 7;
            const __nv_bfloat16* src;
            if (p == 0)      src = Qh + (size_t)(i0 + row) * D_MODEL + h * HEAD_DIM + c16 * 8;
            else if (p == 1) src = Ql + (size_t)(i0 + row) * D_MODEL + h * HEAD_DIM + c16 * 8;
            else if (p == 2) src = Th + (size_t)(t0 + row) * HEAD_DIM + c16 * 8;
            else             src = Tl + (size_t)(t0 + row) * HEAD_DIM + c16 * 8;
            CP_ASYNC16(sbase + p * QPLANE_B + row * 144 + c16 * 16, src);
        }
    }
    CP_COMMIT(); CP_WAIT(0);
    __syncthreads();

    float acc[4][4][4];
    #pragma unroll
    for (int i = 0; i < 4; i++)
        #pragma unroll
        for (int j = 0; j < 4; j++)
            #pragma unroll
            for (int q = 0; q < 4; q++) acc[i][j][q] = 0.f;

    #pragma unroll
    for (int ks = 0; ks < 4; ks++) {
        const uint32_t colb = (uint32_t)(ks * 16 + ((lane >> 4) * 8)) * 2;
        uint32_t ah[4][4], al[4][4], bh[2][4], bl[2][4];
        #pragma unroll
        for (int mt = 0; mt < 4; mt++) {
            const uint32_t r = wm * 64 + mt * 16 + (lane & 15);
            ldm_x4(ah[mt], sbase + 0 * QPLANE_B + r * 144 + colb);
            ldm_x4(al[mt], sbase + 1 * QPLANE_B + r * 144 + colb);
        }
        #pragma unroll
        for (int nt2 = 0; nt2 < 2; nt2++) {
            const uint32_t r = wn * 32 + nt2 * 16 + (lane & 15);
            ldm_x4(bh[nt2], sbase + 2 * QPLANE_B + r * 144 + colb);
            ldm_x4(bl[nt2], sbase + 3 * QPLANE_B + r * 144 + colb);
        }
        #pragma unroll
        for (int mt = 0; mt < 4; mt++)
            #pragma unroll
            for (int nt = 0; nt < 4; nt++) {
                uint32_t bhf[2] = { bh[nt >> 1][nt & 1], bh[nt >> 1][(nt & 1) + 2] };
                uint32_t blf[2] = { bl[nt >> 1][nt & 1], bl[nt >> 1][(nt & 1) + 2] };
                mma_bf16(acc[mt][nt], ah[mt], bhf);
                mma_bf16(acc[mt][nt], ah[mt], blf);
                mma_bf16(acc[mt][nt], al[mt], bhf);
            }
    }

    #pragma unroll
    for (int mt = 0; mt < 4; mt++) {
        const int rloc = wm * 64 + mt * 16 + (lane >> 2);
        float* Rrow0 = R + (((size_t)(h * S_LEN + i0 + rloc))     << 11);
        float* Rrow1 = R + (((size_t)(h * S_LEN + i0 + rloc + 8)) << 11);
        #pragma unroll
        for (int nt = 0; nt < 4; nt++) {
            const int cloc = wn * 32 + nt * 8 + 2 * (lane & 3);
            const int k0 = tt * 128 + cloc - rloc;
            if ((unsigned)(k0)     < (unsigned)KPACK) Rrow0[k0]     = acc[mt][nt][0];
            if ((unsigned)(k0 + 1) < (unsigned)KPACK) Rrow0[k0 + 1] = acc[mt][nt][1];
            if ((unsigned)(k0 - 8) < (unsigned)KPACK) Rrow1[k0 - 8] = acc[mt][nt][2];
            if ((unsigned)(k0 - 7) < (unsigned)KPACK) Rrow1[k0 - 7] = acc[mt][nt][3];
        }
    }
}

// ============================ mma.sync flash attention =======================
// CTA = 128 q-rows x 1 head; 8 warps x 16 rows. j-tiles of 64, double-buffered
// cp.async of Kh/Kl/Vh/Vl (144B pitch, 64 rows x 128B). S init from packed QR
// gather; QK and PV via split-bf16 mma; online softmax in fragments.
#define APITCH_B 144
#define APLANE_B (64 * APITCH_B)       // 9216
#define ASTAGE_B (4 * APLANE_B)        // 36864

__global__ __launch_bounds__(256) void attn_mma_kernel(
    const __nv_bfloat16* __restrict__ Qh, const __nv_bfloat16* __restrict__ Ql,
    const __nv_bfloat16* __restrict__ Kh, const __nv_bfloat16* __restrict__ Kl,
    const __nv_bfloat16* __restrict__ Vh, const __nv_bfloat16* __restrict__ Vl,
    const float* __restrict__ QR,
    __nv_bfloat16* __restrict__ AOh, __nv_bfloat16* __restrict__ AOl)
{
    extern __shared__ char dsm[];
    const int tid = threadIdx.x, lane = tid & 31, w = tid >> 5;
    const int i0 = blockIdx.x * 128, h = blockIdx.y;
    const uint32_t sb = smem_u32(dsm);

    // ---- stage Q (128 rows x 64 bf16 = 8x16B per row, 2 planes) ----
    #pragma unroll
    for (int p = 0; p < 2; p++) {
        const __nv_bfloat16* g = p ? Ql : Qh;
        #pragma unroll
        for (int v = 0; v < 4; v++) {
            const int idx = tid + v * 256;
            const int row = idx >> 3, c16 = idx & 7;
            CP_ASYNC16(sb + p * 18432 + row * APITCH_B + c16 * 16,
                       g + (size_t)(i0 + row) * D_MODEL + h * HEAD_DIM + c16 * 8);
        }
    }
    CP_COMMIT(); CP_WAIT(0);
    __syncthreads();

    uint32_t qfh[4][4], qfl[4][4];
    {
        const uint32_t rbyte = (uint32_t)(w * 16 + (lane & 15)) * APITCH_B;
        #pragma unroll
        for (int kf = 0; kf < 4; kf++) {
            const uint32_t colb = (uint32_t)(kf * 16 + ((lane >> 4) * 8)) * 2;
            ldm_x4(qfh[kf], sb + 0 * 18432 + rbyte + colb);
            ldm_x4(qfl[kf], sb + 1 * 18432 + rbyte + colb);
        }
    }
    __syncthreads();

    float o[8][4];
    #pragma unroll
    for (int i = 0; i < 8; i++)
        #pragma unroll
        for (int q = 0; q < 4; q++) o[i][q] = 0.f;
    float mrow0 = -1e30f, mrow1 = -1e30f, lrow0 = 0.f, lrow1 = 0.f;
    const int r0 = w * 16 + (lane >> 2);        // local row (second row = +8)
    const float* qrow0 = QR + (((size_t)(h * S_LEN + i0 + r0)) << 11);
    const float* qrow1 = qrow0 + ((size_t)8 << 11);

    // prefetch tile 0: 64 rows x 8x16B per plane
    {
        const __nv_bfloat16* gs[4] = { Kh, Kl, Vh, Vl };
        #pragma unroll
        for (int p = 0; p < 4; p++)
            #pragma unroll
            for (int v = 0; v < 2; v++) {
                const int idx = tid + v * 256;
                const int row = idx >> 3, c16 = idx & 7;
                CP_ASYNC16(sb + p * APLANE_B + row * APITCH_B + c16 * 16,
                           gs[p] + (size_t)row * D_MODEL + h * HEAD_DIM + c16 * 8);
            }
        CP_COMMIT();
    }

    for (int jt = 0; jt < 32; jt++) {
        if (jt + 1 < 32) {
            const int jn = (jt + 1) * 64;
            const uint32_t st2 = sb + ((jt + 1) & 1) * ASTAGE_B;
            const __nv_bfloat16* gs[4] = { Kh, Kl, Vh, Vl };
            #pragma unroll
            for (int p = 0; p < 4; p++)
                #pragma unroll
                for (int v = 0; v < 2; v++) {
                    const int idx = tid + v * 256;
                    const int row = idx >> 3, c16 = idx & 7;
                    CP_ASYNC16(st2 + p * APLANE_B + row * APITCH_B + c16 * 16,
                               gs[p] + (size_t)(jn + row) * D_MODEL + h * HEAD_DIM + c16 * 8);
                }
            CP_COMMIT(); CP_WAIT(1);
        } else {
            CP_WAIT(0);
        }
        __syncthreads();

        const uint32_t st = sb + (jt & 1) * ASTAGE_B;
        const int j0 = jt * 64;

        // --- S init from packed rel: rel(i,j) = QR[h][i][2047 - j] ---
        float c[8][4];
        #pragma unroll
        for (int nf = 0; nf < 8; nf++) {
            const int jc = j0 + nf * 8 + (lane & 3) * 2;
            float2 g0 = *(const float2*)&qrow0[2046 - jc];
            float2 g1 = *(const float2*)&qrow1[2046 - jc];
            c[nf][0] = g0.y; c[nf][1] = g0.x;
            c[nf][2] = g1.y; c[nf][3] = g1.x;
        }

        // --- S += Q . K^T (split bf16) ---
        #pragma unroll
        for (int jf = 0; jf < 4; jf++) {
            const uint32_t rby = (uint32_t)(jf * 16 + (lane & 15)) * APITCH_B;
            #pragma unroll
            for (int kf = 0; kf < 4; kf++) {
                const uint32_t cb = (uint32_t)(kf * 16 + ((lane >> 4) * 8)) * 2;
                uint32_t kh4[4], kl4[4];
                ldm_x4(kh4, st + 0 * APLANE_B + rby + cb);
                ldm_x4(kl4, st + 1 * APLANE_B + rby + cb);
                uint32_t b0h[2] = { kh4[0], kh4[2] }, b1h[2] = { kh4[1], kh4[3] };
                uint32_t b0l[2] = { kl4[0], kl4[2] }, b1l[2] = { kl4[1], kl4[3] };
                mma_bf16(c[jf*2+0], qfh[kf], b0h);
                mma_bf16(c[jf*2+0], qfh[kf], b0l);
                mma_bf16(c[jf*2+0], qfl[kf], b0h);
                mma_bf16(c[jf*2+1], qfh[kf], b1h);
                mma_bf16(c[jf*2+1], qfh[kf], b1l);
                mma_bf16(c[jf*2+1], qfl[kf], b1h);
            }
        }

        // --- online softmax in fragments ---
        float mx0 = -1e30f, mx1 = -1e30f;
        #pragma unroll
        for (int nf = 0; nf < 8; nf++) {
            mx0 = fmaxf(mx0, fmaxf(c[nf][0], c[nf][1]));
            mx1 = fmaxf(mx1, fmaxf(c[nf][2], c[nf][3]));
        }
        mx0 = fmaxf(mx0, __shfl_xor_sync(0xffffffffu, mx0, 1));
        mx0 = fmaxf(mx0, __shfl_xor_sync(0xffffffffu, mx0, 2));
        mx1 = fmaxf(mx1, __shfl_xor_sync(0xffffffffu, mx1, 1));
        mx1 = fmaxf(mx1, __shfl_xor_sync(0xffffffffu, mx1, 2));
        const float mn0 = fmaxf(mrow0, mx0), mn1 = fmaxf(mrow1, mx1);
        const float cor0 = __expf(mrow0 - mn0), cor1 = __expf(mrow1 - mn1);
        mrow0 = mn0; mrow1 = mn1;

        uint32_t P0h[8], P1h[8], P0l[8], P1l[8];
        float ls0 = 0.f, ls1 = 0.f;
        #pragma unroll
        for (int nf = 0; nf < 8; nf++) {
            float p0 = __expf(c[nf][0] - mn0), p1 = __expf(c[nf][1] - mn0);
            float p2 = __expf(c[nf][2] - mn1), p3 = __expf(c[nf][3] - mn1);
            ls0 += p0 + p1; ls1 += p2 + p3;
            __nv_bfloat16 h0,l0,h1,l1;
            split2(p0,h0,l0); split2(p1,h1,l1);
            P0h[nf] = pack2(h0,h1); P0l[nf] = pack2(l0,l1);
            split2(p2,h0,l0); split2(p3,h1,l1);
            P1h[nf] = pack2(h0,h1); P1l[nf] = pack2(l0,l1);
        }
        ls0 += __shfl_xor_sync(0xffffffffu, ls0, 1);
        ls0 += __shfl_xor_sync(0xffffffffu, ls0, 2);
        ls1 += __shfl_xor_sync(0xffffffffu, ls1, 1);
        ls1 += __shfl_xor_sync(0xffffffffu, ls1, 2);
        lrow0 = lrow0 * cor0 + ls0;
        lrow1 = lrow1 * cor1 + ls1;
        #pragma unroll
        for (int df = 0; df < 8; df++) {
            o[df][0] *= cor0; o[df][1] *= cor0;
            o[df][2] *= cor1; o[df][3] *= cor1;
        }

        // --- O += P . V (split bf16); V fragments via ldmatrix.trans ---
        #pragma unroll
        for (int kfj = 0; kfj < 4; kfj++) {
            uint32_t ah[4] = { P0h[2*kfj], P1h[2*kfj], P0h[2*kfj+1], P1h[2*kfj+1] };
            uint32_t al[4] = { P0l[2*kfj], P1l[2*kfj], P0l[2*kfj+1], P1l[2*kfj+1] };
            const uint32_t rby = (uint32_t)(kfj * 16 + (lane & 15)) * APITCH_B;
            #pragma unroll
            for (int dc = 0; dc < 4; dc++) {
                const uint32_t cb = (uint32_t)(dc * 16 + ((lane >> 4) * 8)) * 2;
                uint32_t vh4[4], vl4[4];
                ldm_x4_t(vh4, st + 2 * APLANE_B + rby + cb);
                ldm_x4_t(vl4, st + 3 * APLANE_B + rby + cb);
                uint32_t bh0[2] = { vh4[0], vh4[1] }, bh1[2] = { vh4[2], vh4[3] };
                uint32_t bl0[2] = { vl4[0], vl4[1] }, bl1[2] = { vl4[2], vl4[3] };
                mma_bf16(o[dc*2+0], ah, bh0);
                mma_bf16(o[dc*2+0], ah, bl0);
                mma_bf16(o[dc*2+0], al, bh0);
                mma_bf16(o[dc*2+1], ah, bh1);
                mma_bf16(o[dc*2+1], ah, bl1);
                mma_bf16(o[dc*2+1], al, bh1);
            }
        }
        __syncthreads();
    }

    // ---- finalize: O /= l, split-store AO bf16 planes ----
    const float inv0 = 1.f / lrow0, inv1 = 1.f / lrow1;
    const int gr0 = i0 + r0, gr1 = gr0 + 8;
    #pragma unroll
    for (int df = 0; df < 8; df++) {
        const int d = h * HEAD_DIM + df * 8 + (lane & 3) * 2;
        __nv_bfloat16 h0,l0,h1,l1;
        split2(o[df][0] * inv0, h0, l0); split2(o[df][1] * inv0, h1, l1);
        *(__nv_bfloat162*)&AOh[(size_t)gr0 * D_MODEL + d] = __nv_bfloat162{h0,h1};
        *(__nv_bfloat162*)&AOl[(size_t)gr0 * D_MODEL + d] = __nv_bfloat162{l0,l1};
        split2(o[df][2] * inv1, h0, l0); split2(o[df][3] * inv1, h1, l1);
        *(__nv_bfloat162*)&AOh[(size_t)gr1 * D_MODEL + d] = __nv_bfloat162{h0,h1};
        *(__nv_bfloat162*)&AOl[(size_t)gr1 * D_MODEL + d] = __nv_bfloat162{l0,l1};
    }
}

// ============================ Launcher =======================================
extern "C" void kernel_launch(void* const* d_in, const int* in_sizes, int n_in,
                              void* d_out, int out_size)
{
    const float* x   = (const float*)d_in[0];
    const float* Wq  = (const float*)d_in[1];
    const float* bq  = (const float*)d_in[2];
    const float* Wk  = (const float*)d_in[3];
    const float* bk  = (const float*)d_in[4];
    const float* Wv  = (const float*)d_in[5];
    const float* bv  = (const float*)d_in[6];
    const float* Wo  = (const float*)d_in[7];
    const float* bo  = (const float*)d_in[8];
    const float* rel = (const float*)d_in[9];
    float* out = (float*)d_out;

    float* pQR;
    __nv_bfloat16 *pxh, *pxl, *pQh, *pQl, *pKh, *pKl, *pVh, *pVl;
    __nv_bfloat16 *pAOh, *pAOl, *pWth, *pWtl, *pTh, *pTl;
    cudaGetSymbolAddress((void**)&pQR,  g_QR);
    cudaGetSymbolAddress((void**)&pxh,  g_xh);
    cudaGetSymbolAddress((void**)&pxl,  g_xl);
    cudaGetSymbolAddress((void**)&pQh,  g_Qh);
    cudaGetSymbolAddress((void**)&pQl,  g_Ql);
    cudaGetSymbolAddress((void**)&pKh,  g_Kh);
    cudaGetSymbolAddress((void**)&pKl,  g_Kl);
    cudaGetSymbolAddress((void**)&pVh,  g_Vh);
    cudaGetSymbolAddress((void**)&pVl,  g_Vl);
    cudaGetSymbolAddress((void**)&pAOh, g_AOh);
    cudaGetSymbolAddress((void**)&pAOl, g_AOl);
    cudaGetSymbolAddress((void**)&pWth, g_Wth);
    cudaGetSymbolAddress((void**)&pWtl, g_Wtl);
    cudaGetSymbolAddress((void**)&pTh,  g_Th);
    cudaGetSymbolAddress((void**)&pTl,  g_Tl);

    const int gemm_smem = 2 * STAGE_B;       // 81,920
    const int qrel_smem = 4 * QPLANE_B;      // 73,728
    const int attn_smem = 2 * ASTAGE_B;      // 73,728
    cudaFuncSetAttribute(tc_gemm_kernel,  cudaFuncAttributeMaxDynamicSharedMemorySize, gemm_smem);
    cudaFuncSetAttribute(tc_qrel_kernel,  cudaFuncAttributeMaxDynamicSharedMemorySize, qrel_smem);
    cudaFuncSetAttribute(attn_mma_kernel, cudaFuncAttributeMaxDynamicSharedMemorySize, attn_smem);

    // 0) splits: x, W^T (x4), rel_table
    split_plane_kernel<<<(S_LEN * D_MODEL / 4 + 255) / 256, 256>>>(x, pxh, pxl, S_LEN * D_MODEL / 4);
    WSrc ws; ws.w[0] = Wq; ws.w[1] = Wk; ws.w[2] = Wv; ws.w[3] = Wo;
    wsplit_kernel<<<dim3(32, 32, 4), 256>>>(ws, pWth, pWtl);
    split_T_kernel<<<(TPAD * HEAD_DIM + 255) / 256, 256>>>(rel, pTh, pTl);

    const size_t MM = (size_t)D_MODEL * D_MODEL;

    // 1) QKV projections -> bf16 planes only (K folded with 1/8)
    TCArgs aq{ pxh, pxl, pWth + 0*MM, pWtl + 0*MM, bq, nullptr, pQh, pQl, 1.0f };
    TCArgs ak{ pxh, pxl, pWth + 1*MM, pWtl + 1*MM, bk, nullptr, pKh, pKl, 0.125f };
    TCArgs av{ pxh, pxl, pWth + 2*MM, pWtl + 2*MM, bv, nullptr, pVh, pVl, 1.0f };
    tc_gemm_kernel<<<dim3(8, 16, 3), 256, gemm_smem>>>(aq, ak, av);

    // 2) packed banded qrel
    tc_qrel_kernel<<<dim3(17, 16, 16), 256, qrel_smem>>>(pQh, pQl, pTh, pTl, pQR);

    // 3) mma flash attention -> AO bf16 planes
    attn_mma_kernel<<<dim3(16, 16), 256, attn_smem>>>(pQh, pQl, pKh, pKl, pVh, pVl,
                                                      pQR, pAOh, pAOl);

    // 4) output projection -> fp32 out
    TCArgs ao{ pAOh, pAOl, pWth + 3*MM, pWtl + 3*MM, bo, out, nullptr, nullptr, 1.0f };
    tc_gemm_kernel<<<dim3(8, 16, 1), 256, gemm_smem>>>(ao, ao, ao);
}

// round 9
// speedup vs baseline: 2.4373x; 1.0207x over previous
#include <cuda_runtime.h>
#include <cuda_bf16.h>
#include <cstdint>

#define S_LEN 2048
#define D_MODEL 1024
#define N_HEADS 16
#define HEAD_DIM 64
#define TBL 4095        // 2*S - 1
#define KPACK 2048      // packed rel length per row
#define TPAD 4096       // padded rel_table rows (rows >= TBL zeroed)

// ---------------- scratch (__device__ arrays, no allocs) ---------------------
__device__ float g_QR[(size_t)N_HEADS * S_LEN * KPACK];  // 256 MiB packed rel

__device__ __nv_bfloat16 g_xh [S_LEN * D_MODEL], g_xl [S_LEN * D_MODEL];
__device__ __nv_bfloat16 g_Qh [S_LEN * D_MODEL], g_Ql [S_LEN * D_MODEL];
__device__ __nv_bfloat16 g_Kh [S_LEN * D_MODEL], g_Kl [S_LEN * D_MODEL];
__device__ __nv_bfloat16 g_Vh [S_LEN * D_MODEL], g_Vl [S_LEN * D_MODEL];
__device__ __nv_bfloat16 g_AOh[S_LEN * D_MODEL], g_AOl[S_LEN * D_MODEL];
__device__ __nv_bfloat16 g_Wth[4u * D_MODEL * D_MODEL], g_Wtl[4u * D_MODEL * D_MODEL];
__device__ __nv_bfloat16 g_Th [TPAD * HEAD_DIM], g_Tl [TPAD * HEAD_DIM];

// ============================ helpers ========================================
__device__ __forceinline__ uint32_t smem_u32(const void* p) {
    uint32_t a;
    asm("{ .reg .u64 t; cvta.to.shared.u64 t, %1; cvt.u32.u64 %0, t; }" : "=r"(a) : "l"(p));
    return a;
}
__device__ __forceinline__ void ldm_x4(uint32_t* r, uint32_t addr) {
    asm volatile("ldmatrix.sync.aligned.m8n8.x4.shared.b16 {%0,%1,%2,%3}, [%4];"
        : "=r"(r[0]), "=r"(r[1]), "=r"(r[2]), "=r"(r[3]) : "r"(addr));
}
__device__ __forceinline__ void ldm_x4_t(uint32_t* r, uint32_t addr) {
    asm volatile("ldmatrix.sync.aligned.m8n8.x4.trans.shared.b16 {%0,%1,%2,%3}, [%4];"
        : "=r"(r[0]), "=r"(r[1]), "=r"(r[2]), "=r"(r[3]) : "r"(addr));
}
__device__ __forceinline__ void mma_bf16(float* c, const uint32_t* a, const uint32_t* b) {
    asm volatile("mma.sync.aligned.m16n8k16.row.col.f32.bf16.bf16.f32 "
        "{%0,%1,%2,%3}, {%4,%5,%6,%7}, {%8,%9}, {%0,%1,%2,%3};"
        : "+f"(c[0]), "+f"(c[1]), "+f"(c[2]), "+f"(c[3])
        : "r"(a[0]), "r"(a[1]), "r"(a[2]), "r"(a[3]), "r"(b[0]), "r"(b[1]));
}
#define CP_ASYNC16(dst, src) \
    asm volatile("cp.async.cg.shared.global [%0], [%1], 16;" :: "r"(dst), "l"(src))
#define CP_COMMIT() asm volatile("cp.async.commit_group;")
#define CP_WAIT(N)  asm volatile("cp.async.wait_group %0;" :: "n"(N) : "memory")

__device__ __forceinline__ void split2(float v, __nv_bfloat16& h, __nv_bfloat16& l) {
    h = __float2bfloat16(v);
    l = __float2bfloat16(v - __bfloat162float(h));
}
__device__ __forceinline__ uint32_t pack2(__nv_bfloat16 lo, __nv_bfloat16 hi) {
    __nv_bfloat162 t{lo, hi};
    return *(uint32_t*)&t;
}

// ============================ split kernels ==================================
__global__ void split_plane_kernel(const float* __restrict__ src,
                                   __nv_bfloat16* __restrict__ ph,
                                   __nv_bfloat16* __restrict__ pl, int n4)
{
    int i = blockIdx.x * blockDim.x + threadIdx.x;
    if (i >= n4) return;
    float4 v = *(const float4*)(src + (size_t)i * 4);
    __nv_bfloat16 h, l;
    split2(v.x, h, l); ph[i*4+0] = h; pl[i*4+0] = l;
    split2(v.y, h, l); ph[i*4+1] = h; pl[i*4+1] = l;
    split2(v.z, h, l); ph[i*4+2] = h; pl[i*4+2] = l;
    split2(v.w, h, l); ph[i*4+3] = h; pl[i*4+3] = l;
}

__global__ void split_T_kernel(const float* __restrict__ rel,
                               __nv_bfloat16* __restrict__ th,
                               __nv_bfloat16* __restrict__ tl)
{
    int i = blockIdx.x * blockDim.x + threadIdx.x;
    if (i >= TPAD * HEAD_DIM) return;
    int t = i >> 6;
    float v = (t < TBL) ? rel[i] : 0.f;
    __nv_bfloat16 h, l; split2(v, h, l);
    th[i] = h; tl[i] = l;
}

struct WSrc { const float* w[4]; };
__global__ __launch_bounds__(256) void wsplit_kernel(WSrc ws,
                                                     __nv_bfloat16* __restrict__ dh,
                                                     __nv_bfloat16* __restrict__ dl)
{
    __shared__ float t[32][33];
    const float* W = ws.w[blockIdx.z];
    __nv_bfloat16* oh = dh + (size_t)blockIdx.z * D_MODEL * D_MODEL;
    __nv_bfloat16* ol = dl + (size_t)blockIdx.z * D_MODEL * D_MODEL;
    const int n0 = blockIdx.x * 32, k0 = blockIdx.y * 32;
    const int tx = threadIdx.x & 31, ty = threadIdx.x >> 5;
    #pragma unroll
    for (int rr = 0; rr < 32; rr += 8)
        t[ty + rr][tx] = W[(size_t)(k0 + ty + rr) * D_MODEL + n0 + tx];
    __syncthreads();
    #pragma unroll
    for (int rr = 0; rr < 32; rr += 8) {
        float v = t[tx][ty + rr];
        __nv_bfloat16 h, l; split2(v, h, l);
        oh[(size_t)(n0 + ty + rr) * D_MODEL + k0 + tx] = h;
        ol[(size_t)(n0 + ty + rr) * D_MODEL + k0 + tx] = l;
    }
}

// ============================ mma.sync projection GEMM =======================
// Single-sync double buffer: per iter  wait(0) -> barrier -> issue next -> compute.
#define GPITCH 40
#define PLANE_B (128 * GPITCH * 2)     // 10240 bytes per plane
#define STAGE_B (4 * PLANE_B)          // 40960 bytes per stage

struct TCArgs {
    const __nv_bfloat16 *Ah, *Al, *Bh, *Bl;
    const float* bias; float* C;       // C may be null (bf16-only output)
    __nv_bfloat16 *Ch, *Cl;            // may be null (fp32-only output)
    float scale;
};

__global__ __launch_bounds__(256) void tc_gemm_kernel(TCArgs a0, TCArgs a1, TCArgs a2)
{
    TCArgs a = (blockIdx.z == 0) ? a0 : ((blockIdx.z == 1) ? a1 : a2);
    extern __shared__ char dsm[];
    __shared__ float biasS[128];

    const int tid = threadIdx.x, lane = tid & 31, w = tid >> 5;
    const int wm = w >> 2, wn = w & 3;
    const int m0 = blockIdx.y * 128, n0 = blockIdx.x * 128;
    const uint32_t sbase = smem_u32(dsm);

    if (tid < 128) biasS[tid] = a.bias[n0 + tid];

    const __nv_bfloat16* gsrc[4] = { a.Ah, a.Al, a.Bh, a.Bl };
    const int rb[4] = { m0, m0, n0, n0 };

    // prologue: chunk 0 -> stage 0
    #pragma unroll
    for (int p = 0; p < 4; p++) {
        const __nv_bfloat16* g = gsrc[p];
        #pragma unroll
        for (int v = 0; v < 2; v++) {
            const int idx = tid + v * 256;
            const int row = idx >> 2, c16 = idx & 3;
            CP_ASYNC16(sbase + p * PLANE_B + row * 80 + c16 * 16,
                       g + (size_t)(rb[p] + row) * D_MODEL + c16 * 8);
        }
    }
    CP_COMMIT();

    float acc[4][4][4];
    #pragma unroll
    for (int i = 0; i < 4; i++)
        #pragma unroll
        for (int j = 0; j < 4; j++)
            #pragma unroll
            for (int q = 0; q < 4; q++) acc[i][j][q] = 0.f;

    for (int c = 0; c < 32; c++) {
        CP_WAIT(0);            // chunk c resident
        __syncthreads();       // all warps done with chunk c-1; chunk c visible
        if (c + 1 < 32) {      // issue chunk c+1 into the opposite stage
            const int k0 = (c + 1) * 32;
            const uint32_t st = sbase + ((c + 1) & 1) * STAGE_B;
            #pragma unroll
            for (int p = 0; p < 4; p++) {
                const __nv_bfloat16* g = gsrc[p];
                #pragma unroll
                for (int v = 0; v < 2; v++) {
                    const int idx = tid + v * 256;
                    const int row = idx >> 2, c16 = idx & 3;
                    CP_ASYNC16(st + p * PLANE_B + row * 80 + c16 * 16,
                               g + (size_t)(rb[p] + row) * D_MODEL + k0 + c16 * 8);
                }
            }
            CP_COMMIT();
        }

        const uint32_t sb = sbase + (c & 1) * STAGE_B;
        #pragma unroll
        for (int ks = 0; ks < 2; ks++) {
            const uint32_t colb = (uint32_t)(ks * 16 + ((lane >> 4) * 8)) * 2;
            uint32_t ah[4][4], al[4][4], bh[2][4], bl[2][4];
            #pragma unroll
            for (int mt = 0; mt < 4; mt++) {
                const uint32_t r = wm * 64 + mt * 16 + (lane & 15);
                ldm_x4(ah[mt], sb + 0 * PLANE_B + r * 80 + colb);
                ldm_x4(al[mt], sb + 1 * PLANE_B + r * 80 + colb);
            }
            #pragma unroll
            for (int nt2 = 0; nt2 < 2; nt2++) {
                const uint32_t r = wn * 32 + nt2 * 16 + (lane & 15);
                ldm_x4(bh[nt2], sb + 2 * PLANE_B + r * 80 + colb);
                ldm_x4(bl[nt2], sb + 3 * PLANE_B + r * 80 + colb);
            }
            #pragma unroll
            for (int mt = 0; mt < 4; mt++)
                #pragma unroll
                for (int nt = 0; nt < 4; nt++) {
                    uint32_t bhf[2] = { bh[nt >> 1][nt & 1], bh[nt >> 1][(nt & 1) + 2] };
                    uint32_t blf[2] = { bl[nt >> 1][nt & 1], bl[nt >> 1][(nt & 1) + 2] };
                    mma_bf16(acc[mt][nt], ah[mt], bhf);
                    mma_bf16(acc[mt][nt], ah[mt], blf);
                    mma_bf16(acc[mt][nt], al[mt], bhf);
                }
        }
    }

    #pragma unroll
    for (int mt = 0; mt < 4; mt++) {
        const int r0 = m0 + wm * 64 + mt * 16 + (lane >> 2);
        #pragma unroll
        for (int nt = 0; nt < 4; nt++) {
            const int cl = wn * 32 + nt * 8 + 2 * (lane & 3);
            const int cg = n0 + cl;
            float2 v0, v1;
            v0.x = (acc[mt][nt][0] + biasS[cl + 0]) * a.scale;
            v0.y = (acc[mt][nt][1] + biasS[cl + 1]) * a.scale;
            v1.x = (acc[mt][nt][2] + biasS[cl + 0]) * a.scale;
            v1.y = (acc[mt][nt][3] + biasS[cl + 1]) * a.scale;
            if (a.C) {
                *(float2*)&a.C[(size_t)r0 * D_MODEL + cg]       = v0;
                *(float2*)&a.C[(size_t)(r0 + 8) * D_MODEL + cg] = v1;
            }
            if (a.Ch) {
                __nv_bfloat16 h0,l0,h1,l1;
                split2(v0.x,h0,l0); split2(v0.y,h1,l1);
                *(__nv_bfloat162*)&a.Ch[(size_t)r0 * D_MODEL + cg] = __nv_bfloat162{h0,h1};
                *(__nv_bfloat162*)&a.Cl[(size_t)r0 * D_MODEL + cg] = __nv_bfloat162{l0,l1};
                split2(v1.x,h0,l0); split2(v1.y,h1,l1);
                *(__nv_bfloat162*)&a.Ch[(size_t)(r0 + 8) * D_MODEL + cg] = __nv_bfloat162{h0,h1};
                *(__nv_bfloat162*)&a.Cl[(size_t)(r0 + 8) * D_MODEL + cg] = __nv_bfloat162{l0,l1};
            }
        }
    }
}

// ============================ mma.sync qrel ==================================
#define QPITCH 72
#define QPLANE_B (128 * QPITCH * 2)    // 18432 bytes

__global__ __launch_bounds__(256) void tc_qrel_kernel(const __nv_bfloat16* __restrict__ Qh,
                                                      const __nv_bfloat16* __restrict__ Ql,
                                                      const __nv_bfloat16* __restrict__ Th,
                                                      const __nv_bfloat16* __restrict__ Tl,
                                                      float* __restrict__ R)
{
    extern __shared__ char dsm[];
    const int tid = threadIdx.x, lane = tid & 31, w = tid >> 5;
    const int wm = w >> 2, wn = w & 3;
    const int tt = blockIdx.x, i0 = blockIdx.y * 128, h = blockIdx.z;
    const int t0 = i0 + tt * 128;
    const uint32_t sbase = smem_u32(dsm);

    #pragma unroll
    for (int p = 0; p < 4; p++) {
        #pragma unroll
        for (int v = 0; v < 4; v++) {
            const int idx = tid + v * 256;
            const int row = idx >> 3, c16 = idx & 7;
            const __nv_bfloat16* src;
            if (p == 0)      src = Qh + (size_t)(i0 + row) * D_MODEL + h * HEAD_DIM + c16 * 8;
            else if (p == 1) src = Ql + (size_t)(i0 + row) * D_MODEL + h * HEAD_DIM + c16 * 8;
            else if (p == 2) src = Th + (size_t)(t0 + row) * HEAD_DIM + c16 * 8;
            else             src = Tl + (size_t)(t0 + row) * HEAD_DIM + c16 * 8;
            CP_ASYNC16(sbase + p * QPLANE_B + row * 144 + c16 * 16, src);
        }
    }
    CP_COMMIT(); CP_WAIT(0);
    __syncthreads();

    float acc[4][4][4];
    #pragma unroll
    for (int i = 0; i < 4; i++)
        #pragma unroll
        for (int j = 0; j < 4; j++)
            #pragma unroll
            for (int q = 0; q < 4; q++) acc[i][j][q] = 0.f;

    #pragma unroll
    for (int ks = 0; ks < 4; ks++) {
        const uint32_t colb = (uint32_t)(ks * 16 + ((lane >> 4) * 8)) * 2;
        uint32_t ah[4][4], al[4][4], bh[2][4], bl[2][4];
        #pragma unroll
        for (int mt = 0; mt < 4; mt++) {
            const uint32_t r = wm * 64 + mt * 16 + (lane & 15);
            ldm_x4(ah[mt], sbase + 0 * QPLANE_B + r * 144 + colb);
            ldm_x4(al[mt], sbase + 1 * QPLANE_B + r * 144 + colb);
        }
        #pragma unroll
        for (int nt2 = 0; nt2 < 2; nt2++) {
            const uint32_t r = wn * 32 + nt2 * 16 + (lane & 15);
            ldm_x4(bh[nt2], sbase + 2 * QPLANE_B + r * 144 + colb);
            ldm_x4(bl[nt2], sbase + 3 * QPLANE_B + r * 144 + colb);
        }
        #pragma unroll
        for (int mt = 0; mt < 4; mt++)
            #pragma unroll
            for (int nt = 0; nt < 4; nt++) {
                uint32_t bhf[2] = { bh[nt >> 1][nt & 1], bh[nt >> 1][(nt & 1) + 2] };
                uint32_t blf[2] = { bl[nt >> 1][nt & 1], bl[nt >> 1][(nt & 1) + 2] };
                mma_bf16(acc[mt][nt], ah[mt], bhf);
                mma_bf16(acc[mt][nt], ah[mt], blf);
                mma_bf16(acc[mt][nt], al[mt], bhf);
            }
    }

    #pragma unroll
    for (int mt = 0; mt < 4; mt++) {
        const int rloc = wm * 64 + mt * 16 + (lane >> 2);
        float* Rrow0 = R + (((size_t)(h * S_LEN + i0 + rloc))     << 11);
        float* Rrow1 = R + (((size_t)(h * S_LEN + i0 + rloc + 8)) << 11);
        #pragma unroll
        for (int nt = 0; nt < 4; nt++) {
            const int cloc = wn * 32 + nt * 8 + 2 * (lane & 3);
            const int k0 = tt * 128 + cloc - rloc;
            if ((unsigned)(k0)     < (unsigned)KPACK) Rrow0[k0]     = acc[mt][nt][0];
            if ((unsigned)(k0 + 1) < (unsigned)KPACK) Rrow0[k0 + 1] = acc[mt][nt][1];
            if ((unsigned)(k0 - 8) < (unsigned)KPACK) Rrow1[k0 - 8] = acc[mt][nt][2];
            if ((unsigned)(k0 - 7) < (unsigned)KPACK) Rrow1[k0 - 7] = acc[mt][nt][3];
        }
    }
}

// ============================ mma.sync flash attention =======================
// Single-sync double buffer on the j-loop (wait -> barrier -> issue -> compute).
#define APITCH_B 144
#define APLANE_B (64 * APITCH_B)       // 9216
#define ASTAGE_B (4 * APLANE_B)        // 36864

__global__ __launch_bounds__(256) void attn_mma_kernel(
    const __nv_bfloat16* __restrict__ Qh, const __nv_bfloat16* __restrict__ Ql,
    const __nv_bfloat16* __restrict__ Kh, const __nv_bfloat16* __restrict__ Kl,
    const __nv_bfloat16* __restrict__ Vh, const __nv_bfloat16* __restrict__ Vl,
    const float* __restrict__ QR,
    __nv_bfloat16* __restrict__ AOh, __nv_bfloat16* __restrict__ AOl)
{
    extern __shared__ char dsm[];
    const int tid = threadIdx.x, lane = tid & 31, w = tid >> 5;
    const int i0 = blockIdx.x * 128, h = blockIdx.y;
    const uint32_t sb = smem_u32(dsm);

    // ---- stage Q (128 rows x 64 bf16 = 8x16B per row, 2 planes) ----
    #pragma unroll
    for (int p = 0; p < 2; p++) {
        const __nv_bfloat16* g = p ? Ql : Qh;
        #pragma unroll
        for (int v = 0; v < 4; v++) {
            const int idx = tid + v * 256;
            const int row = idx >> 3, c16 = idx & 7;
            CP_ASYNC16(sb + p * 18432 + row * APITCH_B + c16 * 16,
                       g + (size_t)(i0 + row) * D_MODEL + h * HEAD_DIM + c16 * 8);
        }
    }
    CP_COMMIT(); CP_WAIT(0);
    __syncthreads();

    uint32_t qfh[4][4], qfl[4][4];
    {
        const uint32_t rbyte = (uint32_t)(w * 16 + (lane & 15)) * APITCH_B;
        #pragma unroll
        for (int kf = 0; kf < 4; kf++) {
            const uint32_t colb = (uint32_t)(kf * 16 + ((lane >> 4) * 8)) * 2;
            ldm_x4(qfh[kf], sb + 0 * 18432 + rbyte + colb);
            ldm_x4(qfl[kf], sb + 1 * 18432 + rbyte + colb);
        }
    }
    __syncthreads();

    float o[8][4];
    #pragma unroll
    for (int i = 0; i < 8; i++)
        #pragma unroll
        for (int q = 0; q < 4; q++) o[i][q] = 0.f;
    float mrow0 = -1e30f, mrow1 = -1e30f, lrow0 = 0.f, lrow1 = 0.f;
    const int r0 = w * 16 + (lane >> 2);        // local row (second row = +8)
    const float* qrow0 = QR + (((size_t)(h * S_LEN + i0 + r0)) << 11);
    const float* qrow1 = qrow0 + ((size_t)8 << 11);

    // prologue: tile 0 -> stage 0
    {
        const __nv_bfloat16* gs[4] = { Kh, Kl, Vh, Vl };
        #pragma unroll
        for (int p = 0; p < 4; p++)
            #pragma unroll
            for (int v = 0; v < 2; v++) {
                const int idx = tid + v * 256;
                const int row = idx >> 3, c16 = idx & 7;
                CP_ASYNC16(sb + p * APLANE_B + row * APITCH_B + c16 * 16,
                           gs[p] + (size_t)row * D_MODEL + h * HEAD_DIM + c16 * 8);
            }
        CP_COMMIT();
    }

    for (int jt = 0; jt < 32; jt++) {
        CP_WAIT(0);            // tile jt resident
        __syncthreads();       // all warps done with tile jt-1; tile jt visible
        if (jt + 1 < 32) {     // issue tile jt+1 into the opposite stage
            const int jn = (jt + 1) * 64;
            const uint32_t st2 = sb + ((jt + 1) & 1) * ASTAGE_B;
            const __nv_bfloat16* gs[4] = { Kh, Kl, Vh, Vl };
            #pragma unroll
            for (int p = 0; p < 4; p++)
                #pragma unroll
                for (int v = 0; v < 2; v++) {
                    const int idx = tid + v * 256;
                    const int row = idx >> 3, c16 = idx & 7;
                    CP_ASYNC16(st2 + p * APLANE_B + row * APITCH_B + c16 * 16,
                               gs[p] + (size_t)(jn + row) * D_MODEL + h * HEAD_DIM + c16 * 8);
                }
            CP_COMMIT();
        }

        const uint32_t st = sb + (jt & 1) * ASTAGE_B;
        const int j0 = jt * 64;

        // --- S init from packed rel: rel(i,j) = QR[h][i][2047 - j] ---
        float c[8][4];
        #pragma unroll
        for (int nf = 0; nf < 8; nf++) {
            const int jc = j0 + nf * 8 + (lane & 3) * 2;
            float2 g0 = *(const float2*)&qrow0[2046 - jc];
            float2 g1 = *(const float2*)&qrow1[2046 - jc];
            c[nf][0] = g0.y; c[nf][1] = g0.x;
            c[nf][2] = g1.y; c[nf][3] = g1.x;
        }

        // --- S += Q . K^T (split bf16) ---
        #pragma unroll
        for (int jf = 0; jf < 4; jf++) {
            const uint32_t rby = (uint32_t)(jf * 16 + (lane & 15)) * APITCH_B;
            #pragma unroll
            for (int kf = 0; kf < 4; kf++) {
                const uint32_t cb = (uint32_t)(kf * 16 + ((lane >> 4) * 8)) * 2;
                uint32_t kh4[4], kl4[4];
                ldm_x4(kh4, st + 0 * APLANE_B + rby + cb);
                ldm_x4(kl4, st + 1 * APLANE_B + rby + cb);
                uint32_t b0h[2] = { kh4[0], kh4[2] }, b1h[2] = { kh4[1], kh4[3] };
                uint32_t b0l[2] = { kl4[0], kl4[2] }, b1l[2] = { kl4[1], kl4[3] };
                mma_bf16(c[jf*2+0], qfh[kf], b0h);
                mma_bf16(c[jf*2+0], qfh[kf], b0l);
                mma_bf16(c[jf*2+0], qfl[kf], b0h);
                mma_bf16(c[jf*2+1], qfh[kf], b1h);
                mma_bf16(c[jf*2+1], qfh[kf], b1l);
                mma_bf16(c[jf*2+1], qfl[kf], b1h);
            }
        }

        // --- online softmax in fragments ---
        float mx0 = -1e30f, mx1 = -1e30f;
        #pragma unroll
        for (int nf = 0; nf < 8; nf++) {
            mx0 = fmaxf(mx0, fmaxf(c[nf][0], c[nf][1]));
            mx1 = fmaxf(mx1, fmaxf(c[nf][2], c[nf][3]));
        }
        mx0 = fmaxf(mx0, __shfl_xor_sync(0xffffffffu, mx0, 1));
        mx0 = fmaxf(mx0, __shfl_xor_sync(0xffffffffu, mx0, 2));
        mx1 = fmaxf(mx1, __shfl_xor_sync(0xffffffffu, mx1, 1));
        mx1 = fmaxf(mx1, __shfl_xor_sync(0xffffffffu, mx1, 2));
        const float mn0 = fmaxf(mrow0, mx0), mn1 = fmaxf(mrow1, mx1);
        const float cor0 = __expf(mrow0 - mn0), cor1 = __expf(mrow1 - mn1);
        mrow0 = mn0; mrow1 = mn1;

        uint32_t P0h[8], P1h[8], P0l[8], P1l[8];
        float ls0 = 0.f, ls1 = 0.f;
        #pragma unroll
        for (int nf = 0; nf < 8; nf++) {
            float p0 = __expf(c[nf][0] - mn0), p1 = __expf(c[nf][1] - mn0);
            float p2 = __expf(c[nf][2] - mn1), p3 = __expf(c[nf][3] - mn1);
            ls0 += p0 + p1; ls1 += p2 + p3;
            __nv_bfloat16 h0,l0,h1,l1;
            split2(p0,h0,l0); split2(p1,h1,l1);
            P0h[nf] = pack2(h0,h1); P0l[nf] = pack2(l0,l1);
            split2(p2,h0,l0); split2(p3,h1,l1);
            P1h[nf] = pack2(h0,h1); P1l[nf] = pack2(l0,l1);
        }
        ls0 += __shfl_xor_sync(0xffffffffu, ls0, 1);
        ls0 += __shfl_xor_sync(0xffffffffu, ls0, 2);
        ls1 += __shfl_xor_sync(0xffffffffu, ls1, 1);
        ls1 += __shfl_xor_sync(0xffffffffu, ls1, 2);
        lrow0 = lrow0 * cor0 + ls0;
        lrow1 = lrow1 * cor1 + ls1;
        #pragma unroll
        for (int df = 0; df < 8; df++) {
            o[df][0] *= cor0; o[df][1] *= cor0;
            o[df][2] *= cor1; o[df][3] *= cor1;
        }

        // --- O += P . V (split bf16); V fragments via ldmatrix.trans ---
        #pragma unroll
        for (int kfj = 0; kfj < 4; kfj++) {
            uint32_t ah[4] = { P0h[2*kfj], P1h[2*kfj], P0h[2*kfj+1], P1h[2*kfj+1] };
            uint32_t al[4] = { P0l[2*kfj], P1l[2*kfj], P0l[2*kfj+1], P1l[2*kfj+1] };
            const uint32_t rby = (uint32_t)(kfj * 16 + (lane & 15)) * APITCH_B;
            #pragma unroll
            for (int dc = 0; dc < 4; dc++) {
                const uint32_t cb = (uint32_t)(dc * 16 + ((lane >> 4) * 8)) * 2;
                uint32_t vh4[4], vl4[4];
                ldm_x4_t(vh4, st + 2 * APLANE_B + rby + cb);
                ldm_x4_t(vl4, st + 3 * APLANE_B + rby + cb);
                uint32_t bh0[2] = { vh4[0], vh4[1] }, bh1[2] = { vh4[2], vh4[3] };
                uint32_t bl0[2] = { vl4[0], vl4[1] }, bl1[2] = { vl4[2], vl4[3] };
                mma_bf16(o[dc*2+0], ah, bh0);
                mma_bf16(o[dc*2+0], ah, bl0);
                mma_bf16(o[dc*2+0], al, bh0);
                mma_bf16(o[dc*2+1], ah, bh1);
                mma_bf16(o[dc*2+1], ah, bl1);
                mma_bf16(o[dc*2+1], al, bh1);
            }
        }
    }

    // ---- finalize: O /= l, split-store AO bf16 planes ----
    const float inv0 = 1.f / lrow0, inv1 = 1.f / lrow1;
    const int gr0 = i0 + r0, gr1 = gr0 + 8;
    #pragma unroll
    for (int df = 0; df < 8; df++) {
        const int d = h * HEAD_DIM + df * 8 + (lane & 3) * 2;
        __nv_bfloat16 h0,l0,h1,l1;
        split2(o[df][0] * inv0, h0, l0); split2(o[df][1] * inv0, h1, l1);
        *(__nv_bfloat162*)&AOh[(size_t)gr0 * D_MODEL + d] = __nv_bfloat162{h0,h1};
        *(__nv_bfloat162*)&AOl[(size_t)gr0 * D_MODEL + d] = __nv_bfloat162{l0,l1};
        split2(o[df][2] * inv1, h0, l0); split2(o[df][3] * inv1, h1, l1);
        *(__nv_bfloat162*)&AOh[(size_t)gr1 * D_MODEL + d] = __nv_bfloat162{h0,h1};
        *(__nv_bfloat162*)&AOl[(size_t)gr1 * D_MODEL + d] = __nv_bfloat162{l0,l1};
    }
}

// ============================ Launcher =======================================
extern "C" void kernel_launch(void* const* d_in, const int* in_sizes, int n_in,
                              void* d_out, int out_size)
{
    const float* x   = (const float*)d_in[0];
    const float* Wq  = (const float*)d_in[1];
    const float* bq  = (const float*)d_in[2];
    const float* Wk  = (const float*)d_in[3];
    const float* bk  = (const float*)d_in[4];
    const float* Wv  = (const float*)d_in[5];
    const float* bv  = (const float*)d_in[6];
    const float* Wo  = (const float*)d_in[7];
    const float* bo  = (const float*)d_in[8];
    const float* rel = (const float*)d_in[9];
    float* out = (float*)d_out;

    float* pQR;
    __nv_bfloat16 *pxh, *pxl, *pQh, *pQl, *pKh, *pKl, *pVh, *pVl;
    __nv_bfloat16 *pAOh, *pAOl, *pWth, *pWtl, *pTh, *pTl;
    cudaGetSymbolAddress((void**)&pQR,  g_QR);
    cudaGetSymbolAddress((void**)&pxh,  g_xh);
    cudaGetSymbolAddress((void**)&pxl,  g_xl);
    cudaGetSymbolAddress((void**)&pQh,  g_Qh);
    cudaGetSymbolAddress((void**)&pQl,  g_Ql);
    cudaGetSymbolAddress((void**)&pKh,  g_Kh);
    cudaGetSymbolAddress((void**)&pKl,  g_Kl);
    cudaGetSymbolAddress((void**)&pVh,  g_Vh);
    cudaGetSymbolAddress((void**)&pVl,  g_Vl);
    cudaGetSymbolAddress((void**)&pAOh, g_AOh);
    cudaGetSymbolAddress((void**)&pAOl, g_AOl);
    cudaGetSymbolAddress((void**)&pWth, g_Wth);
    cudaGetSymbolAddress((void**)&pWtl, g_Wtl);
    cudaGetSymbolAddress((void**)&pTh,  g_Th);
    cudaGetSymbolAddress((void**)&pTl,  g_Tl);

    const int gemm_smem = 2 * STAGE_B;       // 81,920
    const int qrel_smem = 4 * QPLANE_B;      // 73,728
    const int attn_smem = 2 * ASTAGE_B;      // 73,728
    cudaFuncSetAttribute(tc_gemm_kernel,  cudaFuncAttributeMaxDynamicSharedMemorySize, gemm_smem);
    cudaFuncSetAttribute(tc_qrel_kernel,  cudaFuncAttributeMaxDynamicSharedMemorySize, qrel_smem);
    cudaFuncSetAttribute(attn_mma_kernel, cudaFuncAttributeMaxDynamicSharedMemorySize, attn_smem);

    // 0) splits: x, W^T (x4), rel_table
    split_plane_kernel<<<(S_LEN * D_MODEL / 4 + 255) / 256, 256>>>(x, pxh, pxl, S_LEN * D_MODEL / 4);
    WSrc ws; ws.w[0] = Wq; ws.w[1] = Wk; ws.w[2] = Wv; ws.w[3] = Wo;
    wsplit_kernel<<<dim3(32, 32, 4), 256>>>(ws, pWth, pWtl);
    split_T_kernel<<<(TPAD * HEAD_DIM + 255) / 256, 256>>>(rel, pTh, pTl);

    const size_t MM = (size_t)D_MODEL * D_MODEL;

    // 1) QKV projections -> bf16 planes only (K folded with 1/8)
    TCArgs aq{ pxh, pxl, pWth + 0*MM, pWtl + 0*MM, bq, nullptr, pQh, pQl, 1.0f };
    TCArgs ak{ pxh, pxl, pWth + 1*MM, pWtl + 1*MM, bk, nullptr, pKh, pKl, 0.125f };
    TCArgs av{ pxh, pxl, pWth + 2*MM, pWtl + 2*MM, bv, nullptr, pVh, pVl, 1.0f };
    tc_gemm_kernel<<<dim3(8, 16, 3), 256, gemm_smem>>>(aq, ak, av);

    // 2) packed banded qrel
    tc_qrel_kernel<<<dim3(17, 16, 16), 256, qrel_smem>>>(pQh, pQl, pTh, pTl, pQR);

    // 3) mma flash attention -> AO bf16 planes
    attn_mma_kernel<<<dim3(16, 16), 256, attn_smem>>>(pQh, pQl, pKh, pKl, pVh, pVl,
                                                      pQR, pAOh, pAOl);

    // 4) output projection -> fp32 out
    TCArgs ao{ pAOh, pAOl, pWth + 3*MM, pWtl + 3*MM, bo, out, nullptr, nullptr, 1.0f };
    tc_gemm_kernel<<<dim3(8, 16, 1), 256, gemm_smem>>>(ao, ao, ao);
}

// round 10
// speedup vs baseline: 2.4475x; 1.0042x over previous
#include <cuda_runtime.h>
#include <cuda_bf16.h>
#include <cstdint>

#define S_LEN 2048
#define D_MODEL 1024
#define N_HEADS 16
#define HEAD_DIM 64
#define TBL 4095        // 2*S - 1
#define KPACK 2048      // packed rel length per row
#define TPAD 4096       // padded rel_table rows (rows >= TBL zeroed)

// ---------------- scratch (__device__ arrays, no allocs) ---------------------
__device__ float g_QR[(size_t)N_HEADS * S_LEN * KPACK];  // 256 MiB packed rel

__device__ __nv_bfloat16 g_xh [S_LEN * D_MODEL], g_xl [S_LEN * D_MODEL];
__device__ __nv_bfloat16 g_Qh [S_LEN * D_MODEL], g_Ql [S_LEN * D_MODEL];
__device__ __nv_bfloat16 g_Kh [S_LEN * D_MODEL], g_Kl [S_LEN * D_MODEL];
__device__ __nv_bfloat16 g_Vh [S_LEN * D_MODEL], g_Vl [S_LEN * D_MODEL];
__device__ __nv_bfloat16 g_AOh[S_LEN * D_MODEL], g_AOl[S_LEN * D_MODEL];
__device__ __nv_bfloat16 g_Wth[4u * D_MODEL * D_MODEL], g_Wtl[4u * D_MODEL * D_MODEL];
__device__ __nv_bfloat16 g_Th [TPAD * HEAD_DIM], g_Tl [TPAD * HEAD_DIM];

// ============================ helpers ========================================
__device__ __forceinline__ uint32_t smem_u32(const void* p) {
    uint32_t a;
    asm("{ .reg .u64 t; cvta.to.shared.u64 t, %1; cvt.u32.u64 %0, t; }" : "=r"(a) : "l"(p));
    return a;
}
__device__ __forceinline__ void ldm_x4(uint32_t* r, uint32_t addr) {
    asm volatile("ldmatrix.sync.aligned.m8n8.x4.shared.b16 {%0,%1,%2,%3}, [%4];"
        : "=r"(r[0]), "=r"(r[1]), "=r"(r[2]), "=r"(r[3]) : "r"(addr));
}
__device__ __forceinline__ void ldm_x4_t(uint32_t* r, uint32_t addr) {
    asm volatile("ldmatrix.sync.aligned.m8n8.x4.trans.shared.b16 {%0,%1,%2,%3}, [%4];"
        : "=r"(r[0]), "=r"(r[1]), "=r"(r[2]), "=r"(r[3]) : "r"(addr));
}
__device__ __forceinline__ void mma_bf16(float* c, const uint32_t* a, const uint32_t* b) {
    asm volatile("mma.sync.aligned.m16n8k16.row.col.f32.bf16.bf16.f32 "
        "{%0,%1,%2,%3}, {%4,%5,%6,%7}, {%8,%9}, {%0,%1,%2,%3};"
        : "+f"(c[0]), "+f"(c[1]), "+f"(c[2]), "+f"(c[3])
        : "r"(a[0]), "r"(a[1]), "r"(a[2]), "r"(a[3]), "r"(b[0]), "r"(b[1]));
}
#define CP_ASYNC16(dst, src) \
    asm volatile("cp.async.cg.shared.global [%0], [%1], 16;" :: "r"(dst), "l"(src))
#define CP_COMMIT() asm volatile("cp.async.commit_group;")
#define CP_WAIT(N)  asm volatile("cp.async.wait_group %0;" :: "n"(N) : "memory")

__device__ __forceinline__ void split2(float v, __nv_bfloat16& h, __nv_bfloat16& l) {
    h = __float2bfloat16(v);
    l = __float2bfloat16(v - __bfloat162float(h));
}
__device__ __forceinline__ uint32_t pack2(__nv_bfloat16 lo, __nv_bfloat16 hi) {
    __nv_bfloat162 t{lo, hi};
    return *(uint32_t*)&t;
}

// ============================ split kernels ==================================
__global__ void split_plane_kernel(const float* __restrict__ src,
                                   __nv_bfloat16* __restrict__ ph,
                                   __nv_bfloat16* __restrict__ pl, int n4)
{
    int i = blockIdx.x * blockDim.x + threadIdx.x;
    if (i >= n4) return;
    float4 v = *(const float4*)(src + (size_t)i * 4);
    __nv_bfloat16 h, l;
    split2(v.x, h, l); ph[i*4+0] = h; pl[i*4+0] = l;
    split2(v.y, h, l); ph[i*4+1] = h; pl[i*4+1] = l;
    split2(v.z, h, l); ph[i*4+2] = h; pl[i*4+2] = l;
    split2(v.w, h, l); ph[i*4+3] = h; pl[i*4+3] = l;
}

__global__ void split_T_kernel(const float* __restrict__ rel,
                               __nv_bfloat16* __restrict__ th,
                               __nv_bfloat16* __restrict__ tl)
{
    int i = blockIdx.x * blockDim.x + threadIdx.x;
    if (i >= TPAD * HEAD_DIM) return;
    int t = i >> 6;
    float v = (t < TBL) ? rel[i] : 0.f;
    __nv_bfloat16 h, l; split2(v, h, l);
    th[i] = h; tl[i] = l;
}

struct WSrc { const float* w[4]; };
__global__ __launch_bounds__(256) void wsplit_kernel(WSrc ws,
                                                     __nv_bfloat16* __restrict__ dh,
                                                     __nv_bfloat16* __restrict__ dl)
{
    __shared__ float t[32][33];
    const float* W = ws.w[blockIdx.z];
    __nv_bfloat16* oh = dh + (size_t)blockIdx.z * D_MODEL * D_MODEL;
    __nv_bfloat16* ol = dl + (size_t)blockIdx.z * D_MODEL * D_MODEL;
    const int n0 = blockIdx.x * 32, k0 = blockIdx.y * 32;
    const int tx = threadIdx.x & 31, ty = threadIdx.x >> 5;
    #pragma unroll
    for (int rr = 0; rr < 32; rr += 8)
        t[ty + rr][tx] = W[(size_t)(k0 + ty + rr) * D_MODEL + n0 + tx];
    __syncthreads();
    #pragma unroll
    for (int rr = 0; rr < 32; rr += 8) {
        float v = t[tx][ty + rr];
        __nv_bfloat16 h, l; split2(v, h, l);
        oh[(size_t)(n0 + ty + rr) * D_MODEL + k0 + tx] = h;
        ol[(size_t)(n0 + ty + rr) * D_MODEL + k0 + tx] = l;
    }
}

// ============================ mma.sync projection GEMM =======================
// Single-sync double buffer: per iter  wait(0) -> barrier -> issue next -> compute.
#define GPITCH 40
#define PLANE_B (128 * GPITCH * 2)     // 10240 bytes per plane
#define STAGE_B (4 * PLANE_B)          // 40960 bytes per stage

struct TCArgs {
    const __nv_bfloat16 *Ah, *Al, *Bh, *Bl;
    const float* bias; float* C;       // C may be null (bf16-only output)
    __nv_bfloat16 *Ch, *Cl;            // may be null (fp32-only output)
    float scale;
};

__global__ __launch_bounds__(256) void tc_gemm_kernel(TCArgs a0, TCArgs a1, TCArgs a2)
{
    TCArgs a = (blockIdx.z == 0) ? a0 : ((blockIdx.z == 1) ? a1 : a2);
    extern __shared__ char dsm[];
    __shared__ float biasS[128];

    const int tid = threadIdx.x, lane = tid & 31, w = tid >> 5;
    const int wm = w >> 2, wn = w & 3;
    const int m0 = blockIdx.y * 128, n0 = blockIdx.x * 128;
    const uint32_t sbase = smem_u32(dsm);

    if (tid < 128) biasS[tid] = a.bias[n0 + tid];

    const __nv_bfloat16* gsrc[4] = { a.Ah, a.Al, a.Bh, a.Bl };
    const int rb[4] = { m0, m0, n0, n0 };

    // prologue: chunk 0 -> stage 0
    #pragma unroll
    for (int p = 0; p < 4; p++) {
        const __nv_bfloat16* g = gsrc[p];
        #pragma unroll
        for (int v = 0; v < 2; v++) {
            const int idx = tid + v * 256;
            const int row = idx >> 2, c16 = idx & 3;
            CP_ASYNC16(sbase + p * PLANE_B + row * 80 + c16 * 16,
                       g + (size_t)(rb[p] + row) * D_MODEL + c16 * 8);
        }
    }
    CP_COMMIT();

    float acc[4][4][4];
    #pragma unroll
    for (int i = 0; i < 4; i++)
        #pragma unroll
        for (int j = 0; j < 4; j++)
            #pragma unroll
            for (int q = 0; q < 4; q++) acc[i][j][q] = 0.f;

    for (int c = 0; c < 32; c++) {
        CP_WAIT(0);            // chunk c resident
        __syncthreads();       // all warps done with chunk c-1; chunk c visible
        if (c + 1 < 32) {      // issue chunk c+1 into the opposite stage
            const int k0 = (c + 1) * 32;
            const uint32_t st = sbase + ((c + 1) & 1) * STAGE_B;
            #pragma unroll
            for (int p = 0; p < 4; p++) {
                const __nv_bfloat16* g = gsrc[p];
                #pragma unroll
                for (int v = 0; v < 2; v++) {
                    const int idx = tid + v * 256;
                    const int row = idx >> 2, c16 = idx & 3;
                    CP_ASYNC16(st + p * PLANE_B + row * 80 + c16 * 16,
                               g + (size_t)(rb[p] + row) * D_MODEL + k0 + c16 * 8);
                }
            }
            CP_COMMIT();
        }

        const uint32_t sb = sbase + (c & 1) * STAGE_B;
        #pragma unroll
        for (int ks = 0; ks < 2; ks++) {
            const uint32_t colb = (uint32_t)(ks * 16 + ((lane >> 4) * 8)) * 2;
            uint32_t ah[4][4], al[4][4], bh[2][4], bl[2][4];
            #pragma unroll
            for (int mt = 0; mt < 4; mt++) {
                const uint32_t r = wm * 64 + mt * 16 + (lane & 15);
                ldm_x4(ah[mt], sb + 0 * PLANE_B + r * 80 + colb);
                ldm_x4(al[mt], sb + 1 * PLANE_B + r * 80 + colb);
            }
            #pragma unroll
            for (int nt2 = 0; nt2 < 2; nt2++) {
                const uint32_t r = wn * 32 + nt2 * 16 + (lane & 15);
                ldm_x4(bh[nt2], sb + 2 * PLANE_B + r * 80 + colb);
                ldm_x4(bl[nt2], sb + 3 * PLANE_B + r * 80 + colb);
            }
            #pragma unroll
            for (int mt = 0; mt < 4; mt++)
                #pragma unroll
                for (int nt = 0; nt < 4; nt++) {
                    uint32_t bhf[2] = { bh[nt >> 1][nt & 1], bh[nt >> 1][(nt & 1) + 2] };
                    uint32_t blf[2] = { bl[nt >> 1][nt & 1], bl[nt >> 1][(nt & 1) + 2] };
                    mma_bf16(acc[mt][nt], ah[mt], bhf);
                    mma_bf16(acc[mt][nt], ah[mt], blf);
                    mma_bf16(acc[mt][nt], al[mt], bhf);
                }
        }
    }

    #pragma unroll
    for (int mt = 0; mt < 4; mt++) {
        const int r0 = m0 + wm * 64 + mt * 16 + (lane >> 2);
        #pragma unroll
        for (int nt = 0; nt < 4; nt++) {
            const int cl = wn * 32 + nt * 8 + 2 * (lane & 3);
            const int cg = n0 + cl;
            float2 v0, v1;
            v0.x = (acc[mt][nt][0] + biasS[cl + 0]) * a.scale;
            v0.y = (acc[mt][nt][1] + biasS[cl + 1]) * a.scale;
            v1.x = (acc[mt][nt][2] + biasS[cl + 0]) * a.scale;
            v1.y = (acc[mt][nt][3] + biasS[cl + 1]) * a.scale;
            if (a.C) {
                *(float2*)&a.C[(size_t)r0 * D_MODEL + cg]       = v0;
                *(float2*)&a.C[(size_t)(r0 + 8) * D_MODEL + cg] = v1;
            }
            if (a.Ch) {
                __nv_bfloat16 h0,l0,h1,l1;
                split2(v0.x,h0,l0); split2(v0.y,h1,l1);
                *(__nv_bfloat162*)&a.Ch[(size_t)r0 * D_MODEL + cg] = __nv_bfloat162{h0,h1};
                *(__nv_bfloat162*)&a.Cl[(size_t)r0 * D_MODEL + cg] = __nv_bfloat162{l0,l1};
                split2(v1.x,h0,l0); split2(v1.y,h1,l1);
                *(__nv_bfloat162*)&a.Ch[(size_t)(r0 + 8) * D_MODEL + cg] = __nv_bfloat162{h0,h1};
                *(__nv_bfloat162*)&a.Cl[(size_t)(r0 + 8) * D_MODEL + cg] = __nv_bfloat162{l0,l1};
            }
        }
    }
}

// ============================ mma.sync qrel ==================================
#define QPITCH 72
#define QPLANE_B (128 * QPITCH * 2)    // 18432 bytes

__global__ __launch_bounds__(256) void tc_qrel_kernel(const __nv_bfloat16* __restrict__ Qh,
                                                      const __nv_bfloat16* __restrict__ Ql,
                                                      const __nv_bfloat16* __restrict__ Th,
                                                      const __nv_bfloat16* __restrict__ Tl,
                                                      float* __restrict__ R)
{
    extern __shared__ char dsm[];
    const int tid = threadIdx.x, lane = tid & 31, w = tid >> 5;
    const int wm = w >> 2, wn = w & 3;
    const int tt = blockIdx.x, i0 = blockIdx.y * 128, h = blockIdx.z;
    const int t0 = i0 + tt * 128;
    const uint32_t sbase = smem_u32(dsm);

    #pragma unroll
    for (int p = 0; p < 4; p++) {
        #pragma unroll
        for (int v = 0; v < 4; v++) {
            const int idx = tid + v * 256;
            const int row = idx >> 3, c16 = idx & 7;
            const __nv_bfloat16* src;
            if (p == 0)      src = Qh + (size_t)(i0 + row) * D_MODEL + h * HEAD_DIM + c16 * 8;
            else if (p == 1) src = Ql + (size_t)(i0 + row) * D_MODEL + h * HEAD_DIM + c16 * 8;
            else if (p == 2) src = Th + (size_t)(t0 + row) * HEAD_DIM + c16 * 8;
            else             src = Tl + (size_t)(t0 + row) * HEAD_DIM + c16 * 8;
            CP_ASYNC16(sbase + p * QPLANE_B + row * 144 + c16 * 16, src);
        }
    }
    CP_COMMIT(); CP_WAIT(0);
    __syncthreads();

    float acc[4][4][4];
    #pragma unroll
    for (int i = 0; i < 4; i++)
        #pragma unroll
        for (int j = 0; j < 4; j++)
            #pragma unroll
            for (int q = 0; q < 4; q++) acc[i][j][q] = 0.f;

    #pragma unroll
    for (int ks = 0; ks < 4; ks++) {
        const uint32_t colb = (uint32_t)(ks * 16 + ((lane >> 4) * 8)) * 2;
        uint32_t ah[4][4], al[4][4], bh[2][4], bl[2][4];
        #pragma unroll
        for (int mt = 0; mt < 4; mt++) {
            const uint32_t r = wm * 64 + mt * 16 + (lane & 15);
            ldm_x4(ah[mt], sbase + 0 * QPLANE_B + r * 144 + colb);
            ldm_x4(al[mt], sbase + 1 * QPLANE_B + r * 144 + colb);
        }
        #pragma unroll
        for (int nt2 = 0; nt2 < 2; nt2++) {
            const uint32_t r = wn * 32 + nt2 * 16 + (lane & 15);
            ldm_x4(bh[nt2], sbase + 2 * QPLANE_B + r * 144 + colb);
            ldm_x4(bl[nt2], sbase + 3 * QPLANE_B + r * 144 + colb);
        }
        #pragma unroll
        for (int mt = 0; mt < 4; mt++)
            #pragma unroll
            for (int nt = 0; nt < 4; nt++) {
                uint32_t bhf[2] = { bh[nt >> 1][nt & 1], bh[nt >> 1][(nt & 1) + 2] };
                uint32_t blf[2] = { bl[nt >> 1][nt & 1], bl[nt >> 1][(nt & 1) + 2] };
                mma_bf16(acc[mt][nt], ah[mt], bhf);
                mma_bf16(acc[mt][nt], ah[mt], blf);
                mma_bf16(acc[mt][nt], al[mt], bhf);
            }
    }

    #pragma unroll
    for (int mt = 0; mt < 4; mt++) {
        const int rloc = wm * 64 + mt * 16 + (lane >> 2);
        float* Rrow0 = R + (((size_t)(h * S_LEN + i0 + rloc))     << 11);
        float* Rrow1 = R + (((size_t)(h * S_LEN + i0 + rloc + 8)) << 11);
        #pragma unroll
        for (int nt = 0; nt < 4; nt++) {
            const int cloc = wn * 32 + nt * 8 + 2 * (lane & 3);
            const int k0 = tt * 128 + cloc - rloc;
            if ((unsigned)(k0)     < (unsigned)KPACK) Rrow0[k0]     = acc[mt][nt][0];
            if ((unsigned)(k0 + 1) < (unsigned)KPACK) Rrow0[k0 + 1] = acc[mt][nt][1];
            if ((unsigned)(k0 - 8) < (unsigned)KPACK) Rrow1[k0 - 8] = acc[mt][nt][2];
            if ((unsigned)(k0 - 7) < (unsigned)KPACK) Rrow1[k0 - 7] = acc[mt][nt][3];
        }
    }
}

// ============================ mma.sync flash attention =======================
// Single-sync double buffer on the j-loop (wait -> barrier -> issue -> compute).
#define APITCH_B 144
#define APLANE_B (64 * APITCH_B)       // 9216
#define ASTAGE_B (4 * APLANE_B)        // 36864

__global__ __launch_bounds__(256) void attn_mma_kernel(
    const __nv_bfloat16* __restrict__ Qh, const __nv_bfloat16* __restrict__ Ql,
    const __nv_bfloat16* __restrict__ Kh, const __nv_bfloat16* __restrict__ Kl,
    const __nv_bfloat16* __restrict__ Vh, const __nv_bfloat16* __restrict__ Vl,
    const float* __restrict__ QR,
    __nv_bfloat16* __restrict__ AOh, __nv_bfloat16* __restrict__ AOl)
{
    extern __shared__ char dsm[];
    const int tid = threadIdx.x, lane = tid & 31, w = tid >> 5;
    const int i0 = blockIdx.x * 128, h = blockIdx.y;
    const uint32_t sb = smem_u32(dsm);

    // ---- stage Q (128 rows x 64 bf16 = 8x16B per row, 2 planes) ----
    #pragma unroll
    for (int p = 0; p < 2; p++) {
        const __nv_bfloat16* g = p ? Ql : Qh;
        #pragma unroll
        for (int v = 0; v < 4; v++) {
            const int idx = tid + v * 256;
            const int row = idx >> 3, c16 = idx & 7;
            CP_ASYNC16(sb + p * 18432 + row * APITCH_B + c16 * 16,
                       g + (size_t)(i0 + row) * D_MODEL + h * HEAD_DIM + c16 * 8);
        }
    }
    CP_COMMIT(); CP_WAIT(0);
    __syncthreads();

    uint32_t qfh[4][4], qfl[4][4];
    {
        const uint32_t rbyte = (uint32_t)(w * 16 + (lane & 15)) * APITCH_B;
        #pragma unroll
        for (int kf = 0; kf < 4; kf++) {
            const uint32_t colb = (uint32_t)(kf * 16 + ((lane >> 4) * 8)) * 2;
            ldm_x4(qfh[kf], sb + 0 * 18432 + rbyte + colb);
            ldm_x4(qfl[kf], sb + 1 * 18432 + rbyte + colb);
        }
    }
    __syncthreads();

    float o[8][4];
    #pragma unroll
    for (int i = 0; i < 8; i++)
        #pragma unroll
        for (int q = 0; q < 4; q++) o[i][q] = 0.f;
    float mrow0 = -1e30f, mrow1 = -1e30f, lrow0 = 0.f, lrow1 = 0.f;
    const int r0 = w * 16 + (lane >> 2);        // local row (second row = +8)
    const float* qrow0 = QR + (((size_t)(h * S_LEN + i0 + r0)) << 11);
    const float* qrow1 = qrow0 + ((size_t)8 << 11);

    // prologue: tile 0 -> stage 0
    {
        const __nv_bfloat16* gs[4] = { Kh, Kl, Vh, Vl };
        #pragma unroll
        for (int p = 0; p < 4; p++)
            #pragma unroll
            for (int v = 0; v < 2; v++) {
                const int idx = tid + v * 256;
                const int row = idx >> 3, c16 = idx & 7;
                CP_ASYNC16(sb + p * APLANE_B + row * APITCH_B + c16 * 16,
                           gs[p] + (size_t)row * D_MODEL + h * HEAD_DIM + c16 * 8);
            }
        CP_COMMIT();
    }

    for (int jt = 0; jt < 32; jt++) {
        CP_WAIT(0);            // tile jt resident
        __syncthreads();       // all warps done with tile jt-1; tile jt visible
        if (jt + 1 < 32) {     // issue tile jt+1 into the opposite stage
            const int jn = (jt + 1) * 64;
            const uint32_t st2 = sb + ((jt + 1) & 1) * ASTAGE_B;
            const __nv_bfloat16* gs[4] = { Kh, Kl, Vh, Vl };
            #pragma unroll
            for (int p = 0; p < 4; p++)
                #pragma unroll
                for (int v = 0; v < 2; v++) {
                    const int idx = tid + v * 256;
                    const int row = idx >> 3, c16 = idx & 7;
                    CP_ASYNC16(st2 + p * APLANE_B + row * APITCH_B + c16 * 16,
                               gs[p] + (size_t)(jn + row) * D_MODEL + h * HEAD_DIM + c16 * 8);
                }
            CP_COMMIT();
        }

        const uint32_t st = sb + (jt & 1) * ASTAGE_B;
        const int j0 = jt * 64;

        // --- S init from packed rel: rel(i,j) = QR[h][i][2047 - j] ---
        float c[8][4];
        #pragma unroll
        for (int nf = 0; nf < 8; nf++) {
            const int jc = j0 + nf * 8 + (lane & 3) * 2;
            float2 g0 = *(const float2*)&qrow0[2046 - jc];
            float2 g1 = *(const float2*)&qrow1[2046 - jc];
            c[nf][0] = g0.y; c[nf][1] = g0.x;
            c[nf][2] = g1.y; c[nf][3] = g1.x;
        }

        // --- S += Q . K^T (split bf16) ---
        #pragma unroll
        for (int jf = 0; jf < 4; jf++) {
            const uint32_t rby = (uint32_t)(jf * 16 + (lane & 15)) * APITCH_B;
            #pragma unroll
            for (int kf = 0; kf < 4; kf++) {
                const uint32_t cb = (uint32_t)(kf * 16 + ((lane >> 4) * 8)) * 2;
                uint32_t kh4[4], kl4[4];
                ldm_x4(kh4, st + 0 * APLANE_B + rby + cb);
                ldm_x4(kl4, st + 1 * APLANE_B + rby + cb);
                uint32_t b0h[2] = { kh4[0], kh4[2] }, b1h[2] = { kh4[1], kh4[3] };
                uint32_t b0l[2] = { kl4[0], kl4[2] }, b1l[2] = { kl4[1], kl4[3] };
                mma_bf16(c[jf*2+0], qfh[kf], b0h);
                mma_bf16(c[jf*2+0], qfh[kf], b0l);
                mma_bf16(c[jf*2+0], qfl[kf], b0h);
                mma_bf16(c[jf*2+1], qfh[kf], b1h);
                mma_bf16(c[jf*2+1], qfh[kf], b1l);
                mma_bf16(c[jf*2+1], qfl[kf], b1h);
            }
        }

        // --- online softmax in fragments ---
        float mx0 = -1e30f, mx1 = -1e30f;
        #pragma unroll
        for (int nf = 0; nf < 8; nf++) {
            mx0 = fmaxf(mx0, fmaxf(c[nf][0], c[nf][1]));
            mx1 = fmaxf(mx1, fmaxf(c[nf][2], c[nf][3]));
        }
        mx0 = fmaxf(mx0, __shfl_xor_sync(0xffffffffu, mx0, 1));
        mx0 = fmaxf(mx0, __shfl_xor_sync(0xffffffffu, mx0, 2));
        mx1 = fmaxf(mx1, __shfl_xor_sync(0xffffffffu, mx1, 1));
        mx1 = fmaxf(mx1, __shfl_xor_sync(0xffffffffu, mx1, 2));
        const float mn0 = fmaxf(mrow0, mx0), mn1 = fmaxf(mrow1, mx1);
        const float cor0 = __expf(mrow0 - mn0), cor1 = __expf(mrow1 - mn1);
        mrow0 = mn0; mrow1 = mn1;

        uint32_t P0h[8], P1h[8], P0l[8], P1l[8];
        float ls0 = 0.f, ls1 = 0.f;
        #pragma unroll
        for (int nf = 0; nf < 8; nf++) {
            float p0 = __expf(c[nf][0] - mn0), p1 = __expf(c[nf][1] - mn0);
            float p2 = __expf(c[nf][2] - mn1), p3 = __expf(c[nf][3] - mn1);
            ls0 += p0 + p1; ls1 += p2 + p3;
            __nv_bfloat16 h0,l0,h1,l1;
            split2(p0,h0,l0); split2(p1,h1,l1);
            P0h[nf] = pack2(h0,h1); P0l[nf] = pack2(l0,l1);
            split2(p2,h0,l0); split2(p3,h1,l1);
            P1h[nf] = pack2(h0,h1); P1l[nf] = pack2(l0,l1);
        }
        ls0 += __shfl_xor_sync(0xffffffffu, ls0, 1);
        ls0 += __shfl_xor_sync(0xffffffffu, ls0, 2);
        ls1 += __shfl_xor_sync(0xffffffffu, ls1, 1);
        ls1 += __shfl_xor_sync(0xffffffffu, ls1, 2);
        lrow0 = lrow0 * cor0 + ls0;
        lrow1 = lrow1 * cor1 + ls1;
        #pragma unroll
        for (int df = 0; df < 8; df++) {
            o[df][0] *= cor0; o[df][1] *= cor0;
            o[df][2] *= cor1; o[df][3] *= cor1;
        }

        // --- O += P . V (split bf16); V fragments via ldmatrix.trans ---
        #pragma unroll
        for (int kfj = 0; kfj < 4; kfj++) {
            uint32_t ah[4] = { P0h[2*kfj], P1h[2*kfj], P0h[2*kfj+1], P1h[2*kfj+1] };
            uint32_t al[4] = { P0l[2*kfj], P1l[2*kfj], P0l[2*kfj+1], P1l[2*kfj+1] };
            const uint32_t rby = (uint32_t)(kfj * 16 + (lane & 15)) * APITCH_B;
            #pragma unroll
            for (int dc = 0; dc < 4; dc++) {
                const uint32_t cb = (uint32_t)(dc * 16 + ((lane >> 4) * 8)) * 2;
                uint32_t vh4[4], vl4[4];
                ldm_x4_t(vh4, st + 2 * APLANE_B + rby + cb);
                ldm_x4_t(vl4, st + 3 * APLANE_B + rby + cb);
                uint32_t bh0[2] = { vh4[0], vh4[1] }, bh1[2] = { vh4[2], vh4[3] };
                uint32_t bl0[2] = { vl4[0], vl4[1] }, bl1[2] = { vl4[2], vl4[3] };
                mma_bf16(o[dc*2+0], ah, bh0);
                mma_bf16(o[dc*2+0], ah, bl0);
                mma_bf16(o[dc*2+0], al, bh0);
                mma_bf16(o[dc*2+1], ah, bh1);
                mma_bf16(o[dc*2+1], ah, bl1);
                mma_bf16(o[dc*2+1], al, bh1);
            }
        }
    }

    // ---- finalize: O /= l, split-store AO bf16 planes ----
    const float inv0 = 1.f / lrow0, inv1 = 1.f / lrow1;
    const int gr0 = i0 + r0, gr1 = gr0 + 8;
    #pragma unroll
    for (int df = 0; df < 8; df++) {
        const int d = h * HEAD_DIM + df * 8 + (lane & 3) * 2;
        __nv_bfloat16 h0,l0,h1,l1;
        split2(o[df][0] * inv0, h0, l0); split2(o[df][1] * inv0, h1, l1);
        *(__nv_bfloat162*)&AOh[(size_t)gr0 * D_MODEL + d] = __nv_bfloat162{h0,h1};
        *(__nv_bfloat162*)&AOl[(size_t)gr0 * D_MODEL + d] = __nv_bfloat162{l0,l1};
        split2(o[df][2] * inv1, h0, l0); split2(o[df][3] * inv1, h1, l1);
        *(__nv_bfloat162*)&AOh[(size_t)gr1 * D_MODEL + d] = __nv_bfloat162{h0,h1};
        *(__nv_bfloat162*)&AOl[(size_t)gr1 * D_MODEL + d] = __nv_bfloat162{l0,l1};
    }
}

// ============================ Launcher =======================================
extern "C" void kernel_launch(void* const* d_in, const int* in_sizes, int n_in,
                              void* d_out, int out_size)
{
    const float* x   = (const float*)d_in[0];
    const float* Wq  = (const float*)d_in[1];
    const float* bq  = (const float*)d_in[2];
    const float* Wk  = (const float*)d_in[3];
    const float* bk  = (const float*)d_in[4];
    const float* Wv  = (const float*)d_in[5];
    const float* bv  = (const float*)d_in[6];
    const float* Wo  = (const float*)d_in[7];
    const float* bo  = (const float*)d_in[8];
    const float* rel = (const float*)d_in[9];
    float* out = (float*)d_out;

    float* pQR;
    __nv_bfloat16 *pxh, *pxl, *pQh, *pQl, *pKh, *pKl, *pVh, *pVl;
    __nv_bfloat16 *pAOh, *pAOl, *pWth, *pWtl, *pTh, *pTl;
    cudaGetSymbolAddress((void**)&pQR,  g_QR);
    cudaGetSymbolAddress((void**)&pxh,  g_xh);
    cudaGetSymbolAddress((void**)&pxl,  g_xl);
    cudaGetSymbolAddress((void**)&pQh,  g_Qh);
    cudaGetSymbolAddress((void**)&pQl,  g_Ql);
    cudaGetSymbolAddress((void**)&pKh,  g_Kh);
    cudaGetSymbolAddress((void**)&pKl,  g_Kl);
    cudaGetSymbolAddress((void**)&pVh,  g_Vh);
    cudaGetSymbolAddress((void**)&pVl,  g_Vl);
    cudaGetSymbolAddress((void**)&pAOh, g_AOh);
    cudaGetSymbolAddress((void**)&pAOl, g_AOl);
    cudaGetSymbolAddress((void**)&pWth, g_Wth);
    cudaGetSymbolAddress((void**)&pWtl, g_Wtl);
    cudaGetSymbolAddress((void**)&pTh,  g_Th);
    cudaGetSymbolAddress((void**)&pTl,  g_Tl);

    const int gemm_smem = 2 * STAGE_B;       // 81,920
    const int qrel_smem = 4 * QPLANE_B;      // 73,728
    const int attn_smem = 2 * ASTAGE_B;      // 73,728
    cudaFuncSetAttribute(tc_gemm_kernel,  cudaFuncAttributeMaxDynamicSharedMemorySize, gemm_smem);
    cudaFuncSetAttribute(tc_qrel_kernel,  cudaFuncAttributeMaxDynamicSharedMemorySize, qrel_smem);
    cudaFuncSetAttribute(attn_mma_kernel, cudaFuncAttributeMaxDynamicSharedMemorySize, attn_smem);

    // 0) splits: x, W^T (x4), rel_table
    split_plane_kernel<<<(S_LEN * D_MODEL / 4 + 255) / 256, 256>>>(x, pxh, pxl, S_LEN * D_MODEL / 4);
    WSrc ws; ws.w[0] = Wq; ws.w[1] = Wk; ws.w[2] = Wv; ws.w[3] = Wo;
    wsplit_kernel<<<dim3(32, 32, 4), 256>>>(ws, pWth, pWtl);
    split_T_kernel<<<(TPAD * HEAD_DIM + 255) / 256, 256>>>(rel, pTh, pTl);

    const size_t MM = (size_t)D_MODEL * D_MODEL;

    // 1) QKV projections -> bf16 planes only (K folded with 1/8)
    TCArgs aq{ pxh, pxl, pWth + 0*MM, pWtl + 0*MM, bq, nullptr, pQh, pQl, 1.0f };
    TCArgs ak{ pxh, pxl, pWth + 1*MM, pWtl + 1*MM, bk, nullptr, pKh, pKl, 0.125f };
    TCArgs av{ pxh, pxl, pWth + 2*MM, pWtl + 2*MM, bv, nullptr, pVh, pVl, 1.0f };
    tc_gemm_kernel<<<dim3(8, 16, 3), 256, gemm_smem>>>(aq, ak, av);

    // 2) packed banded qrel
    tc_qrel_kernel<<<dim3(17, 16, 16), 256, qrel_smem>>>(pQh, pQl, pTh, pTl, pQR);

    // 3) mma flash attention -> AO bf16 planes
    attn_mma_kernel<<<dim3(16, 16), 256, attn_smem>>>(pQh, pQl, pKh, pKl, pVh, pVl,
                                                      pQR, pAOh, pAOl);

    // 4) output projection -> fp32 out
    TCArgs ao{ pAOh, pAOl, pWth + 3*MM, pWtl + 3*MM, bo, out, nullptr, nullptr, 1.0f };
    tc_gemm_kernel<<<dim3(8, 16, 1), 256, gemm_smem>>>(ao, ao, ao);
}

// round 11
// speedup vs baseline: 2.7980x; 1.1432x over previous
#include <cuda_runtime.h>
#include <cuda_bf16.h>
#include <cstdint>

#define S_LEN 2048
#define D_MODEL 1024
#define N_HEADS 16
#define HEAD_DIM 64
#define TBL 4095        // 2*S - 1
#define KPACK 2048      // packed rel length per row
#define TPAD 4096       // padded rel_table rows (rows >= TBL zeroed)
#define LOG2E 1.4426950408889634f

// ---------------- scratch (__device__ arrays, no allocs) ---------------------
__device__ float g_QR[(size_t)N_HEADS * S_LEN * KPACK];  // 256 MiB packed rel (pre-scaled by log2e)

__device__ __nv_bfloat16 g_xh [S_LEN * D_MODEL], g_xl [S_LEN * D_MODEL];
__device__ __nv_bfloat16 g_Qh [S_LEN * D_MODEL], g_Ql [S_LEN * D_MODEL];
__device__ __nv_bfloat16 g_Kh [S_LEN * D_MODEL], g_Kl [S_LEN * D_MODEL];
__device__ __nv_bfloat16 g_Vh [S_LEN * D_MODEL], g_Vl [S_LEN * D_MODEL];
__device__ __nv_bfloat16 g_AOh[S_LEN * D_MODEL], g_AOl[S_LEN * D_MODEL];
__device__ __nv_bfloat16 g_Wth[4u * D_MODEL * D_MODEL], g_Wtl[4u * D_MODEL * D_MODEL];
__device__ __nv_bfloat16 g_Th [TPAD * HEAD_DIM], g_Tl [TPAD * HEAD_DIM];

// ============================ helpers ========================================
__device__ __forceinline__ uint32_t smem_u32(const void* p) {
    uint32_t a;
    asm("{ .reg .u64 t; cvta.to.shared.u64 t, %1; cvt.u32.u64 %0, t; }" : "=r"(a) : "l"(p));
    return a;
}
__device__ __forceinline__ void ldm_x4(uint32_t* r, uint32_t addr) {
    asm volatile("ldmatrix.sync.aligned.m8n8.x4.shared.b16 {%0,%1,%2,%3}, [%4];"
        : "=r"(r[0]), "=r"(r[1]), "=r"(r[2]), "=r"(r[3]) : "r"(addr));
}
__device__ __forceinline__ void ldm_x4_t(uint32_t* r, uint32_t addr) {
    asm volatile("ldmatrix.sync.aligned.m8n8.x4.trans.shared.b16 {%0,%1,%2,%3}, [%4];"
        : "=r"(r[0]), "=r"(r[1]), "=r"(r[2]), "=r"(r[3]) : "r"(addr));
}
__device__ __forceinline__ void mma_bf16(float* c, const uint32_t* a, const uint32_t* b) {
    asm volatile("mma.sync.aligned.m16n8k16.row.col.f32.bf16.bf16.f32 "
        "{%0,%1,%2,%3}, {%4,%5,%6,%7}, {%8,%9}, {%0,%1,%2,%3};"
        : "+f"(c[0]), "+f"(c[1]), "+f"(c[2]), "+f"(c[3])
        : "r"(a[0]), "r"(a[1]), "r"(a[2]), "r"(a[3]), "r"(b[0]), "r"(b[1]));
}
__device__ __forceinline__ float ex2(float x) {
    float r;
    asm("ex2.approx.ftz.f32 %0, %1;" : "=f"(r) : "f"(x));
    return r;
}
#define CP_ASYNC16(dst, src) \
    asm volatile("cp.async.cg.shared.global [%0], [%1], 16;" :: "r"(dst), "l"(src))
#define CP_COMMIT() asm volatile("cp.async.commit_group;")
#define CP_WAIT(N)  asm volatile("cp.async.wait_group %0;" :: "n"(N) : "memory")

__device__ __forceinline__ void split2(float v, __nv_bfloat16& h, __nv_bfloat16& l) {
    h = __float2bfloat16(v);
    l = __float2bfloat16(v - __bfloat162float(h));
}
__device__ __forceinline__ uint32_t pack2(__nv_bfloat16 lo, __nv_bfloat16 hi) {
    __nv_bfloat162 t{lo, hi};
    return *(uint32_t*)&t;
}

// ============================ split kernels ==================================
__global__ void split_plane_kernel(const float* __restrict__ src,
                                   __nv_bfloat16* __restrict__ ph,
                                   __nv_bfloat16* __restrict__ pl, int n4)
{
    int i = blockIdx.x * blockDim.x + threadIdx.x;
    if (i >= n4) return;
    float4 v = *(const float4*)(src + (size_t)i * 4);
    __nv_bfloat16 h, l;
    split2(v.x, h, l); ph[i*4+0] = h; pl[i*4+0] = l;
    split2(v.y, h, l); ph[i*4+1] = h; pl[i*4+1] = l;
    split2(v.z, h, l); ph[i*4+2] = h; pl[i*4+2] = l;
    split2(v.w, h, l); ph[i*4+3] = h; pl[i*4+3] = l;
}

__global__ void split_T_kernel(const float* __restrict__ rel,
                               __nv_bfloat16* __restrict__ th,
                               __nv_bfloat16* __restrict__ tl)
{
    int i = blockIdx.x * blockDim.x + threadIdx.x;
    if (i >= TPAD * HEAD_DIM) return;
    int t = i >> 6;
    float v = (t < TBL) ? rel[i] : 0.f;
    __nv_bfloat16 h, l; split2(v, h, l);
    th[i] = h; tl[i] = l;
}

struct WSrc { const float* w[4]; };
__global__ __launch_bounds__(256) void wsplit_kernel(WSrc ws,
                                                     __nv_bfloat16* __restrict__ dh,
                                                     __nv_bfloat16* __restrict__ dl)
{
    __shared__ float t[32][33];
    const float* W = ws.w[blockIdx.z];
    __nv_bfloat16* oh = dh + (size_t)blockIdx.z * D_MODEL * D_MODEL;
    __nv_bfloat16* ol = dl + (size_t)blockIdx.z * D_MODEL * D_MODEL;
    const int n0 = blockIdx.x * 32, k0 = blockIdx.y * 32;
    const int tx = threadIdx.x & 31, ty = threadIdx.x >> 5;
    #pragma unroll
    for (int rr = 0; rr < 32; rr += 8)
        t[ty + rr][tx] = W[(size_t)(k0 + ty + rr) * D_MODEL + n0 + tx];
    __syncthreads();
    #pragma unroll
    for (int rr = 0; rr < 32; rr += 8) {
        float v = t[tx][ty + rr];
        __nv_bfloat16 h, l; split2(v, h, l);
        oh[(size_t)(n0 + ty + rr) * D_MODEL + k0 + tx] = h;
        ol[(size_t)(n0 + ty + rr) * D_MODEL + k0 + tx] = l;
    }
}

// ============================ mma.sync projection GEMM =======================
#define GPITCH 40
#define PLANE_B (128 * GPITCH * 2)     // 10240 bytes per plane
#define STAGE_B (4 * PLANE_B)          // 40960 bytes per stage

struct TCArgs {
    const __nv_bfloat16 *Ah, *Al, *Bh, *Bl;
    const float* bias; float* C;       // C may be null (bf16-only output)
    __nv_bfloat16 *Ch, *Cl;            // may be null (fp32-only output)
    float scale;
};

__global__ __launch_bounds__(256) void tc_gemm_kernel(TCArgs a0, TCArgs a1, TCArgs a2)
{
    TCArgs a = (blockIdx.z == 0) ? a0 : ((blockIdx.z == 1) ? a1 : a2);
    extern __shared__ char dsm[];
    __shared__ float biasS[128];

    const int tid = threadIdx.x, lane = tid & 31, w = tid >> 5;
    const int wm = w >> 2, wn = w & 3;
    const int m0 = blockIdx.y * 128, n0 = blockIdx.x * 128;
    const uint32_t sbase = smem_u32(dsm);

    if (tid < 128) biasS[tid] = a.bias[n0 + tid];

    const __nv_bfloat16* gsrc[4] = { a.Ah, a.Al, a.Bh, a.Bl };
    const int rb[4] = { m0, m0, n0, n0 };

    #pragma unroll
    for (int p = 0; p < 4; p++) {
        const __nv_bfloat16* g = gsrc[p];
        #pragma unroll
        for (int v = 0; v < 2; v++) {
            const int idx = tid + v * 256;
            const int row = idx >> 2, c16 = idx & 3;
            CP_ASYNC16(sbase + p * PLANE_B + row * 80 + c16 * 16,
                       g + (size_t)(rb[p] + row) * D_MODEL + c16 * 8);
        }
    }
    CP_COMMIT();

    float acc[4][4][4];
    #pragma unroll
    for (int i = 0; i < 4; i++)
        #pragma unroll
        for (int j = 0; j < 4; j++)
            #pragma unroll
            for (int q = 0; q < 4; q++) acc[i][j][q] = 0.f;

    for (int c = 0; c < 32; c++) {
        CP_WAIT(0);
        __syncthreads();
        if (c + 1 < 32) {
            const int k0 = (c + 1) * 32;
            const uint32_t st = sbase + ((c + 1) & 1) * STAGE_B;
            #pragma unroll
            for (int p = 0; p < 4; p++) {
                const __nv_bfloat16* g = gsrc[p];
                #pragma unroll
                for (int v = 0; v < 2; v++) {
                    const int idx = tid + v * 256;
                    const int row = idx >> 2, c16 = idx & 3;
                    CP_ASYNC16(st + p * PLANE_B + row * 80 + c16 * 16,
                               g + (size_t)(rb[p] + row) * D_MODEL + k0 + c16 * 8);
                }
            }
            CP_COMMIT();
        }

        const uint32_t sb = sbase + (c & 1) * STAGE_B;
        #pragma unroll
        for (int ks = 0; ks < 2; ks++) {
            const uint32_t colb = (uint32_t)(ks * 16 + ((lane >> 4) * 8)) * 2;
            uint32_t ah[4][4], al[4][4], bh[2][4], bl[2][4];
            #pragma unroll
            for (int mt = 0; mt < 4; mt++) {
                const uint32_t r = wm * 64 + mt * 16 + (lane & 15);
                ldm_x4(ah[mt], sb + 0 * PLANE_B + r * 80 + colb);
                ldm_x4(al[mt], sb + 1 * PLANE_B + r * 80 + colb);
            }
            #pragma unroll
            for (int nt2 = 0; nt2 < 2; nt2++) {
                const uint32_t r = wn * 32 + nt2 * 16 + (lane & 15);
                ldm_x4(bh[nt2], sb + 2 * PLANE_B + r * 80 + colb);
                ldm_x4(bl[nt2], sb + 3 * PLANE_B + r * 80 + colb);
            }
            #pragma unroll
            for (int mt = 0; mt < 4; mt++)
                #pragma unroll
                for (int nt = 0; nt < 4; nt++) {
                    uint32_t bhf[2] = { bh[nt >> 1][nt & 1], bh[nt >> 1][(nt & 1) + 2] };
                    uint32_t blf[2] = { bl[nt >> 1][nt & 1], bl[nt >> 1][(nt & 1) + 2] };
                    mma_bf16(acc[mt][nt], ah[mt], bhf);
                    mma_bf16(acc[mt][nt], ah[mt], blf);
                    mma_bf16(acc[mt][nt], al[mt], bhf);
                }
        }
    }

    #pragma unroll
    for (int mt = 0; mt < 4; mt++) {
        const int r0 = m0 + wm * 64 + mt * 16 + (lane >> 2);
        #pragma unroll
        for (int nt = 0; nt < 4; nt++) {
            const int cl = wn * 32 + nt * 8 + 2 * (lane & 3);
            const int cg = n0 + cl;
            float2 v0, v1;
            v0.x = (acc[mt][nt][0] + biasS[cl + 0]) * a.scale;
            v0.y = (acc[mt][nt][1] + biasS[cl + 1]) * a.scale;
            v1.x = (acc[mt][nt][2] + biasS[cl + 0]) * a.scale;
            v1.y = (acc[mt][nt][3] + biasS[cl + 1]) * a.scale;
            if (a.C) {
                *(float2*)&a.C[(size_t)r0 * D_MODEL + cg]       = v0;
                *(float2*)&a.C[(size_t)(r0 + 8) * D_MODEL + cg] = v1;
            }
            if (a.Ch) {
                __nv_bfloat16 h0,l0,h1,l1;
                split2(v0.x,h0,l0); split2(v0.y,h1,l1);
                *(__nv_bfloat162*)&a.Ch[(size_t)r0 * D_MODEL + cg] = __nv_bfloat162{h0,h1};
                *(__nv_bfloat162*)&a.Cl[(size_t)r0 * D_MODEL + cg] = __nv_bfloat162{l0,l1};
                split2(v1.x,h0,l0); split2(v1.y,h1,l1);
                *(__nv_bfloat162*)&a.Ch[(size_t)(r0 + 8) * D_MODEL + cg] = __nv_bfloat162{h0,h1};
                *(__nv_bfloat162*)&a.Cl[(size_t)(r0 + 8) * D_MODEL + cg] = __nv_bfloat162{l0,l1};
            }
        }
    }
}

// ============================ mma.sync qrel ==================================
// Output pre-scaled by log2e (base-2 softmax downstream).
#define QPITCH 72
#define QPLANE_B (128 * QPITCH * 2)    // 18432 bytes

__global__ __launch_bounds__(256, 2) void tc_qrel_kernel(const __nv_bfloat16* __restrict__ Qh,
                                                         const __nv_bfloat16* __restrict__ Ql,
                                                         const __nv_bfloat16* __restrict__ Th,
                                                         const __nv_bfloat16* __restrict__ Tl,
                                                         float* __restrict__ R)
{
    extern __shared__ char dsm[];
    const int tid = threadIdx.x, lane = tid & 31, w = tid >> 5;
    const int wm = w >> 2, wn = w & 3;
    const int tt = blockIdx.x, i0 = blockIdx.y * 128, h = blockIdx.z;
    const int t0 = i0 + tt * 128;
    const uint32_t sbase = smem_u32(dsm);

    #pragma unroll
    for (int p = 0; p < 4; p++) {
        #pragma unroll
        for (int v = 0; v < 4; v++) {
            const int idx = tid + v * 256;
            const int row = idx >> 3, c16 = idx & 7;
            const __nv_bfloat16* src;
            if (p == 0)      src = Qh + (size_t)(i0 + row) * D_MODEL + h * HEAD_DIM + c16 * 8;
            else if (p == 1) src = Ql + (size_t)(i0 + row) * D_MODEL + h * HEAD_DIM + c16 * 8;
            else if (p == 2) src = Th + (size_t)(t0 + row) * HEAD_DIM + c16 * 8;
            else             src = Tl + (size_t)(t0 + row) * HEAD_DIM + c16 * 8;
            CP_ASYNC16(sbase + p * QPLANE_B + row * 144 + c16 * 16, src);
        }
    }
    CP_COMMIT(); CP_WAIT(0);
    __syncthreads();

    float acc[4][4][4];
    #pragma unroll
    for (int i = 0; i < 4; i++)
        #pragma unroll
        for (int j = 0; j < 4; j++)
            #pragma unroll
            for (int q = 0; q < 4; q++) acc[i][j][q] = 0.f;

    #pragma unroll
    for (int ks = 0; ks < 4; ks++) {
        const uint32_t colb = (uint32_t)(ks * 16 + ((lane >> 4) * 8)) * 2;
        uint32_t ah[4][4], al[4][4], bh[2][4], bl[2][4];
        #pragma unroll
        for (int mt = 0; mt < 4; mt++) {
            const uint32_t r = wm * 64 + mt * 16 + (lane & 15);
            ldm_x4(ah[mt], sbase + 0 * QPLANE_B + r * 144 + colb);
            ldm_x4(al[mt], sbase + 1 * QPLANE_B + r * 144 + colb);
        }
        #pragma unroll
        for (int nt2 = 0; nt2 < 2; nt2++) {
            const uint32_t r = wn * 32 + nt2 * 16 + (lane & 15);
            ldm_x4(bh[nt2], sbase + 2 * QPLANE_B + r * 144 + colb);
            ldm_x4(bl[nt2], sbase + 3 * QPLANE_B + r * 144 + colb);
        }
        #pragma unroll
        for (int mt = 0; mt < 4; mt++)
            #pragma unroll
            for (int nt = 0; nt < 4; nt++) {
                uint32_t bhf[2] = { bh[nt >> 1][nt & 1], bh[nt >> 1][(nt & 1) + 2] };
                uint32_t blf[2] = { bl[nt >> 1][nt & 1], bl[nt >> 1][(nt & 1) + 2] };
                mma_bf16(acc[mt][nt], ah[mt], bhf);
                mma_bf16(acc[mt][nt], ah[mt], blf);
                mma_bf16(acc[mt][nt], al[mt], bhf);
            }
    }

    #pragma unroll
    for (int mt = 0; mt < 4; mt++) {
        const int rloc = wm * 64 + mt * 16 + (lane >> 2);
        float* Rrow0 = R + (((size_t)(h * S_LEN + i0 + rloc))     << 11);
        float* Rrow1 = R + (((size_t)(h * S_LEN + i0 + rloc + 8)) << 11);
        #pragma unroll
        for (int nt = 0; nt < 4; nt++) {
            const int cloc = wn * 32 + nt * 8 + 2 * (lane & 3);
            const int k0 = tt * 128 + cloc - rloc;
            if ((unsigned)(k0)     < (unsigned)KPACK) Rrow0[k0]     = acc[mt][nt][0] * LOG2E;
            if ((unsigned)(k0 + 1) < (unsigned)KPACK) Rrow0[k0 + 1] = acc[mt][nt][1] * LOG2E;
            if ((unsigned)(k0 - 8) < (unsigned)KPACK) Rrow1[k0 - 8] = acc[mt][nt][2] * LOG2E;
            if ((unsigned)(k0 - 7) < (unsigned)KPACK) Rrow1[k0 - 7] = acc[mt][nt][3] * LOG2E;
        }
    }
}

// ============================ mma.sync flash attention =======================
// Base-2 online softmax (scores pre-scaled by log2e via K scale + QR scale).
// __launch_bounds__(256, 2): force <=128 regs so 256 CTAs fit in ONE wave.
#define APITCH_B 144
#define APLANE_B (64 * APITCH_B)       // 9216
#define ASTAGE_B (4 * APLANE_B)        // 36864

__global__ __launch_bounds__(256, 2) void attn_mma_kernel(
    const __nv_bfloat16* __restrict__ Qh, const __nv_bfloat16* __restrict__ Ql,
    const __nv_bfloat16* __restrict__ Kh, const __nv_bfloat16* __restrict__ Kl,
    const __nv_bfloat16* __restrict__ Vh, const __nv_bfloat16* __restrict__ Vl,
    const float* __restrict__ QR,
    __nv_bfloat16* __restrict__ AOh, __nv_bfloat16* __restrict__ AOl)
{
    extern __shared__ char dsm[];
    const int tid = threadIdx.x, lane = tid & 31, w = tid >> 5;
    const int i0 = blockIdx.x * 128, h = blockIdx.y;
    const uint32_t sb = smem_u32(dsm);

    // ---- stage Q (128 rows x 64 bf16 = 8x16B per row, 2 planes) ----
    #pragma unroll
    for (int p = 0; p < 2; p++) {
        const __nv_bfloat16* g = p ? Ql : Qh;
        #pragma unroll
        for (int v = 0; v < 4; v++) {
            const int idx = tid + v * 256;
            const int row = idx >> 3, c16 = idx & 7;
            CP_ASYNC16(sb + p * 18432 + row * APITCH_B + c16 * 16,
                       g + (size_t)(i0 + row) * D_MODEL + h * HEAD_DIM + c16 * 8);
        }
    }
    CP_COMMIT(); CP_WAIT(0);
    __syncthreads();

    uint32_t qfh[4][4], qfl[4][4];
    {
        const uint32_t rbyte = (uint32_t)(w * 16 + (lane & 15)) * APITCH_B;
        #pragma unroll
        for (int kf = 0; kf < 4; kf++) {
            const uint32_t colb = (uint32_t)(kf * 16 + ((lane >> 4) * 8)) * 2;
            ldm_x4(qfh[kf], sb + 0 * 18432 + rbyte + colb);
            ldm_x4(qfl[kf], sb + 1 * 18432 + rbyte + colb);
        }
    }
    __syncthreads();

    float o[8][4];
    #pragma unroll
    for (int i = 0; i < 8; i++)
        #pragma unroll
        for (int q = 0; q < 4; q++) o[i][q] = 0.f;
    float mrow0 = -1e30f, mrow1 = -1e30f, lrow0 = 0.f, lrow1 = 0.f;
    const int r0 = w * 16 + (lane >> 2);
    const float* qrow0 = QR + (((size_t)(h * S_LEN + i0 + r0)) << 11);
    const float* qrow1 = qrow0 + ((size_t)8 << 11);

    // prologue: tile 0 -> stage 0
    {
        const __nv_bfloat16* gs[4] = { Kh, Kl, Vh, Vl };
        #pragma unroll
        for (int p = 0; p < 4; p++)
            #pragma unroll
            for (int v = 0; v < 2; v++) {
                const int idx = tid + v * 256;
                const int row = idx >> 3, c16 = idx & 7;
                CP_ASYNC16(sb + p * APLANE_B + row * APITCH_B + c16 * 16,
                           gs[p] + (size_t)row * D_MODEL + h * HEAD_DIM + c16 * 8);
            }
        CP_COMMIT();
    }

    for (int jt = 0; jt < 32; jt++) {
        CP_WAIT(0);
        __syncthreads();
        if (jt + 1 < 32) {
            const int jn = (jt + 1) * 64;
            const uint32_t st2 = sb + ((jt + 1) & 1) * ASTAGE_B;
            const __nv_bfloat16* gs[4] = { Kh, Kl, Vh, Vl };
            #pragma unroll
            for (int p = 0; p < 4; p++)
                #pragma unroll
                for (int v = 0; v < 2; v++) {
                    const int idx = tid + v * 256;
                    const int row = idx >> 3, c16 = idx & 7;
                    CP_ASYNC16(st2 + p * APLANE_B + row * APITCH_B + c16 * 16,
                               gs[p] + (size_t)(jn + row) * D_MODEL + h * HEAD_DIM + c16 * 8);
                }
            CP_COMMIT();
        }

        const uint32_t st = sb + (jt & 1) * ASTAGE_B;
        const int j0 = jt * 64;

        // --- S init from packed rel (already log2e-scaled) ---
        float c[8][4];
        #pragma unroll
        for (int nf = 0; nf < 8; nf++) {
            const int jc = j0 + nf * 8 + (lane & 3) * 2;
            float2 g0 = *(const float2*)&qrow0[2046 - jc];
            float2 g1 = *(const float2*)&qrow1[2046 - jc];
            c[nf][0] = g0.y; c[nf][1] = g0.x;
            c[nf][2] = g1.y; c[nf][3] = g1.x;
        }

        // --- S += Q . K^T (split bf16; K carries 0.125*log2e) ---
        #pragma unroll
        for (int jf = 0; jf < 4; jf++) {
            const uint32_t rby = (uint32_t)(jf * 16 + (lane & 15)) * APITCH_B;
            #pragma unroll
            for (int kf = 0; kf < 4; kf++) {
                const uint32_t cb = (uint32_t)(kf * 16 + ((lane >> 4) * 8)) * 2;
                uint32_t kh4[4], kl4[4];
                ldm_x4(kh4, st + 0 * APLANE_B + rby + cb);
                ldm_x4(kl4, st + 1 * APLANE_B + rby + cb);
                uint32_t b0h[2] = { kh4[0], kh4[2] }, b1h[2] = { kh4[1], kh4[3] };
                uint32_t b0l[2] = { kl4[0], kl4[2] }, b1l[2] = { kl4[1], kl4[3] };
                mma_bf16(c[jf*2+0], qfh[kf], b0h);
                mma_bf16(c[jf*2+0], qfh[kf], b0l);
                mma_bf16(c[jf*2+0], qfl[kf], b0h);
                mma_bf16(c[jf*2+1], qfh[kf], b1h);
                mma_bf16(c[jf*2+1], qfh[kf], b1l);
                mma_bf16(c[jf*2+1], qfl[kf], b1h);
            }
        }

        // --- online softmax (base 2) ---
        float mx0 = -1e30f, mx1 = -1e30f;
        #pragma unroll
        for (int nf = 0; nf < 8; nf++) {
            mx0 = fmaxf(mx0, fmaxf(c[nf][0], c[nf][1]));
            mx1 = fmaxf(mx1, fmaxf(c[nf][2], c[nf][3]));
        }
        mx0 = fmaxf(mx0, __shfl_xor_sync(0xffffffffu, mx0, 1));
        mx0 = fmaxf(mx0, __shfl_xor_sync(0xffffffffu, mx0, 2));
        mx1 = fmaxf(mx1, __shfl_xor_sync(0xffffffffu, mx1, 1));
        mx1 = fmaxf(mx1, __shfl_xor_sync(0xffffffffu, mx1, 2));
        const float mn0 = fmaxf(mrow0, mx0), mn1 = fmaxf(mrow1, mx1);
        const float cor0 = ex2(mrow0 - mn0), cor1 = ex2(mrow1 - mn1);
        mrow0 = mn0; mrow1 = mn1;

        uint32_t P0h[8], P1h[8], P0l[8], P1l[8];
        float ls0 = 0.f, ls1 = 0.f;
        #pragma unroll
        for (int nf = 0; nf < 8; nf++) {
            float p0 = ex2(c[nf][0] - mn0), p1 = ex2(c[nf][1] - mn0);
            float p2 = ex2(c[nf][2] - mn1), p3 = ex2(c[nf][3] - mn1);
            ls0 += p0 + p1; ls1 += p2 + p3;
            __nv_bfloat16 h0,l0,h1,l1;
            split2(p0,h0,l0); split2(p1,h1,l1);
            P0h[nf] = pack2(h0,h1); P0l[nf] = pack2(l0,l1);
            split2(p2,h0,l0); split2(p3,h1,l1);
            P1h[nf] = pack2(h0,h1); P1l[nf] = pack2(l0,l1);
        }
        ls0 += __shfl_xor_sync(0xffffffffu, ls0, 1);
        ls0 += __shfl_xor_sync(0xffffffffu, ls0, 2);
        ls1 += __shfl_xor_sync(0xffffffffu, ls1, 1);
        ls1 += __shfl_xor_sync(0xffffffffu, ls1, 2);
        lrow0 = lrow0 * cor0 + ls0;
        lrow1 = lrow1 * cor1 + ls1;
        #pragma unroll
        for (int df = 0; df < 8; df++) {
            o[df][0] *= cor0; o[df][1] *= cor0;
            o[df][2] *= cor1; o[df][3] *= cor1;
        }

        // --- O += P . V (split bf16); V fragments via ldmatrix.trans ---
        #pragma unroll
        for (int kfj = 0; kfj < 4; kfj++) {
            uint32_t ah[4] = { P0h[2*kfj], P1h[2*kfj], P0h[2*kfj+1], P1h[2*kfj+1] };
            uint32_t al[4] = { P0l[2*kfj], P1l[2*kfj], P0l[2*kfj+1], P1l[2*kfj+1] };
            const uint32_t rby = (uint32_t)(kfj * 16 + (lane & 15)) * APITCH_B;
            #pragma unroll
            for (int dc = 0; dc < 4; dc++) {
                const uint32_t cb = (uint32_t)(dc * 16 + ((lane >> 4) * 8)) * 2;
                uint32_t vh4[4], vl4[4];
                ldm_x4_t(vh4, st + 2 * APLANE_B + rby + cb);
                ldm_x4_t(vl4, st + 3 * APLANE_B + rby + cb);
                uint32_t bh0[2] = { vh4[0], vh4[1] }, bh1[2] = { vh4[2], vh4[3] };
                uint32_t bl0[2] = { vl4[0], vl4[1] }, bl1[2] = { vl4[2], vl4[3] };
                mma_bf16(o[dc*2+0], ah, bh0);
                mma_bf16(o[dc*2+0], ah, bl0);
                mma_bf16(o[dc*2+0], al, bh0);
                mma_bf16(o[dc*2+1], ah, bh1);
                mma_bf16(o[dc*2+1], ah, bl1);
                mma_bf16(o[dc*2+1], al, bh1);
            }
        }
    }

    // ---- finalize: O /= l, split-store AO bf16 planes ----
    const float inv0 = 1.f / lrow0, inv1 = 1.f / lrow1;
    const int gr0 = i0 + r0, gr1 = gr0 + 8;
    #pragma unroll
    for (int df = 0; df < 8; df++) {
        const int d = h * HEAD_DIM + df * 8 + (lane & 3) * 2;
        __nv_bfloat16 h0,l0,h1,l1;
        split2(o[df][0] * inv0, h0, l0); split2(o[df][1] * inv0, h1, l1);
        *(__nv_bfloat162*)&AOh[(size_t)gr0 * D_MODEL + d] = __nv_bfloat162{h0,h1};
        *(__nv_bfloat162*)&AOl[(size_t)gr0 * D_MODEL + d] = __nv_bfloat162{l0,l1};
        split2(o[df][2] * inv1, h0, l0); split2(o[df][3] * inv1, h1, l1);
        *(__nv_bfloat162*)&AOh[(size_t)gr1 * D_MODEL + d] = __nv_bfloat162{h0,h1};
        *(__nv_bfloat162*)&AOl[(size_t)gr1 * D_MODEL + d] = __nv_bfloat162{l0,l1};
    }
}

// ============================ Launcher =======================================
extern "C" void kernel_launch(void* const* d_in, const int* in_sizes, int n_in,
                              void* d_out, int out_size)
{
    const float* x   = (const float*)d_in[0];
    const float* Wq  = (const float*)d_in[1];
    const float* bq  = (const float*)d_in[2];
    const float* Wk  = (const float*)d_in[3];
    const float* bk  = (const float*)d_in[4];
    const float* Wv  = (const float*)d_in[5];
    const float* bv  = (const float*)d_in[6];
    const float* Wo  = (const float*)d_in[7];
    const float* bo  = (const float*)d_in[8];
    const float* rel = (const float*)d_in[9];
    float* out = (float*)d_out;

    float* pQR;
    __nv_bfloat16 *pxh, *pxl, *pQh, *pQl, *pKh, *pKl, *pVh, *pVl;
    __nv_bfloat16 *pAOh, *pAOl, *pWth, *pWtl, *pTh, *pTl;
    cudaGetSymbolAddress((void**)&pQR,  g_QR);
    cudaGetSymbolAddress((void**)&pxh,  g_xh);
    cudaGetSymbolAddress((void**)&pxl,  g_xl);
    cudaGetSymbolAddress((void**)&pQh,  g_Qh);
    cudaGetSymbolAddress((void**)&pQl,  g_Ql);
    cudaGetSymbolAddress((void**)&pKh,  g_Kh);
    cudaGetSymbolAddress((void**)&pKl,  g_Kl);
    cudaGetSymbolAddress((void**)&pVh,  g_Vh);
    cudaGetSymbolAddress((void**)&pVl,  g_Vl);
    cudaGetSymbolAddress((void**)&pAOh, g_AOh);
    cudaGetSymbolAddress((void**)&pAOl, g_AOl);
    cudaGetSymbolAddress((void**)&pWth, g_Wth);
    cudaGetSymbolAddress((void**)&pWtl, g_Wtl);
    cudaGetSymbolAddress((void**)&pTh,  g_Th);
    cudaGetSymbolAddress((void**)&pTl,  g_Tl);

    const int gemm_smem = 2 * STAGE_B;       // 81,920
    const int qrel_smem = 4 * QPLANE_B;      // 73,728
    const int attn_smem = 2 * ASTAGE_B;      // 73,728
    cudaFuncSetAttribute(tc_gemm_kernel,  cudaFuncAttributeMaxDynamicSharedMemorySize, gemm_smem);
    cudaFuncSetAttribute(tc_qrel_kernel,  cudaFuncAttributeMaxDynamicSharedMemorySize, qrel_smem);
    cudaFuncSetAttribute(attn_mma_kernel, cudaFuncAttributeMaxDynamicSharedMemorySize, attn_smem);

    // 0) splits: x, W^T (x4), rel_table
    split_plane_kernel<<<(S_LEN * D_MODEL / 4 + 255) / 256, 256>>>(x, pxh, pxl, S_LEN * D_MODEL / 4);
    WSrc ws; ws.w[0] = Wq; ws.w[1] = Wk; ws.w[2] = Wv; ws.w[3] = Wo;
    wsplit_kernel<<<dim3(32, 32, 4), 256>>>(ws, pWth, pWtl);
    split_T_kernel<<<(TPAD * HEAD_DIM + 255) / 256, 256>>>(rel, pTh, pTl);

    const size_t MM = (size_t)D_MODEL * D_MODEL;

    // 1) QKV projections -> bf16 planes (K folded with 1/8 * log2e for base-2 softmax)
    TCArgs aq{ pxh, pxl, pWth + 0*MM, pWtl + 0*MM, bq, nullptr, pQh, pQl, 1.0f };
    TCArgs ak{ pxh, pxl, pWth + 1*MM, pWtl + 1*MM, bk, nullptr, pKh, pKl, 0.125f * LOG2E };
    TCArgs av{ pxh, pxl, pWth + 2*MM, pWtl + 2*MM, bv, nullptr, pVh, pVl, 1.0f };
    tc_gemm_kernel<<<dim3(8, 16, 3), 256, gemm_smem>>>(aq, ak, av);

    // 2) packed banded qrel (log2e-scaled output)
    tc_qrel_kernel<<<dim3(17, 16, 16), 256, qrel_smem>>>(pQh, pQl, pTh, pTl, pQR);

    // 3) mma flash attention (base-2 softmax) -> AO bf16 planes
    attn_mma_kernel<<<dim3(16, 16), 256, attn_smem>>>(pQh, pQl, pKh, pKl, pVh, pVl,
                                                      pQR, pAOh, pAOl);

    // 4) output projection -> fp32 out
    TCArgs ao{ pAOh, pAOl, pWth + 3*MM, pWtl + 3*MM, bo, out, nullptr, nullptr, 1.0f };
    tc_gemm_kernel<<<dim3(8, 16, 1), 256, gemm_smem>>>(ao, ao, ao);
}